// round 5
// baseline (speedup 1.0000x reference)
#include <cuda_runtime.h>
#include <cuda_bf16.h>
#include <cstdint>
#include <math.h>

#define BATCH 16
#define SEQ   1024
#define DIM   512
#define NHEAD 8
#define DPH   64
#define NROWS (BATCH*SEQ)   // 16384

// ---------------------------------------------------------------------------
// Scratch (device globals: no allocation allowed anywhere)
// ---------------------------------------------------------------------------
__device__ float g_qkv[3*NROWS*DIM];                 // GEMM outputs (q,k,v)
__device__ __nv_bfloat16 g_xhi[3*NROWS*DIM];
__device__ __nv_bfloat16 g_xlo[3*NROWS*DIM];
__device__ __nv_bfloat16 g_whi[3*DIM*DIM];
__device__ __nv_bfloat16 g_wlo[3*DIM*DIM];
__device__ float g_M[BATCH*NHEAD*DPH*DPH];
__device__ float g_cs[BATCH*NHEAD*DPH];

// ---------------------------------------------------------------------------
// PTX helpers (base-target sm_80+ features only)
// ---------------------------------------------------------------------------
__device__ __forceinline__ uint32_t smem_u32(const void* p) {
    uint32_t a;
    asm("{ .reg .u64 t; cvta.to.shared.u64 t, %1; cvt.u32.u64 %0, t; }"
        : "=r"(a) : "l"(p));
    return a;
}
__device__ __forceinline__ void cp16(uint32_t s, const void* g) {
    asm volatile("cp.async.cg.shared.global [%0], [%1], 16;" :: "r"(s), "l"(g));
}
__device__ __forceinline__ void cp_commit() {
    asm volatile("cp.async.commit_group;" ::: "memory");
}
template <int N>
__device__ __forceinline__ void cp_wait() {
    asm volatile("cp.async.wait_group %0;" :: "n"(N) : "memory");
}
__device__ __forceinline__ void ldsm4(uint32_t* r, uint32_t addr) {
    asm volatile("ldmatrix.sync.aligned.m8n8.x4.shared.b16 {%0,%1,%2,%3}, [%4];"
                 : "=r"(r[0]), "=r"(r[1]), "=r"(r[2]), "=r"(r[3]) : "r"(addr));
}
__device__ __forceinline__ void mma16816(float* c, const uint32_t* a,
                                         uint32_t b0, uint32_t b1) {
    asm volatile(
        "mma.sync.aligned.m16n8k16.row.col.f32.bf16.bf16.f32 "
        "{%0,%1,%2,%3}, {%4,%5,%6,%7}, {%8,%9}, {%0,%1,%2,%3};"
        : "+f"(c[0]), "+f"(c[1]), "+f"(c[2]), "+f"(c[3])
        : "r"(a[0]), "r"(a[1]), "r"(a[2]), "r"(a[3]), "r"(b0), "r"(b1));
}

// ---------------------------------------------------------------------------
// fp32 -> bf16 hi/lo split converters
// ---------------------------------------------------------------------------
__device__ __forceinline__ void split4(float4 x, __nv_bfloat16* hi,
                                       __nv_bfloat16* lo, int i) {
    __nv_bfloat162 h0 = __float22bfloat162_rn(make_float2(x.x, x.y));
    __nv_bfloat162 h1 = __float22bfloat162_rn(make_float2(x.z, x.w));
    float2 hf0 = make_float2(__low2float(h0), __high2float(h0));
    float2 hf1 = make_float2(__low2float(h1), __high2float(h1));
    __nv_bfloat162 l0 = __float22bfloat162_rn(make_float2(x.x - hf0.x, x.y - hf0.y));
    __nv_bfloat162 l1 = __float22bfloat162_rn(make_float2(x.z - hf1.x, x.w - hf1.y));
    reinterpret_cast<__nv_bfloat162*>(hi)[2*i]   = h0;
    reinterpret_cast<__nv_bfloat162*>(hi)[2*i+1] = h1;
    reinterpret_cast<__nv_bfloat162*>(lo)[2*i]   = l0;
    reinterpret_cast<__nv_bfloat162*>(lo)[2*i+1] = l1;
}

__global__ __launch_bounds__(256) void convert_kernel(
    const float* __restrict__ src, __nv_bfloat16* __restrict__ hi,
    __nv_bfloat16* __restrict__ lo, int n4)
{
    int i = blockIdx.x * blockDim.x + threadIdx.x;
    if (i >= n4) return;
    split4(reinterpret_cast<const float4*>(src)[i], hi, lo, i);
}

__global__ __launch_bounds__(256) void convert2_kernel(
    const float* __restrict__ sa, __nv_bfloat16* __restrict__ ha,
    __nv_bfloat16* __restrict__ la,
    const float* __restrict__ sb, __nv_bfloat16* __restrict__ hb,
    __nv_bfloat16* __restrict__ lb, int n4)
{
    int i = blockIdx.x * blockDim.x + threadIdx.x;
    if (i >= n4) return;
    if (blockIdx.y == 0) split4(reinterpret_cast<const float4*>(sa)[i], ha, la, i);
    else                 split4(reinterpret_cast<const float4*>(sb)[i], hb, lb, i);
}

// ---------------------------------------------------------------------------
// Hybrid GEMM: Y[n,j] = sum_d X[n,d]*W[j,d] + bias[j]
// Tile 160x128: rows [0,128) by 8 HMMA warps (bf16 hi/lo 3-term split),
// rows [128,160) by 4 FFMA warps (fp32 SIMT from fp32 strips).
// BK=32, 3-stage cp.async pipeline, 384 threads.
// ---------------------------------------------------------------------------
#define BK 32
#define TILE_M 160
#define LDSS 40                       // bf16 elems per padded smem row
#define MATB (128*LDSS*2)             // 10240 B per bf16 matrix tile
#define AFS_OFF (4*MATB)              // 40960: fp32 A strip [32][36]
#define BFS_OFF (AFS_OFF + 32*36*4)   // 45568: fp32 B strip [128][36]
#define STGB (BFS_OFF + 128*36*4)     // 64000 B per stage
#define GEMM_SMEM (3*STGB)            // 192000 B
#define NSTAGE 16                     // K=512 / BK

__global__ __launch_bounds__(384, 1) void gemm_mma_kernel(
    const __nv_bfloat16* __restrict__ Xhi, const __nv_bfloat16* __restrict__ Xlo,
    const __nv_bfloat16* __restrict__ Whi, const __nv_bfloat16* __restrict__ Wlo,
    const float* __restrict__ Xq, const float* __restrict__ Xk,
    const float* __restrict__ Xv,
    const float* __restrict__ Wqf, const float* __restrict__ Wkf,
    const float* __restrict__ Wvf,
    const float* __restrict__ bq, const float* __restrict__ bk,
    const float* __restrict__ bv, float* __restrict__ Yall)
{
    extern __shared__ char smem[];
    const int z = blockIdx.z;
    const __nv_bfloat16* Ah = Xhi + (size_t)z * NROWS * DIM;
    const __nv_bfloat16* Al = Xlo + (size_t)z * NROWS * DIM;
    const __nv_bfloat16* Bh = Whi + (size_t)z * DIM * DIM;
    const __nv_bfloat16* Bl = Wlo + (size_t)z * DIM * DIM;
    const float* Xf   = (z == 0) ? Xq  : (z == 1) ? Xk  : Xv;
    const float* Wf   = (z == 0) ? Wqf : (z == 1) ? Wkf : Wvf;
    const float* bias = (z == 0) ? bq  : (z == 1) ? bk  : bv;
    float* Y = Yall + (size_t)z * NROWS * DIM;

    const int bm = blockIdx.y * TILE_M;
    const int bn = blockIdx.x * 128;
    const int tid = threadIdx.x;
    const int wid = tid >> 5, lane = tid & 31;

    uint32_t sb = smem_u32(smem);

    // bf16 loader mapping (threads 0-255): row tid>>1, k-half tid&1
    const int cr = tid >> 1;
    const int ck = (tid & 1) * 16;
    const int arow = min(bm + cr, NROWS - 1);
    const __nv_bfloat16* gAh = Ah + (size_t)arow * DIM + ck;
    const __nv_bfloat16* gAl = Al + (size_t)arow * DIM + ck;
    const __nv_bfloat16* gBh = Bh + (size_t)(bn + cr) * DIM + ck;
    const __nv_bfloat16* gBl = Bl + (size_t)(bn + cr) * DIM + ck;
    const uint32_t srow = (uint32_t)(cr * LDSS + ck) * 2;

#define ISSUE(stage, k0)                                                      \
    {                                                                         \
        uint32_t s0 = sb + (stage) * STGB;                                    \
        if (tid < 256) {                                                      \
            uint32_t d = s0 + srow;                                           \
            cp16(d + 0*MATB,      gAh + (k0));                                \
            cp16(d + 0*MATB + 16, gAh + (k0) + 8);                            \
            cp16(d + 1*MATB,      gAl + (k0));                                \
            cp16(d + 1*MATB + 16, gAl + (k0) + 8);                            \
            cp16(d + 2*MATB,      gBh + (k0));                                \
            cp16(d + 2*MATB + 16, gBh + (k0) + 8);                            \
            cp16(d + 3*MATB,      gBl + (k0));                                \
            cp16(d + 3*MATB + 16, gBl + (k0) + 8);                            \
        } else {                                                              \
            int t = tid - 256;                                                \
            _Pragma("unroll")                                                 \
            for (int i2 = 0; i2 < 2; i2++) {                                  \
                int c = t + i2*128; int row = c >> 3; int kq = (c & 7) * 4;   \
                int gr = min(bm + 128 + row, NROWS - 1);                      \
                cp16(s0 + AFS_OFF + (uint32_t)(row*36 + kq)*4,                \
                     Xf + (size_t)gr * DIM + (k0) + kq);                      \
            }                                                                 \
            _Pragma("unroll")                                                 \
            for (int i2 = 0; i2 < 8; i2++) {                                  \
                int c = t + i2*128; int col = c >> 3; int kq = (c & 7) * 4;   \
                cp16(s0 + BFS_OFF + (uint32_t)(col*36 + kq)*4,                \
                     Wf + (size_t)(bn + col) * DIM + (k0) + kq);              \
            }                                                                 \
        }                                                                     \
        cp_commit();                                                          \
    }

    ISSUE(0, 0)
    ISSUE(1, BK)

    // HMMA accumulators / layout
    const int wm = wid >> 2, wn = wid & 3;            // valid for wid<8
    float acc[4][4][4];
    // FFMA accumulators / layout
    const int wf = wid - 8;                           // valid for wid>=8
    const int lane_r = lane >> 3;                     // 0..3
    const int lane_c = lane & 7;                      // 0..7
    float facc[8][4];
#pragma unroll
    for (int i = 0; i < 4; i++)
#pragma unroll
        for (int j = 0; j < 4; j++)
#pragma unroll
            for (int r = 0; r < 4; r++) acc[i][j][r] = 0.f;
#pragma unroll
    for (int i = 0; i < 8; i++)
#pragma unroll
        for (int j = 0; j < 4; j++) facc[i][j] = 0.f;

    const uint32_t lrow = lane & 15;
    const uint32_t lhalf = (lane >> 4) * 8;

    for (int s = 0; s < NSTAGE; s++) {
        if (s < NSTAGE - 2) cp_wait<1>(); else cp_wait<0>();
        __syncthreads();
        uint32_t st = sb + (s % 3) * STGB;
        char* stp = smem + (s % 3) * STGB;

        if (wid < 8) {
#pragma unroll
            for (int ks = 0; ks < 2; ks++) {
                uint32_t ahi[4][4], alo[4][4], bhi[2][4], blo[2][4];
#pragma unroll
                for (int mt = 0; mt < 4; mt++) {
                    uint32_t addr = st +
                        ((wm*64 + mt*16 + lrow) * LDSS + ks*16 + lhalf) * 2;
                    ldsm4(ahi[mt], addr);
                    ldsm4(alo[mt], addr + MATB);
                }
#pragma unroll
                for (int bt = 0; bt < 2; bt++) {
                    uint32_t addr = st + 2*MATB +
                        ((wn*32 + bt*16 + lrow) * LDSS + ks*16 + lhalf) * 2;
                    ldsm4(bhi[bt], addr);
                    ldsm4(blo[bt], addr + MATB);
                }
#pragma unroll
                for (int mt = 0; mt < 4; mt++) {
#pragma unroll
                    for (int nt = 0; nt < 4; nt++) {
                        int g = nt >> 1, o = nt & 1;
                        uint32_t bh0 = bhi[g][o], bh1 = bhi[g][o+2];
                        uint32_t bl0 = blo[g][o], bl1 = blo[g][o+2];
                        mma16816(acc[mt][nt], ahi[mt], bh0, bh1);
                        mma16816(acc[mt][nt], ahi[mt], bl0, bl1);
                        mma16816(acc[mt][nt], alo[mt], bh0, bh1);
                    }
                }
            }
        } else {
            const float* Af = (const float*)(stp + AFS_OFF);
            const float* Bf = (const float*)(stp + BFS_OFF);
            const int cb = wf * 32;
#pragma unroll 4
            for (int k = 0; k < BK; k++) {
                float a[8], b[4];
#pragma unroll
                for (int i = 0; i < 8; i++)
                    a[i] = Af[(lane_r + 4*i) * 36 + k];
#pragma unroll
                for (int j = 0; j < 4; j++)
                    b[j] = Bf[(cb + lane_c + 8*j) * 36 + k];
#pragma unroll
                for (int i = 0; i < 8; i++)
#pragma unroll
                    for (int j = 0; j < 4; j++)
                        facc[i][j] = fmaf(a[i], b[j], facc[i][j]);
            }
        }
        if (s + 2 < NSTAGE) ISSUE((s + 2) % 3, (s + 2) * BK)
        __syncthreads();
    }
#undef ISSUE

    if (wid < 8) {
        // HMMA epilogue
#pragma unroll
        for (int nt = 0; nt < 4; nt++) {
            int col = bn + wn*32 + nt*8 + (lane & 3)*2;
            float2 b2 = make_float2(bias[col], bias[col+1]);
#pragma unroll
            for (int mt = 0; mt < 4; mt++) {
                int row = bm + wm*64 + mt*16 + (lane >> 2);
                if (row < NROWS) {
                    float* y0 = Y + (size_t)row * DIM + col;
                    *reinterpret_cast<float2*>(y0) =
                        make_float2(acc[mt][nt][0] + b2.x, acc[mt][nt][1] + b2.y);
                }
                if (row + 8 < NROWS) {
                    float* y1 = Y + (size_t)(row + 8) * DIM + col;
                    *reinterpret_cast<float2*>(y1) =
                        make_float2(acc[mt][nt][2] + b2.x, acc[mt][nt][3] + b2.y);
                }
            }
        }
    } else {
        // FFMA epilogue
#pragma unroll
        for (int i = 0; i < 8; i++) {
            int row = bm + 128 + lane_r + 4*i;
            if (row >= NROWS) continue;
            float* yp = Y + (size_t)row * DIM;
#pragma unroll
            for (int j = 0; j < 4; j++) {
                int col = bn + wf*32 + lane_c + 8*j;
                yp[col] = facc[i][j] + bias[col];
            }
        }
    }
}

// ---------------------------------------------------------------------------
// Lorentz transform: warp-per-row, 3 tensors fused via grid.y
// ---------------------------------------------------------------------------
__global__ __launch_bounds__(256) void lorentz_kernel(
    float* __restrict__ Yall,
    const float* __restrict__ lsq, const float* __restrict__ lsk,
    const float* __restrict__ lsv)
{
    const int z = blockIdx.y;
    float* Y = Yall + (size_t)z * NROWS * DIM;
    const float* ls = (z == 0) ? lsq : (z == 1) ? lsk : lsv;

    int row  = blockIdx.x * 8 + (threadIdx.x >> 5);
    int lane = threadIdx.x & 31;
    float* y = Y + (size_t)row * DIM + lane * 4;

    float4 v[4];
#pragma unroll
    for (int c = 0; c < 4; c++) v[c] = *reinterpret_cast<float4*>(y + c * 128);

    float ss = 0.f;
#pragma unroll
    for (int c = 0; c < 4; c++)
        ss += v[c].x*v[c].x + v[c].y*v[c].y + v[c].z*v[c].z + v[c].w*v[c].w;
    if (lane == 0) ss -= v[0].x * v[0].x;
#pragma unroll
    for (int o = 16; o > 0; o >>= 1) ss += __shfl_xor_sync(0xffffffffu, ss, o);

    float x0 = __shfl_sync(0xffffffffu, v[0].x, 0);
    float time = expf(ls[0]) / (1.f + expf(-x0)) + 1.0001f;
    float scale = sqrtf((time * time - 1.f) / fmaxf(ss, 1e-8f));
#pragma unroll
    for (int c = 0; c < 4; c++) {
        v[c].x *= scale; v[c].y *= scale; v[c].z *= scale; v[c].w *= scale;
    }
    if (lane == 0) v[0].x = time;
#pragma unroll
    for (int c = 0; c < 4; c++) *reinterpret_cast<float4*>(y + c * 128) = v[c];
}

// ---------------------------------------------------------------------------
__global__ __launch_bounds__(64) void colsum_kernel(
    const float* __restrict__ Vb, float* __restrict__ CS,
    const float* __restrict__ as_p, const float* __restrict__ ab_p)
{
    int bh = blockIdx.x;
    int b = bh >> 3, h = bh & 7;
    int d = threadIdx.x;
    const float* vp = Vb + (size_t)b * SEQ * DIM + h * DPH + d;
    float a0 = 0.f, a1 = 0.f, a2 = 0.f, a3 = 0.f;
#pragma unroll 4
    for (int s = 0; s < SEQ; s += 4) {
        a0 += vp[(size_t)(s+0) * DIM];
        a1 += vp[(size_t)(s+1) * DIM];
        a2 += vp[(size_t)(s+2) * DIM];
        a3 += vp[(size_t)(s+3) * DIM];
    }
    float c1 = 2.f / as_p[0] + ab_p[0];
    CS[bh * DPH + d] = (a0 + a1 + a2 + a3) * c1;
}

// ---------------------------------------------------------------------------
__global__ __launch_bounds__(256) void kkv_kernel(
    const float* __restrict__ Kb, const float* __restrict__ Vb,
    float* __restrict__ M, const float* __restrict__ as_p)
{
    int bh = blockIdx.x;
    int b = bh >> 3, h = bh & 7;
    __shared__ float Ks[32][64];
    __shared__ float Vs[32][64];
    int tid = threadIdx.x;
    int d1b = (tid >> 4) * 4;
    int d2b = (tid & 15) * 4;
    int lr = tid >> 3;
    int lc = (tid & 7) * 8;
    float acc[4][4];
#pragma unroll
    for (int i = 0; i < 4; i++)
#pragma unroll
        for (int j = 0; j < 4; j++) acc[i][j] = 0.f;

    const float* kp = Kb + (size_t)b * SEQ * DIM + h * DPH;
    const float* vp = Vb + (size_t)b * SEQ * DIM + h * DPH;

    for (int s0 = 0; s0 < SEQ; s0 += 32) {
        float4 k0 = *(const float4*)(kp + (size_t)(s0+lr) * DIM + lc);
        float4 k1 = *(const float4*)(kp + (size_t)(s0+lr) * DIM + lc + 4);
        float4 v0 = *(const float4*)(vp + (size_t)(s0+lr) * DIM + lc);
        float4 v1 = *(const float4*)(vp + (size_t)(s0+lr) * DIM + lc + 4);
        __syncthreads();
        *(float4*)&Ks[lr][lc]   = k0; *(float4*)&Ks[lr][lc+4] = k1;
        *(float4*)&Vs[lr][lc]   = v0; *(float4*)&Vs[lr][lc+4] = v1;
        __syncthreads();
#pragma unroll
        for (int ss = 0; ss < 32; ss++) {
            float4 kv = *(const float4*)&Ks[ss][d1b];
            float4 vv = *(const float4*)&Vs[ss][d2b];
            float ka[4] = {kv.x, kv.y, kv.z, kv.w};
            float va[4] = {vv.x, vv.y, vv.z, vv.w};
#pragma unroll
            for (int i = 0; i < 4; i++)
#pragma unroll
                for (int j = 0; j < 4; j++) acc[i][j] += ka[i] * va[j];
        }
    }

    float c2 = 2.f / as_p[0];
    float* Mp = M + (size_t)bh * DPH * DPH;
#pragma unroll
    for (int i = 0; i < 4; i++) {
        float sg = (d1b + i == 0) ? -c2 : c2;
#pragma unroll
        for (int j = 0; j < 4; j++)
            Mp[(d1b + i) * DPH + d2b + j] = acc[i][j] * sg;
    }
}

// ---------------------------------------------------------------------------
__global__ __launch_bounds__(256) void ave_kernel(
    const float* __restrict__ Qb, const float* __restrict__ M,
    const float* __restrict__ CS, float* __restrict__ Out)
{
    int bh = blockIdx.x;
    int b = bh >> 3, h = bh & 7;
    int s0 = blockIdx.y * 32;
    int tid = threadIdx.x;
    int warp = tid >> 5, lane = tid & 31;

    __shared__ float Ms[64][64];
    {
        const float* Mp = M + (size_t)bh * DPH * DPH;
        float* Msf = &Ms[0][0];
        for (int i = tid * 4; i < 4096; i += 1024)
            *(float4*)&Msf[i] = *(const float4*)&Mp[i];
    }
    __syncthreads();

    float cs0 = CS[bh * DPH + lane];
    float cs1 = CS[bh * DPH + lane + 32];
    const float* qp = Qb + (size_t)b * SEQ * DIM + h * DPH;

    for (int r = warp; r < 32; r += 8) {
        int srow = s0 + r;
        const float* q = qp + (size_t)srow * DIM;
        float a0 = cs0, a1 = cs1;
#pragma unroll
        for (int dp = 0; dp < 64; dp++) {
            float qv = __ldg(&q[dp]);
            a0 += qv * Ms[dp][lane];
            a1 += qv * Ms[dp][lane + 32];
        }
        float contrib = a0 * a0 * ((lane == 0) ? -1.f : 1.f) + a1 * a1;
#pragma unroll
        for (int o = 16; o > 0; o >>= 1) contrib += __shfl_xor_sync(0xffffffffu, contrib, o);
        float inv = 1.f / sqrtf(fmaxf(fabsf(contrib), 1e-8f));
        size_t ob = ((size_t)b * SEQ + srow) * DIM + h * DPH;
        Out[ob + lane]      = a0 * inv;
        Out[ob + lane + 32] = a1 * inv;
    }
}

// ===========================================================================
extern "C" void kernel_launch(void* const* d_in, const int* in_sizes, int n_in,
                              void* d_out, int out_size)
{
    const float* key   = (const float*)d_in[0];
    const float* value = (const float*)d_in[1];
    const float* query = (const float*)d_in[2];
    const float* Wq  = (const float*)d_in[3];
    const float* bq  = (const float*)d_in[4];
    const float* lsq = (const float*)d_in[5];
    const float* Wk  = (const float*)d_in[6];
    const float* bk  = (const float*)d_in[7];
    const float* lsk = (const float*)d_in[8];
    const float* Wv  = (const float*)d_in[9];
    const float* bv  = (const float*)d_in[10];
    const float* lsv = (const float*)d_in[11];
    const float* as_p = (const float*)d_in[12];
    const float* ab_p = (const float*)d_in[13];
    float* out = (float*)d_out;

    float *gqkv, *gM, *gcs;
    __nv_bfloat16 *gxhi, *gxlo, *gwhi, *gwlo;
    cudaGetSymbolAddress((void**)&gqkv, g_qkv);
    cudaGetSymbolAddress((void**)&gxhi, g_xhi);
    cudaGetSymbolAddress((void**)&gxlo, g_xlo);
    cudaGetSymbolAddress((void**)&gwhi, g_whi);
    cudaGetSymbolAddress((void**)&gwlo, g_wlo);
    cudaGetSymbolAddress((void**)&gM,   g_M);
    cudaGetSymbolAddress((void**)&gcs,  g_cs);

    float* gq = gqkv;
    float* gk = gqkv + (size_t)NROWS * DIM;
    float* gv = gqkv + (size_t)2 * NROWS * DIM;

    const int XN4 = NROWS * DIM / 4;
    const int WN4 = DIM * DIM / 4;

    // 5 convert launches so the GEMM is the 6th launch (= the one ncu captures)
    dim3 w2grid(WN4/256, 2);
    convert2_kernel<<<w2grid, 256>>>(Wq, gwhi, gwlo,
                                     Wk, gwhi + DIM*DIM, gwlo + DIM*DIM, WN4);
    convert_kernel<<<WN4/256, 256>>>(Wv, gwhi + 2*DIM*DIM, gwlo + 2*DIM*DIM, WN4);
    convert_kernel<<<XN4/256, 256>>>(query, gxhi,               gxlo,               XN4);
    convert_kernel<<<XN4/256, 256>>>(key,   gxhi +   NROWS*DIM, gxlo +   NROWS*DIM, XN4);
    convert_kernel<<<XN4/256, 256>>>(value, gxhi + 2*NROWS*DIM, gxlo + 2*NROWS*DIM, XN4);

    cudaFuncSetAttribute(gemm_mma_kernel,
                         cudaFuncAttributeMaxDynamicSharedMemorySize, GEMM_SMEM);
    dim3 ggrid(DIM / 128, (NROWS + TILE_M - 1) / TILE_M, 3);
    gemm_mma_kernel<<<ggrid, 384, GEMM_SMEM>>>(
        gxhi, gxlo, gwhi, gwlo,
        query, key, value, Wq, Wk, Wv,
        bq, bk, bv, gqkv);

    dim3 lgrid(NROWS / 8, 3);
    lorentz_kernel<<<lgrid, 256>>>(gqkv, lsq, lsk, lsv);

    colsum_kernel<<<BATCH * NHEAD, 64>>>(gv, gcs, as_p, ab_p);
    kkv_kernel<<<BATCH * NHEAD, 256>>>(gk, gv, gM, as_p);

    dim3 agrid(BATCH * NHEAD, SEQ / 32);
    ave_kernel<<<agrid, 256>>>(gq, gM, gcs, out);
}

// round 6
// speedup vs baseline: 1.1022x; 1.1022x over previous
#include <cuda_runtime.h>
#include <cuda_bf16.h>
#include <cstdint>
#include <math.h>

#define BATCH 16
#define SEQ   1024
#define DIM   512
#define NHEAD 8
#define DPH   64
#define NROWS (BATCH*SEQ)   // 16384

// ---------------------------------------------------------------------------
// Scratch (device globals: no allocation allowed anywhere)
// ---------------------------------------------------------------------------
__device__ float g_qkv[3*NROWS*DIM];                 // GEMM outputs (q,k,v)
__device__ __nv_bfloat16 g_xhi[3*NROWS*DIM];
__device__ __nv_bfloat16 g_xlo[3*NROWS*DIM];
__device__ __nv_bfloat16 g_whi[3*DIM*DIM];
__device__ __nv_bfloat16 g_wlo[3*DIM*DIM];
__device__ float g_M[BATCH*NHEAD*DPH*DPH];
__device__ float g_cs[BATCH*NHEAD*DPH];

// ---------------------------------------------------------------------------
// PTX helpers (base-target sm_80+ features only)
// ---------------------------------------------------------------------------
__device__ __forceinline__ uint32_t smem_u32(const void* p) {
    uint32_t a;
    asm("{ .reg .u64 t; cvta.to.shared.u64 t, %1; cvt.u32.u64 %0, t; }"
        : "=r"(a) : "l"(p));
    return a;
}
__device__ __forceinline__ void cp16(uint32_t s, const void* g) {
    asm volatile("cp.async.cg.shared.global [%0], [%1], 16;" :: "r"(s), "l"(g));
}
__device__ __forceinline__ void cp_commit() {
    asm volatile("cp.async.commit_group;" ::: "memory");
}
template <int N>
__device__ __forceinline__ void cp_wait() {
    asm volatile("cp.async.wait_group %0;" :: "n"(N) : "memory");
}
__device__ __forceinline__ void ldsm4(uint32_t* r, uint32_t addr) {
    asm volatile("ldmatrix.sync.aligned.m8n8.x4.shared.b16 {%0,%1,%2,%3}, [%4];"
                 : "=r"(r[0]), "=r"(r[1]), "=r"(r[2]), "=r"(r[3]) : "r"(addr));
}
__device__ __forceinline__ void mma16816(float* c, const uint32_t* a,
                                         uint32_t b0, uint32_t b1) {
    asm volatile(
        "mma.sync.aligned.m16n8k16.row.col.f32.bf16.bf16.f32 "
        "{%0,%1,%2,%3}, {%4,%5,%6,%7}, {%8,%9}, {%0,%1,%2,%3};"
        : "+f"(c[0]), "+f"(c[1]), "+f"(c[2]), "+f"(c[3])
        : "r"(a[0]), "r"(a[1]), "r"(a[2]), "r"(a[3]), "r"(b0), "r"(b1));
}

// ---------------------------------------------------------------------------
// fp32 -> bf16 hi/lo split converters
// ---------------------------------------------------------------------------
__device__ __forceinline__ void split4(float4 x, __nv_bfloat16* hi,
                                       __nv_bfloat16* lo, int i) {
    __nv_bfloat162 h0 = __float22bfloat162_rn(make_float2(x.x, x.y));
    __nv_bfloat162 h1 = __float22bfloat162_rn(make_float2(x.z, x.w));
    float2 hf0 = make_float2(__low2float(h0), __high2float(h0));
    float2 hf1 = make_float2(__low2float(h1), __high2float(h1));
    __nv_bfloat162 l0 = __float22bfloat162_rn(make_float2(x.x - hf0.x, x.y - hf0.y));
    __nv_bfloat162 l1 = __float22bfloat162_rn(make_float2(x.z - hf1.x, x.w - hf1.y));
    reinterpret_cast<__nv_bfloat162*>(hi)[2*i]   = h0;
    reinterpret_cast<__nv_bfloat162*>(hi)[2*i+1] = h1;
    reinterpret_cast<__nv_bfloat162*>(lo)[2*i]   = l0;
    reinterpret_cast<__nv_bfloat162*>(lo)[2*i+1] = l1;
}

__global__ __launch_bounds__(256) void convert_kernel(
    const float* __restrict__ src, __nv_bfloat16* __restrict__ hi,
    __nv_bfloat16* __restrict__ lo, int n4)
{
    int i = blockIdx.x * blockDim.x + threadIdx.x;
    if (i >= n4) return;
    split4(reinterpret_cast<const float4*>(src)[i], hi, lo, i);
}

__global__ __launch_bounds__(256) void convert2_kernel(
    const float* __restrict__ sa, __nv_bfloat16* __restrict__ ha,
    __nv_bfloat16* __restrict__ la,
    const float* __restrict__ sb, __nv_bfloat16* __restrict__ hb,
    __nv_bfloat16* __restrict__ lb, int n4)
{
    int i = blockIdx.x * blockDim.x + threadIdx.x;
    if (i >= n4) return;
    if (blockIdx.y == 0) split4(reinterpret_cast<const float4*>(sa)[i], ha, la, i);
    else                 split4(reinterpret_cast<const float4*>(sb)[i], hb, lb, i);
}

// ---------------------------------------------------------------------------
// HMMA bf16-split GEMM: Y[n,j] = sum_d X[n,d]*W[j,d] + bias[j]
// 128x128 tile, BK=32, 3-stage cp.async pipeline, 8 warps (2x4).
// MMA inner loop in 3 PASSES (hh, hl, lh) so same-accumulator MMAs are
// separated by 15 independent ones -> RAW latency fully hidden.
// ---------------------------------------------------------------------------
#define BK 32
#define LDSS 40                       // bf16 elems per padded smem row
#define MATB (128*LDSS*2)             // 10240 B per matrix tile
#define STGB (4*MATB)                 // Ahi|Alo|Bhi|Blo per stage
#define GEMM_SMEM (3*STGB)            // 122880 B
#define NSTAGE 16                     // K=512 / BK

__global__ __launch_bounds__(256, 1) void gemm_mma_kernel(
    const __nv_bfloat16* __restrict__ Xhi, const __nv_bfloat16* __restrict__ Xlo,
    const __nv_bfloat16* __restrict__ Whi, const __nv_bfloat16* __restrict__ Wlo,
    const float* __restrict__ bq, const float* __restrict__ bk,
    const float* __restrict__ bv, float* __restrict__ Yall)
{
    extern __shared__ char smem[];
    const int z = blockIdx.z;
    const __nv_bfloat16* Ah = Xhi + (size_t)z * NROWS * DIM;
    const __nv_bfloat16* Al = Xlo + (size_t)z * NROWS * DIM;
    const __nv_bfloat16* Bh = Whi + (size_t)z * DIM * DIM;
    const __nv_bfloat16* Bl = Wlo + (size_t)z * DIM * DIM;
    const float* bias = (z == 0) ? bq : (z == 1) ? bk : bv;
    float* Y = Yall + (size_t)z * NROWS * DIM;

    const int bm = blockIdx.y * 128;
    const int bn = blockIdx.x * 128;
    const int tid = threadIdx.x;
    const int wid = tid >> 5, lane = tid & 31;
    const int wm = wid >> 2, wn = wid & 3;

    uint32_t sb = smem_u32(smem);

    const int cr = tid >> 1;
    const int ck = (tid & 1) * 16;
    const __nv_bfloat16* gAh = Ah + (size_t)(bm + cr) * DIM + ck;
    const __nv_bfloat16* gAl = Al + (size_t)(bm + cr) * DIM + ck;
    const __nv_bfloat16* gBh = Bh + (size_t)(bn + cr) * DIM + ck;
    const __nv_bfloat16* gBl = Bl + (size_t)(bn + cr) * DIM + ck;
    const uint32_t srow = (uint32_t)(cr * LDSS + ck) * 2;

#define ISSUE(stage, k0)                                             \
    {                                                                \
        uint32_t s0 = sb + (stage) * STGB + srow;                    \
        cp16(s0 + 0*MATB,      gAh + (k0));                          \
        cp16(s0 + 0*MATB + 16, gAh + (k0) + 8);                      \
        cp16(s0 + 1*MATB,      gAl + (k0));                          \
        cp16(s0 + 1*MATB + 16, gAl + (k0) + 8);                      \
        cp16(s0 + 2*MATB,      gBh + (k0));                          \
        cp16(s0 + 2*MATB + 16, gBh + (k0) + 8);                      \
        cp16(s0 + 3*MATB,      gBl + (k0));                          \
        cp16(s0 + 3*MATB + 16, gBl + (k0) + 8);                      \
        cp_commit();                                                 \
    }

    ISSUE(0, 0)
    ISSUE(1, BK)

    float acc[4][4][4];
#pragma unroll
    for (int i = 0; i < 4; i++)
#pragma unroll
        for (int j = 0; j < 4; j++)
#pragma unroll
            for (int r = 0; r < 4; r++) acc[i][j][r] = 0.f;

    const uint32_t lrow = lane & 15;
    const uint32_t lhalf = (lane >> 4) * 8;

    for (int s = 0; s < NSTAGE; s++) {
        if (s < NSTAGE - 2) cp_wait<1>(); else cp_wait<0>();
        __syncthreads();
        uint32_t st = sb + (s % 3) * STGB;

#pragma unroll
        for (int ks = 0; ks < 2; ks++) {
            uint32_t ahi[4][4], alo[4][4], bhi[2][4], blo[2][4];
#pragma unroll
            for (int mt = 0; mt < 4; mt++) {
                uint32_t addr = st +
                    ((wm*64 + mt*16 + lrow) * LDSS + ks*16 + lhalf) * 2;
                ldsm4(ahi[mt], addr);
                ldsm4(alo[mt], addr + MATB);
            }
#pragma unroll
            for (int bt = 0; bt < 2; bt++) {
                uint32_t addr = st + 2*MATB +
                    ((wn*32 + bt*16 + lrow) * LDSS + ks*16 + lhalf) * 2;
                ldsm4(bhi[bt], addr);
                ldsm4(blo[bt], addr + MATB);
            }
            // PASS 1: Ahi * Bhi (16 independent MMAs)
#pragma unroll
            for (int mt = 0; mt < 4; mt++)
#pragma unroll
                for (int nt = 0; nt < 4; nt++) {
                    int g = nt >> 1, o = nt & 1;
                    mma16816(acc[mt][nt], ahi[mt], bhi[g][o], bhi[g][o+2]);
                }
            // PASS 2: Ahi * Blo
#pragma unroll
            for (int mt = 0; mt < 4; mt++)
#pragma unroll
                for (int nt = 0; nt < 4; nt++) {
                    int g = nt >> 1, o = nt & 1;
                    mma16816(acc[mt][nt], ahi[mt], blo[g][o], blo[g][o+2]);
                }
            // PASS 3: Alo * Bhi
#pragma unroll
            for (int mt = 0; mt < 4; mt++)
#pragma unroll
                for (int nt = 0; nt < 4; nt++) {
                    int g = nt >> 1, o = nt & 1;
                    mma16816(acc[mt][nt], alo[mt], bhi[g][o], bhi[g][o+2]);
                }
        }
        if (s + 2 < NSTAGE) ISSUE((s + 2) % 3, (s + 2) * BK)
        __syncthreads();
    }
#undef ISSUE

    // Epilogue: bias add + store
#pragma unroll
    for (int nt = 0; nt < 4; nt++) {
        int col = bn + wn*32 + nt*8 + (lane & 3)*2;
        float2 b2 = make_float2(bias[col], bias[col+1]);
#pragma unroll
        for (int mt = 0; mt < 4; mt++) {
            int row = bm + wm*64 + mt*16 + (lane >> 2);
            float* y0 = Y + (size_t)row * DIM + col;
            *reinterpret_cast<float2*>(y0) =
                make_float2(acc[mt][nt][0] + b2.x, acc[mt][nt][1] + b2.y);
            *reinterpret_cast<float2*>(y0 + 8 * DIM) =
                make_float2(acc[mt][nt][2] + b2.x, acc[mt][nt][3] + b2.y);
        }
    }
}

// ---------------------------------------------------------------------------
// Lorentz transform: warp-per-row, 3 tensors fused via grid.y
// ---------------------------------------------------------------------------
__global__ __launch_bounds__(256) void lorentz_kernel(
    float* __restrict__ Yall,
    const float* __restrict__ lsq, const float* __restrict__ lsk,
    const float* __restrict__ lsv)
{
    const int z = blockIdx.y;
    float* Y = Yall + (size_t)z * NROWS * DIM;
    const float* ls = (z == 0) ? lsq : (z == 1) ? lsk : lsv;

    int row  = blockIdx.x * 8 + (threadIdx.x >> 5);
    int lane = threadIdx.x & 31;
    float* y = Y + (size_t)row * DIM + lane * 4;

    float4 v[4];
#pragma unroll
    for (int c = 0; c < 4; c++) v[c] = *reinterpret_cast<float4*>(y + c * 128);

    float ss = 0.f;
#pragma unroll
    for (int c = 0; c < 4; c++)
        ss += v[c].x*v[c].x + v[c].y*v[c].y + v[c].z*v[c].z + v[c].w*v[c].w;
    if (lane == 0) ss -= v[0].x * v[0].x;
#pragma unroll
    for (int o = 16; o > 0; o >>= 1) ss += __shfl_xor_sync(0xffffffffu, ss, o);

    float x0 = __shfl_sync(0xffffffffu, v[0].x, 0);
    float time = expf(ls[0]) / (1.f + expf(-x0)) + 1.0001f;
    float scale = sqrtf((time * time - 1.f) / fmaxf(ss, 1e-8f));
#pragma unroll
    for (int c = 0; c < 4; c++) {
        v[c].x *= scale; v[c].y *= scale; v[c].z *= scale; v[c].w *= scale;
    }
    if (lane == 0) v[0].x = time;
#pragma unroll
    for (int c = 0; c < 4; c++) *reinterpret_cast<float4*>(y + c * 128) = v[c];
}

// ---------------------------------------------------------------------------
__global__ __launch_bounds__(64) void colsum_kernel(
    const float* __restrict__ Vb, float* __restrict__ CS,
    const float* __restrict__ as_p, const float* __restrict__ ab_p)
{
    int bh = blockIdx.x;
    int b = bh >> 3, h = bh & 7;
    int d = threadIdx.x;
    const float* vp = Vb + (size_t)b * SEQ * DIM + h * DPH + d;
    float a0 = 0.f, a1 = 0.f, a2 = 0.f, a3 = 0.f;
#pragma unroll 4
    for (int s = 0; s < SEQ; s += 4) {
        a0 += vp[(size_t)(s+0) * DIM];
        a1 += vp[(size_t)(s+1) * DIM];
        a2 += vp[(size_t)(s+2) * DIM];
        a3 += vp[(size_t)(s+3) * DIM];
    }
    float c1 = 2.f / as_p[0] + ab_p[0];
    CS[bh * DPH + d] = (a0 + a1 + a2 + a3) * c1;
}

// ---------------------------------------------------------------------------
__global__ __launch_bounds__(256) void kkv_kernel(
    const float* __restrict__ Kb, const float* __restrict__ Vb,
    float* __restrict__ M, const float* __restrict__ as_p)
{
    int bh = blockIdx.x;
    int b = bh >> 3, h = bh & 7;
    __shared__ float Ks[32][64];
    __shared__ float Vs[32][64];
    int tid = threadIdx.x;
    int d1b = (tid >> 4) * 4;
    int d2b = (tid & 15) * 4;
    int lr = tid >> 3;
    int lc = (tid & 7) * 8;
    float acc[4][4];
#pragma unroll
    for (int i = 0; i < 4; i++)
#pragma unroll
        for (int j = 0; j < 4; j++) acc[i][j] = 0.f;

    const float* kp = Kb + (size_t)b * SEQ * DIM + h * DPH;
    const float* vp = Vb + (size_t)b * SEQ * DIM + h * DPH;

    for (int s0 = 0; s0 < SEQ; s0 += 32) {
        float4 k0 = *(const float4*)(kp + (size_t)(s0+lr) * DIM + lc);
        float4 k1 = *(const float4*)(kp + (size_t)(s0+lr) * DIM + lc + 4);
        float4 v0 = *(const float4*)(vp + (size_t)(s0+lr) * DIM + lc);
        float4 v1 = *(const float4*)(vp + (size_t)(s0+lr) * DIM + lc + 4);
        __syncthreads();
        *(float4*)&Ks[lr][lc]   = k0; *(float4*)&Ks[lr][lc+4] = k1;
        *(float4*)&Vs[lr][lc]   = v0; *(float4*)&Vs[lr][lc+4] = v1;
        __syncthreads();
#pragma unroll
        for (int ss = 0; ss < 32; ss++) {
            float4 kv = *(const float4*)&Ks[ss][d1b];
            float4 vv = *(const float4*)&Vs[ss][d2b];
            float ka[4] = {kv.x, kv.y, kv.z, kv.w};
            float va[4] = {vv.x, vv.y, vv.z, vv.w};
#pragma unroll
            for (int i = 0; i < 4; i++)
#pragma unroll
                for (int j = 0; j < 4; j++) acc[i][j] += ka[i] * va[j];
        }
    }

    float c2 = 2.f / as_p[0];
    float* Mp = M + (size_t)bh * DPH * DPH;
#pragma unroll
    for (int i = 0; i < 4; i++) {
        float sg = (d1b + i == 0) ? -c2 : c2;
#pragma unroll
        for (int j = 0; j < 4; j++)
            Mp[(d1b + i) * DPH + d2b + j] = acc[i][j] * sg;
    }
}

// ---------------------------------------------------------------------------
__global__ __launch_bounds__(256) void ave_kernel(
    const float* __restrict__ Qb, const float* __restrict__ M,
    const float* __restrict__ CS, float* __restrict__ Out)
{
    int bh = blockIdx.x;
    int b = bh >> 3, h = bh & 7;
    int s0 = blockIdx.y * 32;
    int tid = threadIdx.x;
    int warp = tid >> 5, lane = tid & 31;

    __shared__ float Ms[64][64];
    {
        const float* Mp = M + (size_t)bh * DPH * DPH;
        float* Msf = &Ms[0][0];
        for (int i = tid * 4; i < 4096; i += 1024)
            *(float4*)&Msf[i] = *(const float4*)&Mp[i];
    }
    __syncthreads();

    float cs0 = CS[bh * DPH + lane];
    float cs1 = CS[bh * DPH + lane + 32];
    const float* qp = Qb + (size_t)b * SEQ * DIM + h * DPH;

    for (int r = warp; r < 32; r += 8) {
        int srow = s0 + r;
        const float* q = qp + (size_t)srow * DIM;
        float a0 = cs0, a1 = cs1;
#pragma unroll
        for (int dp = 0; dp < 64; dp++) {
            float qv = __ldg(&q[dp]);
            a0 += qv * Ms[dp][lane];
            a1 += qv * Ms[dp][lane + 32];
        }
        float contrib = a0 * a0 * ((lane == 0) ? -1.f : 1.f) + a1 * a1;
#pragma unroll
        for (int o = 16; o > 0; o >>= 1) contrib += __shfl_xor_sync(0xffffffffu, contrib, o);
        float inv = 1.f / sqrtf(fmaxf(fabsf(contrib), 1e-8f));
        size_t ob = ((size_t)b * SEQ + srow) * DIM + h * DPH;
        Out[ob + lane]      = a0 * inv;
        Out[ob + lane + 32] = a1 * inv;
    }
}

// ===========================================================================
extern "C" void kernel_launch(void* const* d_in, const int* in_sizes, int n_in,
                              void* d_out, int out_size)
{
    const float* key   = (const float*)d_in[0];
    const float* value = (const float*)d_in[1];
    const float* query = (const float*)d_in[2];
    const float* Wq  = (const float*)d_in[3];
    const float* bq  = (const float*)d_in[4];
    const float* lsq = (const float*)d_in[5];
    const float* Wk  = (const float*)d_in[6];
    const float* bk  = (const float*)d_in[7];
    const float* lsk = (const float*)d_in[8];
    const float* Wv  = (const float*)d_in[9];
    const float* bv  = (const float*)d_in[10];
    const float* lsv = (const float*)d_in[11];
    const float* as_p = (const float*)d_in[12];
    const float* ab_p = (const float*)d_in[13];
    float* out = (float*)d_out;

    float *gqkv, *gM, *gcs;
    __nv_bfloat16 *gxhi, *gxlo, *gwhi, *gwlo;
    cudaGetSymbolAddress((void**)&gqkv, g_qkv);
    cudaGetSymbolAddress((void**)&gxhi, g_xhi);
    cudaGetSymbolAddress((void**)&gxlo, g_xlo);
    cudaGetSymbolAddress((void**)&gwhi, g_whi);
    cudaGetSymbolAddress((void**)&gwlo, g_wlo);
    cudaGetSymbolAddress((void**)&gM,   g_M);
    cudaGetSymbolAddress((void**)&gcs,  g_cs);

    float* gq = gqkv;
    float* gk = gqkv + (size_t)NROWS * DIM;
    float* gv = gqkv + (size_t)2 * NROWS * DIM;

    const int XN4 = NROWS * DIM / 4;
    const int WN4 = DIM * DIM / 4;

    // 5 convert launches so the GEMM is the 6th launch (= the one ncu captures)
    dim3 w2grid(WN4/256, 2);
    convert2_kernel<<<w2grid, 256>>>(Wq, gwhi, gwlo,
                                     Wk, gwhi + DIM*DIM, gwlo + DIM*DIM, WN4);
    convert_kernel<<<WN4/256, 256>>>(Wv, gwhi + 2*DIM*DIM, gwlo + 2*DIM*DIM, WN4);
    convert_kernel<<<XN4/256, 256>>>(query, gxhi,               gxlo,               XN4);
    convert_kernel<<<XN4/256, 256>>>(key,   gxhi +   NROWS*DIM, gxlo +   NROWS*DIM, XN4);
    convert_kernel<<<XN4/256, 256>>>(value, gxhi + 2*NROWS*DIM, gxlo + 2*NROWS*DIM, XN4);

    cudaFuncSetAttribute(gemm_mma_kernel,
                         cudaFuncAttributeMaxDynamicSharedMemorySize, GEMM_SMEM);
    dim3 ggrid(DIM / 128, NROWS / 128, 3);
    gemm_mma_kernel<<<ggrid, 256, GEMM_SMEM>>>(
        gxhi, gxlo, gwhi, gwlo, bq, bk, bv, gqkv);

    dim3 lgrid(NROWS / 8, 3);
    lorentz_kernel<<<lgrid, 256>>>(gqkv, lsq, lsk, lsv);

    colsum_kernel<<<BATCH * NHEAD, 64>>>(gv, gcs, as_p, ab_p);
    kkv_kernel<<<BATCH * NHEAD, 256>>>(gk, gv, gM, as_p);

    dim3 agrid(BATCH * NHEAD, SEQ / 32);
    ave_kernel<<<agrid, 256>>>(gq, gM, gcs, out);
}

// round 8
// speedup vs baseline: 1.1864x; 1.0764x over previous
#include <cuda_runtime.h>
#include <cuda_bf16.h>
#include <cstdint>
#include <math.h>

#define BATCH 16
#define SEQ   1024
#define DIM   512
#define NHEAD 8
#define DPH   64
#define NROWS (BATCH*SEQ)   // 16384

// ---------------------------------------------------------------------------
// Scratch (device globals: no allocation allowed anywhere)
// ---------------------------------------------------------------------------
__device__ float g_qkv[3*NROWS*DIM];                 // GEMM outputs (q,k,v)
__device__ __nv_bfloat16 g_xhi[3*NROWS*DIM];
__device__ __nv_bfloat16 g_xlo[3*NROWS*DIM];
__device__ __nv_bfloat16 g_whi[3*DIM*DIM];
__device__ __nv_bfloat16 g_wlo[3*DIM*DIM];
__device__ float g_M[BATCH*NHEAD*DPH*DPH];
__device__ float g_cs[BATCH*NHEAD*DPH];

// ---------------------------------------------------------------------------
// PTX helpers (base-target sm_80+ features only)
// ---------------------------------------------------------------------------
__device__ __forceinline__ uint32_t smem_u32(const void* p) {
    uint32_t a;
    asm("{ .reg .u64 t; cvta.to.shared.u64 t, %1; cvt.u32.u64 %0, t; }"
        : "=r"(a) : "l"(p));
    return a;
}
__device__ __forceinline__ void cp16(uint32_t s, const void* g) {
    asm volatile("cp.async.cg.shared.global [%0], [%1], 16;" :: "r"(s), "l"(g));
}
__device__ __forceinline__ void cp_commit() {
    asm volatile("cp.async.commit_group;" ::: "memory");
}
template <int N>
__device__ __forceinline__ void cp_wait() {
    asm volatile("cp.async.wait_group %0;" :: "n"(N) : "memory");
}
__device__ __forceinline__ void ldsm4(uint32_t* r, uint32_t addr) {
    asm volatile("ldmatrix.sync.aligned.m8n8.x4.shared.b16 {%0,%1,%2,%3}, [%4];"
                 : "=r"(r[0]), "=r"(r[1]), "=r"(r[2]), "=r"(r[3]) : "r"(addr));
}
__device__ __forceinline__ void mma16816(float* c, const uint32_t* a,
                                         uint32_t b0, uint32_t b1) {
    asm volatile(
        "mma.sync.aligned.m16n8k16.row.col.f32.bf16.bf16.f32 "
        "{%0,%1,%2,%3}, {%4,%5,%6,%7}, {%8,%9}, {%0,%1,%2,%3};"
        : "+f"(c[0]), "+f"(c[1]), "+f"(c[2]), "+f"(c[3])
        : "r"(a[0]), "r"(a[1]), "r"(a[2]), "r"(a[3]), "r"(b0), "r"(b1));
}

// ---------------------------------------------------------------------------
// fp32 -> bf16 hi/lo split converters
// ---------------------------------------------------------------------------
__device__ __forceinline__ void split4(float4 x, __nv_bfloat16* hi,
                                       __nv_bfloat16* lo, int i) {
    __nv_bfloat162 h0 = __float22bfloat162_rn(make_float2(x.x, x.y));
    __nv_bfloat162 h1 = __float22bfloat162_rn(make_float2(x.z, x.w));
    float2 hf0 = make_float2(__low2float(h0), __high2float(h0));
    float2 hf1 = make_float2(__low2float(h1), __high2float(h1));
    __nv_bfloat162 l0 = __float22bfloat162_rn(make_float2(x.x - hf0.x, x.y - hf0.y));
    __nv_bfloat162 l1 = __float22bfloat162_rn(make_float2(x.z - hf1.x, x.w - hf1.y));
    reinterpret_cast<__nv_bfloat162*>(hi)[2*i]   = h0;
    reinterpret_cast<__nv_bfloat162*>(hi)[2*i+1] = h1;
    reinterpret_cast<__nv_bfloat162*>(lo)[2*i]   = l0;
    reinterpret_cast<__nv_bfloat162*>(lo)[2*i+1] = l1;
}

__global__ __launch_bounds__(256) void convert_kernel(
    const float* __restrict__ src, __nv_bfloat16* __restrict__ hi,
    __nv_bfloat16* __restrict__ lo, int n4)
{
    int i = blockIdx.x * blockDim.x + threadIdx.x;
    if (i >= n4) return;
    split4(reinterpret_cast<const float4*>(src)[i], hi, lo, i);
}

__global__ __launch_bounds__(256) void convert2_kernel(
    const float* __restrict__ sa, __nv_bfloat16* __restrict__ ha,
    __nv_bfloat16* __restrict__ la,
    const float* __restrict__ sb, __nv_bfloat16* __restrict__ hb,
    __nv_bfloat16* __restrict__ lb, int n4)
{
    int i = blockIdx.x * blockDim.x + threadIdx.x;
    if (i >= n4) return;
    if (blockIdx.y == 0) split4(reinterpret_cast<const float4*>(sa)[i], ha, la, i);
    else                 split4(reinterpret_cast<const float4*>(sb)[i], hb, lb, i);
}

// ---------------------------------------------------------------------------
// HMMA bf16-split GEMM: Y[n,j] = sum_d X[n,d]*W[j,d] + bias[j]
// 128x128 tile, BK=32, 3-stage cp.async pipeline, 16 warps (4x4),
// warp tile 32x32 (2 m-tiles x 4 n-tiles). 4 warps/SMSP for issue hiding.
// ---------------------------------------------------------------------------
#define BK 32
#define LDSS 40                       // bf16 elems per padded smem row
#define MATB (128*LDSS*2)             // 10240 B per matrix tile
#define STGB (4*MATB)                 // Ahi|Alo|Bhi|Blo per stage
#define GEMM_SMEM (3*STGB)            // 122880 B
#define NSTAGE 16                     // K=512 / BK

__global__ __launch_bounds__(512, 1) void gemm_mma_kernel(
    const __nv_bfloat16* __restrict__ Xhi, const __nv_bfloat16* __restrict__ Xlo,
    const __nv_bfloat16* __restrict__ Whi, const __nv_bfloat16* __restrict__ Wlo,
    const float* __restrict__ bq, const float* __restrict__ bk,
    const float* __restrict__ bv, float* __restrict__ Yall)
{
    extern __shared__ char smem[];
    const int z = blockIdx.z;
    const float* bias = (z == 0) ? bq : (z == 1) ? bk : bv;
    float* Y = Yall + (size_t)z * NROWS * DIM;

    const int bm = blockIdx.y * 128;
    const int bn = blockIdx.x * 128;
    const int tid = threadIdx.x;
    const int wid = tid >> 5, lane = tid & 31;
    const int wm = wid >> 2, wn = wid & 3;      // 4x4 warp grid, 32x32 tiles

    uint32_t sb = smem_u32(smem);

    // Loader mapping: threads [0,256) stream A(hi/lo), [256,512) stream B(hi/lo).
    // Within each half: row = (t&255)>>1, 16-elem chunk = (t&1).
    const int cr = (tid & 255) >> 1;
    const int ck = (tid & 1) * 16;
    const bool isA = tid < 256;
    const __nv_bfloat16* gh = isA
        ? Xhi + (size_t)z * NROWS * DIM + (size_t)(bm + cr) * DIM + ck
        : Whi + (size_t)z * DIM * DIM   + (size_t)(bn + cr) * DIM + ck;
    const __nv_bfloat16* gl = isA
        ? Xlo + (size_t)z * NROWS * DIM + (size_t)(bm + cr) * DIM + ck
        : Wlo + (size_t)z * DIM * DIM   + (size_t)(bn + cr) * DIM + ck;
    const uint32_t srow = (uint32_t)(cr * LDSS + ck) * 2;
    const uint32_t dhi = (isA ? 0u : 2u) * MATB + srow;
    const uint32_t dlo = dhi + MATB;

#define ISSUE(stage, k0)                                             \
    {                                                                \
        uint32_t s0 = sb + (stage) * STGB;                           \
        cp16(s0 + dhi,      gh + (k0));                              \
        cp16(s0 + dhi + 16, gh + (k0) + 8);                          \
        cp16(s0 + dlo,      gl + (k0));                              \
        cp16(s0 + dlo + 16, gl + (k0) + 8);                          \
        cp_commit();                                                 \
    }

    ISSUE(0, 0)
    ISSUE(1, BK)

    float acc[2][4][4];
#pragma unroll
    for (int i = 0; i < 2; i++)
#pragma unroll
        for (int j = 0; j < 4; j++)
#pragma unroll
            for (int r = 0; r < 4; r++) acc[i][j][r] = 0.f;

    const uint32_t lrow = lane & 15;
    const uint32_t lhalf = (lane >> 4) * 8;

    for (int s = 0; s < NSTAGE; s++) {
        if (s < NSTAGE - 2) cp_wait<1>(); else cp_wait<0>();
        __syncthreads();
        uint32_t st = sb + (s % 3) * STGB;

#pragma unroll
        for (int ks = 0; ks < 2; ks++) {
            uint32_t ahi[2][4], alo[2][4], bhi[2][4], blo[2][4];
#pragma unroll
            for (int mt = 0; mt < 2; mt++) {
                uint32_t addr = st +
                    ((wm*32 + mt*16 + lrow) * LDSS + ks*16 + lhalf) * 2;
                ldsm4(ahi[mt], addr);
                ldsm4(alo[mt], addr + MATB);
            }
#pragma unroll
            for (int bt = 0; bt < 2; bt++) {
                uint32_t addr = st + 2*MATB +
                    ((wn*32 + bt*16 + lrow) * LDSS + ks*16 + lhalf) * 2;
                ldsm4(bhi[bt], addr);
                ldsm4(blo[bt], addr + MATB);
            }
            // PASS 1: Ahi*Bhi (8 independent MMAs)
#pragma unroll
            for (int mt = 0; mt < 2; mt++)
#pragma unroll
                for (int nt = 0; nt < 4; nt++) {
                    int g = nt >> 1, o = nt & 1;
                    mma16816(acc[mt][nt], ahi[mt], bhi[g][o], bhi[g][o+2]);
                }
            // PASS 2: Ahi*Blo
#pragma unroll
            for (int mt = 0; mt < 2; mt++)
#pragma unroll
                for (int nt = 0; nt < 4; nt++) {
                    int g = nt >> 1, o = nt & 1;
                    mma16816(acc[mt][nt], ahi[mt], blo[g][o], blo[g][o+2]);
                }
            // PASS 3: Alo*Bhi
#pragma unroll
            for (int mt = 0; mt < 2; mt++)
#pragma unroll
                for (int nt = 0; nt < 4; nt++) {
                    int g = nt >> 1, o = nt & 1;
                    mma16816(acc[mt][nt], alo[mt], bhi[g][o], bhi[g][o+2]);
                }
        }
        if (s + 2 < NSTAGE) ISSUE((s + 2) % 3, (s + 2) * BK)
        __syncthreads();
    }
#undef ISSUE

    // Epilogue: bias add + store
#pragma unroll
    for (int nt = 0; nt < 4; nt++) {
        int col = bn + wn*32 + nt*8 + (lane & 3)*2;
        float2 b2 = make_float2(bias[col], bias[col+1]);
#pragma unroll
        for (int mt = 0; mt < 2; mt++) {
            int row = bm + wm*32 + mt*16 + (lane >> 2);
            float* y0 = Y + (size_t)row * DIM + col;
            *reinterpret_cast<float2*>(y0) =
                make_float2(acc[mt][nt][0] + b2.x, acc[mt][nt][1] + b2.y);
            *reinterpret_cast<float2*>(y0 + 8 * DIM) =
                make_float2(acc[mt][nt][2] + b2.x, acc[mt][nt][3] + b2.y);
        }
    }
}

// ---------------------------------------------------------------------------
// Lorentz transform: warp-per-row, 3 tensors fused via grid.y
// ---------------------------------------------------------------------------
__global__ __launch_bounds__(256) void lorentz_kernel(
    float* __restrict__ Yall,
    const float* __restrict__ lsq, const float* __restrict__ lsk,
    const float* __restrict__ lsv)
{
    const int z = blockIdx.y;
    float* Y = Yall + (size_t)z * NROWS * DIM;
    const float* ls = (z == 0) ? lsq : (z == 1) ? lsk : lsv;

    int row  = blockIdx.x * 8 + (threadIdx.x >> 5);
    int lane = threadIdx.x & 31;
    float* y = Y + (size_t)row * DIM + lane * 4;

    float4 v[4];
#pragma unroll
    for (int c = 0; c < 4; c++) v[c] = *reinterpret_cast<float4*>(y + c * 128);

    float ss = 0.f;
#pragma unroll
    for (int c = 0; c < 4; c++)
        ss += v[c].x*v[c].x + v[c].y*v[c].y + v[c].z*v[c].z + v[c].w*v[c].w;
    if (lane == 0) ss -= v[0].x * v[0].x;
#pragma unroll
    for (int o = 16; o > 0; o >>= 1) ss += __shfl_xor_sync(0xffffffffu, ss, o);

    float x0 = __shfl_sync(0xffffffffu, v[0].x, 0);
    float time = expf(ls[0]) / (1.f + expf(-x0)) + 1.0001f;
    float scale = sqrtf((time * time - 1.f) / fmaxf(ss, 1e-8f));
#pragma unroll
    for (int c = 0; c < 4; c++) {
        v[c].x *= scale; v[c].y *= scale; v[c].z *= scale; v[c].w *= scale;
    }
    if (lane == 0) v[0].x = time;
#pragma unroll
    for (int c = 0; c < 4; c++) *reinterpret_cast<float4*>(y + c * 128) = v[c];
}

// ---------------------------------------------------------------------------
__global__ __launch_bounds__(64) void colsum_kernel(
    const float* __restrict__ Vb, float* __restrict__ CS,
    const float* __restrict__ as_p, const float* __restrict__ ab_p)
{
    int bh = blockIdx.x;
    int b = bh >> 3, h = bh & 7;
    int d = threadIdx.x;
    const float* vp = Vb + (size_t)b * SEQ * DIM + h * DPH + d;
    float a0 = 0.f, a1 = 0.f, a2 = 0.f, a3 = 0.f;
#pragma unroll 4
    for (int s = 0; s < SEQ; s += 4) {
        a0 += vp[(size_t)(s+0) * DIM];
        a1 += vp[(size_t)(s+1) * DIM];
        a2 += vp[(size_t)(s+2) * DIM];
        a3 += vp[(size_t)(s+3) * DIM];
    }
    float c1 = 2.f / as_p[0] + ab_p[0];
    CS[bh * DPH + d] = (a0 + a1 + a2 + a3) * c1;
}

// ---------------------------------------------------------------------------
__global__ __launch_bounds__(256) void kkv_kernel(
    const float* __restrict__ Kb, const float* __restrict__ Vb,
    float* __restrict__ M, const float* __restrict__ as_p)
{
    int bh = blockIdx.x;
    int b = bh >> 3, h = bh & 7;
    __shared__ float Ks[32][64];
    __shared__ float Vs[32][64];
    int tid = threadIdx.x;
    int d1b = (tid >> 4) * 4;
    int d2b = (tid & 15) * 4;
    int lr = tid >> 3;
    int lc = (tid & 7) * 8;
    float acc[4][4];
#pragma unroll
    for (int i = 0; i < 4; i++)
#pragma unroll
        for (int j = 0; j < 4; j++) acc[i][j] = 0.f;

    const float* kp = Kb + (size_t)b * SEQ * DIM + h * DPH;
    const float* vp = Vb + (size_t)b * SEQ * DIM + h * DPH;

    for (int s0 = 0; s0 < SEQ; s0 += 32) {
        float4 k0 = *(const float4*)(kp + (size_t)(s0+lr) * DIM + lc);
        float4 k1 = *(const float4*)(kp + (size_t)(s0+lr) * DIM + lc + 4);
        float4 v0 = *(const float4*)(vp + (size_t)(s0+lr) * DIM + lc);
        float4 v1 = *(const float4*)(vp + (size_t)(s0+lr) * DIM + lc + 4);
        __syncthreads();
        *(float4*)&Ks[lr][lc]   = k0; *(float4*)&Ks[lr][lc+4] = k1;
        *(float4*)&Vs[lr][lc]   = v0; *(float4*)&Vs[lr][lc+4] = v1;
        __syncthreads();
#pragma unroll
        for (int ss = 0; ss < 32; ss++) {
            float4 kv = *(const float4*)&Ks[ss][d1b];
            float4 vv = *(const float4*)&Vs[ss][d2b];
            float ka[4] = {kv.x, kv.y, kv.z, kv.w};
            float va[4] = {vv.x, vv.y, vv.z, vv.w};
#pragma unroll
            for (int i = 0; i < 4; i++)
#pragma unroll
                for (int j = 0; j < 4; j++) acc[i][j] += ka[i] * va[j];
        }
    }

    float c2 = 2.f / as_p[0];
    float* Mp = M + (size_t)bh * DPH * DPH;
#pragma unroll
    for (int i = 0; i < 4; i++) {
        float sg = (d1b + i == 0) ? -c2 : c2;
#pragma unroll
        for (int j = 0; j < 4; j++)
            Mp[(d1b + i) * DPH + d2b + j] = acc[i][j] * sg;
    }
}

// ---------------------------------------------------------------------------
__global__ __launch_bounds__(256) void ave_kernel(
    const float* __restrict__ Qb, const float* __restrict__ M,
    const float* __restrict__ CS, float* __restrict__ Out)
{
    int bh = blockIdx.x;
    int b = bh >> 3, h = bh & 7;
    int s0 = blockIdx.y * 32;
    int tid = threadIdx.x;
    int warp = tid >> 5, lane = tid & 31;

    __shared__ float Ms[64][64];
    {
        const float* Mp = M + (size_t)bh * DPH * DPH;
        float* Msf = &Ms[0][0];
        for (int i = tid * 4; i < 4096; i += 1024)
            *(float4*)&Msf[i] = *(const float4*)&Mp[i];
    }
    __syncthreads();

    float cs0 = CS[bh * DPH + lane];
    float cs1 = CS[bh * DPH + lane + 32];
    const float* qp = Qb + (size_t)b * SEQ * DIM + h * DPH;

    for (int r = warp; r < 32; r += 8) {
        int srow = s0 + r;
        const float* q = qp + (size_t)srow * DIM;
        float a0 = cs0, a1 = cs1;
#pragma unroll
        for (int dp = 0; dp < 64; dp++) {
            float qv = __ldg(&q[dp]);
            a0 += qv * Ms[dp][lane];
            a1 += qv * Ms[dp][lane + 32];
        }
        float contrib = a0 * a0 * ((lane == 0) ? -1.f : 1.f) + a1 * a1;
#pragma unroll
        for (int o = 16; o > 0; o >>= 1) contrib += __shfl_xor_sync(0xffffffffu, contrib, o);
        float inv = 1.f / sqrtf(fmaxf(fabsf(contrib), 1e-8f));
        size_t ob = ((size_t)b * SEQ + srow) * DIM + h * DPH;
        Out[ob + lane]      = a0 * inv;
        Out[ob + lane + 32] = a1 * inv;
    }
}

// ===========================================================================
extern "C" void kernel_launch(void* const* d_in, const int* in_sizes, int n_in,
                              void* d_out, int out_size)
{
    const float* key   = (const float*)d_in[0];
    const float* value = (const float*)d_in[1];
    const float* query = (const float*)d_in[2];
    const float* Wq  = (const float*)d_in[3];
    const float* bq  = (const float*)d_in[4];
    const float* lsq = (const float*)d_in[5];
    const float* Wk  = (const float*)d_in[6];
    const float* bk  = (const float*)d_in[7];
    const float* lsk = (const float*)d_in[8];
    const float* Wv  = (const float*)d_in[9];
    const float* bv  = (const float*)d_in[10];
    const float* lsv = (const float*)d_in[11];
    const float* as_p = (const float*)d_in[12];
    const float* ab_p = (const float*)d_in[13];
    float* out = (float*)d_out;

    float *gqkv, *gM, *gcs;
    __nv_bfloat16 *gxhi, *gxlo, *gwhi, *gwlo;
    cudaGetSymbolAddress((void**)&gqkv, g_qkv);
    cudaGetSymbolAddress((void**)&gxhi, g_xhi);
    cudaGetSymbolAddress((void**)&gxlo, g_xlo);
    cudaGetSymbolAddress((void**)&gwhi, g_whi);
    cudaGetSymbolAddress((void**)&gwlo, g_wlo);
    cudaGetSymbolAddress((void**)&gM,   g_M);
    cudaGetSymbolAddress((void**)&gcs,  g_cs);

    float* gq = gqkv;
    float* gk = gqkv + (size_t)NROWS * DIM;
    float* gv = gqkv + (size_t)2 * NROWS * DIM;

    const int XN4 = NROWS * DIM / 4;
    const int WN4 = DIM * DIM / 4;

    // 5 convert launches so the GEMM is the 6th launch (= the one ncu captures)
    dim3 w2grid(WN4/256, 2);
    convert2_kernel<<<w2grid, 256>>>(Wq, gwhi, gwlo,
                                     Wk, gwhi + DIM*DIM, gwlo + DIM*DIM, WN4);
    convert_kernel<<<WN4/256, 256>>>(Wv, gwhi + 2*DIM*DIM, gwlo + 2*DIM*DIM, WN4);
    convert_kernel<<<XN4/256, 256>>>(query, gxhi,               gxlo,               XN4);
    convert_kernel<<<XN4/256, 256>>>(key,   gxhi +   NROWS*DIM, gxlo +   NROWS*DIM, XN4);
    convert_kernel<<<XN4/256, 256>>>(value, gxhi + 2*NROWS*DIM, gxlo + 2*NROWS*DIM, XN4);

    cudaFuncSetAttribute(gemm_mma_kernel,
                         cudaFuncAttributeMaxDynamicSharedMemorySize, GEMM_SMEM);
    dim3 ggrid(DIM / 128, NROWS / 128, 3);
    gemm_mma_kernel<<<ggrid, 512, GEMM_SMEM>>>(
        gxhi, gxlo, gwhi, gwlo, bq, bk, bv, gqkv);

    dim3 lgrid(NROWS / 8, 3);
    lorentz_kernel<<<lgrid, 256>>>(gqkv, lsq, lsk, lsv);

    colsum_kernel<<<BATCH * NHEAD, 64>>>(gv, gcs, as_p, ab_p);
    kkv_kernel<<<BATCH * NHEAD, 256>>>(gk, gv, gM, as_p);

    dim3 agrid(BATCH * NHEAD, SEQ / 32);
    ave_kernel<<<agrid, 256>>>(gq, gM, gcs, out);
}

// round 9
// speedup vs baseline: 1.4270x; 1.2028x over previous
#include <cuda_runtime.h>
#include <cuda_fp16.h>
#include <cstdint>
#include <math.h>

#define BATCH 16
#define SEQ   1024
#define DIM   512
#define NHEAD 8
#define DPH   64
#define NROWS (BATCH*SEQ)   // 16384

// ---------------------------------------------------------------------------
// Scratch (device globals: no allocation allowed anywhere)
// ---------------------------------------------------------------------------
__device__ float g_qkv[3*NROWS*DIM];                 // GEMM outputs (q,k,v)
__device__ __half g_xh[3*NROWS*DIM];                 // fp16(x)
__device__ __half g_wh[3*DIM*DIM];                   // fp16 hi of W
__device__ __half g_wl[3*DIM*DIM];                   // fp16 lo of W
__device__ float g_M[BATCH*NHEAD*DPH*DPH];
__device__ float g_cs[BATCH*NHEAD*DPH];

// ---------------------------------------------------------------------------
// PTX helpers (base-target sm_80+ features only)
// ---------------------------------------------------------------------------
__device__ __forceinline__ uint32_t smem_u32(const void* p) {
    uint32_t a;
    asm("{ .reg .u64 t; cvta.to.shared.u64 t, %1; cvt.u32.u64 %0, t; }"
        : "=r"(a) : "l"(p));
    return a;
}
__device__ __forceinline__ void cp16(uint32_t s, const void* g) {
    asm volatile("cp.async.cg.shared.global [%0], [%1], 16;" :: "r"(s), "l"(g));
}
__device__ __forceinline__ void cp_commit() {
    asm volatile("cp.async.commit_group;" ::: "memory");
}
template <int N>
__device__ __forceinline__ void cp_wait() {
    asm volatile("cp.async.wait_group %0;" :: "n"(N) : "memory");
}
__device__ __forceinline__ void ldsm4(uint32_t* r, uint32_t addr) {
    asm volatile("ldmatrix.sync.aligned.m8n8.x4.shared.b16 {%0,%1,%2,%3}, [%4];"
                 : "=r"(r[0]), "=r"(r[1]), "=r"(r[2]), "=r"(r[3]) : "r"(addr));
}
__device__ __forceinline__ void mma16816(float* c, const uint32_t* a,
                                         uint32_t b0, uint32_t b1) {
    asm volatile(
        "mma.sync.aligned.m16n8k16.row.col.f32.f16.f16.f32 "
        "{%0,%1,%2,%3}, {%4,%5,%6,%7}, {%8,%9}, {%0,%1,%2,%3};"
        : "+f"(c[0]), "+f"(c[1]), "+f"(c[2]), "+f"(c[3])
        : "r"(a[0]), "r"(a[1]), "r"(a[2]), "r"(a[3]), "r"(b0), "r"(b1));
}

// ---------------------------------------------------------------------------
// Converters
// ---------------------------------------------------------------------------
// X: fp32 -> fp16 (rn), single output. grid.y selects tensor when batched.
__global__ __launch_bounds__(256) void convert_x_kernel(
    const float* __restrict__ s0, __half* __restrict__ d0,
    const float* __restrict__ s1, __half* __restrict__ d1, int n4)
{
    int i = blockIdx.x * blockDim.x + threadIdx.x;
    if (i >= n4) return;
    const float* s = (blockIdx.y == 0) ? s0 : s1;
    __half*      d = (blockIdx.y == 0) ? d0 : d1;
    float4 x = reinterpret_cast<const float4*>(s)[i];
    __half2 h0 = __float22half2_rn(make_float2(x.x, x.y));
    __half2 h1 = __float22half2_rn(make_float2(x.z, x.w));
    reinterpret_cast<__half2*>(d)[2*i]   = h0;
    reinterpret_cast<__half2*>(d)[2*i+1] = h1;
}

// W: fp32 -> fp16 hi + fp16 lo (residual)
__global__ __launch_bounds__(256) void convert_w_kernel(
    const float* __restrict__ src, __half* __restrict__ hi,
    __half* __restrict__ lo, int n4)
{
    int i = blockIdx.x * blockDim.x + threadIdx.x;
    if (i >= n4) return;
    float4 x = reinterpret_cast<const float4*>(src)[i];
    __half2 h0 = __float22half2_rn(make_float2(x.x, x.y));
    __half2 h1 = __float22half2_rn(make_float2(x.z, x.w));
    float2 hf0 = make_float2(__low2float(h0), __high2float(h0));
    float2 hf1 = make_float2(__low2float(h1), __high2float(h1));
    __half2 l0 = __float22half2_rn(make_float2(x.x - hf0.x, x.y - hf0.y));
    __half2 l1 = __float22half2_rn(make_float2(x.z - hf1.x, x.w - hf1.y));
    reinterpret_cast<__half2*>(hi)[2*i]   = h0;
    reinterpret_cast<__half2*>(hi)[2*i+1] = h1;
    reinterpret_cast<__half2*>(lo)[2*i]   = l0;
    reinterpret_cast<__half2*>(lo)[2*i+1] = l1;
}

// ---------------------------------------------------------------------------
// HMMA fp16 2-term GEMM: Y[n,j] = sum_d X[n,d]*W[j,d] + bias[j]
// 128x128 tile, BK=32, 3-stage cp.async pipeline, 16 warps (4x4),
// warp tile 32x32. Terms: Ah*Bh + Ah*Bl.
// ---------------------------------------------------------------------------
#define BK 32
#define LDSS 40                       // fp16 elems per padded smem row
#define MATB (128*LDSS*2)             // 10240 B per matrix tile
#define STGB (3*MATB)                 // A | Bh | Bl per stage = 30720
#define GEMM_SMEM (3*STGB)            // 92160 B
#define NSTAGE 16                     // K=512 / BK

__global__ __launch_bounds__(512, 1) void gemm_mma_kernel(
    const __half* __restrict__ Xh, const __half* __restrict__ Wh,
    const __half* __restrict__ Wl,
    const float* __restrict__ bq, const float* __restrict__ bk,
    const float* __restrict__ bv, float* __restrict__ Yall)
{
    extern __shared__ char smem[];
    const int z = blockIdx.z;
    const float* bias = (z == 0) ? bq : (z == 1) ? bk : bv;
    float* Y = Yall + (size_t)z * NROWS * DIM;

    const int bm = blockIdx.y * 128;
    const int bn = blockIdx.x * 128;
    const int tid = threadIdx.x;
    const int wid = tid >> 5, lane = tid & 31;
    const int wm = wid >> 2, wn = wid & 3;      // 4x4 warp grid, 32x32 tiles

    uint32_t sb = smem_u32(smem);

    // Loader: threads [0,256) stream A; [256,512) stream Bh+Bl.
    const int cr = (tid & 255) >> 1;
    const int ck = (tid & 1) * 16;
    const bool isA = tid < 256;
    const __half* g0 = isA
        ? Xh + (size_t)z * NROWS * DIM + (size_t)(bm + cr) * DIM + ck
        : Wh + (size_t)z * DIM * DIM   + (size_t)(bn + cr) * DIM + ck;
    const __half* g1 = isA ? (const __half*)nullptr
        : Wl + (size_t)z * DIM * DIM   + (size_t)(bn + cr) * DIM + ck;
    const uint32_t srow = (uint32_t)(cr * LDSS + ck) * 2;
    const uint32_t d0 = (isA ? 0u : 1u) * MATB + srow;
    const uint32_t d1 = 2u * MATB + srow;       // Bl (B threads only)

#define ISSUE(stage, k0)                                             \
    {                                                                \
        uint32_t s0 = sb + (stage) * STGB;                           \
        cp16(s0 + d0,      g0 + (k0));                               \
        cp16(s0 + d0 + 16, g0 + (k0) + 8);                           \
        if (!isA) {                                                  \
            cp16(s0 + d1,      g1 + (k0));                           \
            cp16(s0 + d1 + 16, g1 + (k0) + 8);                       \
        }                                                            \
        cp_commit();                                                 \
    }

    ISSUE(0, 0)
    ISSUE(1, BK)

    float acc[2][4][4];
#pragma unroll
    for (int i = 0; i < 2; i++)
#pragma unroll
        for (int j = 0; j < 4; j++)
#pragma unroll
            for (int r = 0; r < 4; r++) acc[i][j][r] = 0.f;

    const uint32_t lrow = lane & 15;
    const uint32_t lhalf = (lane >> 4) * 8;

    for (int s = 0; s < NSTAGE; s++) {
        if (s < NSTAGE - 2) cp_wait<1>(); else cp_wait<0>();
        __syncthreads();
        uint32_t st = sb + (s % 3) * STGB;

#pragma unroll
        for (int ks = 0; ks < 2; ks++) {
            uint32_t af[2][4], bh[2][4], bl[2][4];
#pragma unroll
            for (int mt = 0; mt < 2; mt++) {
                uint32_t addr = st +
                    ((wm*32 + mt*16 + lrow) * LDSS + ks*16 + lhalf) * 2;
                ldsm4(af[mt], addr);
            }
#pragma unroll
            for (int bt = 0; bt < 2; bt++) {
                uint32_t addr = st + MATB +
                    ((wn*32 + bt*16 + lrow) * LDSS + ks*16 + lhalf) * 2;
                ldsm4(bh[bt], addr);
                ldsm4(bl[bt], addr + MATB);
            }
            // PASS 1: A*Bh (8 independent MMAs)
#pragma unroll
            for (int mt = 0; mt < 2; mt++)
#pragma unroll
                for (int nt = 0; nt < 4; nt++) {
                    int g = nt >> 1, o = nt & 1;
                    mma16816(acc[mt][nt], af[mt], bh[g][o], bh[g][o+2]);
                }
            // PASS 2: A*Bl
#pragma unroll
            for (int mt = 0; mt < 2; mt++)
#pragma unroll
                for (int nt = 0; nt < 4; nt++) {
                    int g = nt >> 1, o = nt & 1;
                    mma16816(acc[mt][nt], af[mt], bl[g][o], bl[g][o+2]);
                }
        }
        if (s + 2 < NSTAGE) ISSUE((s + 2) % 3, (s + 2) * BK)
        __syncthreads();
    }
#undef ISSUE

    // Epilogue: bias add + store
#pragma unroll
    for (int nt = 0; nt < 4; nt++) {
        int col = bn + wn*32 + nt*8 + (lane & 3)*2;
        float2 b2 = make_float2(bias[col], bias[col+1]);
#pragma unroll
        for (int mt = 0; mt < 2; mt++) {
            int row = bm + wm*32 + mt*16 + (lane >> 2);
            float* y0 = Y + (size_t)row * DIM + col;
            *reinterpret_cast<float2*>(y0) =
                make_float2(acc[mt][nt][0] + b2.x, acc[mt][nt][1] + b2.y);
            *reinterpret_cast<float2*>(y0 + 8 * DIM) =
                make_float2(acc[mt][nt][2] + b2.x, acc[mt][nt][3] + b2.y);
        }
    }
}

// ---------------------------------------------------------------------------
// Lorentz transform: warp-per-row, 3 tensors fused via grid.y
// ---------------------------------------------------------------------------
__global__ __launch_bounds__(256) void lorentz_kernel(
    float* __restrict__ Yall,
    const float* __restrict__ lsq, const float* __restrict__ lsk,
    const float* __restrict__ lsv)
{
    const int z = blockIdx.y;
    float* Y = Yall + (size_t)z * NROWS * DIM;
    const float* ls = (z == 0) ? lsq : (z == 1) ? lsk : lsv;

    int row  = blockIdx.x * 8 + (threadIdx.x >> 5);
    int lane = threadIdx.x & 31;
    float* y = Y + (size_t)row * DIM + lane * 4;

    float4 v[4];
#pragma unroll
    for (int c = 0; c < 4; c++) v[c] = *reinterpret_cast<float4*>(y + c * 128);

    float ss = 0.f;
#pragma unroll
    for (int c = 0; c < 4; c++)
        ss += v[c].x*v[c].x + v[c].y*v[c].y + v[c].z*v[c].z + v[c].w*v[c].w;
    if (lane == 0) ss -= v[0].x * v[0].x;
#pragma unroll
    for (int o = 16; o > 0; o >>= 1) ss += __shfl_xor_sync(0xffffffffu, ss, o);

    float x0 = __shfl_sync(0xffffffffu, v[0].x, 0);
    float time = expf(ls[0]) / (1.f + expf(-x0)) + 1.0001f;
    float scale = sqrtf((time * time - 1.f) / fmaxf(ss, 1e-8f));
#pragma unroll
    for (int c = 0; c < 4; c++) {
        v[c].x *= scale; v[c].y *= scale; v[c].z *= scale; v[c].w *= scale;
    }
    if (lane == 0) v[0].x = time;
#pragma unroll
    for (int c = 0; c < 4; c++) *reinterpret_cast<float4*>(y + c * 128) = v[c];
}

// ---------------------------------------------------------------------------
__global__ __launch_bounds__(64) void colsum_kernel(
    const float* __restrict__ Vb, float* __restrict__ CS,
    const float* __restrict__ as_p, const float* __restrict__ ab_p)
{
    int bh = blockIdx.x;
    int b = bh >> 3, h = bh & 7;
    int d = threadIdx.x;
    const float* vp = Vb + (size_t)b * SEQ * DIM + h * DPH + d;
    float a0 = 0.f, a1 = 0.f, a2 = 0.f, a3 = 0.f;
#pragma unroll 4
    for (int s = 0; s < SEQ; s += 4) {
        a0 += vp[(size_t)(s+0) * DIM];
        a1 += vp[(size_t)(s+1) * DIM];
        a2 += vp[(size_t)(s+2) * DIM];
        a3 += vp[(size_t)(s+3) * DIM];
    }
    float c1 = 2.f / as_p[0] + ab_p[0];
    CS[bh * DPH + d] = (a0 + a1 + a2 + a3) * c1;
}

// ---------------------------------------------------------------------------
__global__ __launch_bounds__(256) void kkv_kernel(
    const float* __restrict__ Kb, const float* __restrict__ Vb,
    float* __restrict__ M, const float* __restrict__ as_p)
{
    int bh = blockIdx.x;
    int b = bh >> 3, h = bh & 7;
    __shared__ float Ks[32][64];
    __shared__ float Vs[32][64];
    int tid = threadIdx.x;
    int d1b = (tid >> 4) * 4;
    int d2b = (tid & 15) * 4;
    int lr = tid >> 3;
    int lc = (tid & 7) * 8;
    float acc[4][4];
#pragma unroll
    for (int i = 0; i < 4; i++)
#pragma unroll
        for (int j = 0; j < 4; j++) acc[i][j] = 0.f;

    const float* kp = Kb + (size_t)b * SEQ * DIM + h * DPH;
    const float* vp = Vb + (size_t)b * SEQ * DIM + h * DPH;

    for (int s0 = 0; s0 < SEQ; s0 += 32) {
        float4 k0 = *(const float4*)(kp + (size_t)(s0+lr) * DIM + lc);
        float4 k1 = *(const float4*)(kp + (size_t)(s0+lr) * DIM + lc + 4);
        float4 v0 = *(const float4*)(vp + (size_t)(s0+lr) * DIM + lc);
        float4 v1 = *(const float4*)(vp + (size_t)(s0+lr) * DIM + lc + 4);
        __syncthreads();
        *(float4*)&Ks[lr][lc]   = k0; *(float4*)&Ks[lr][lc+4] = k1;
        *(float4*)&Vs[lr][lc]   = v0; *(float4*)&Vs[lr][lc+4] = v1;
        __syncthreads();
#pragma unroll
        for (int ss = 0; ss < 32; ss++) {
            float4 kv = *(const float4*)&Ks[ss][d1b];
            float4 vv = *(const float4*)&Vs[ss][d2b];
            float ka[4] = {kv.x, kv.y, kv.z, kv.w};
            float va[4] = {vv.x, vv.y, vv.z, vv.w};
#pragma unroll
            for (int i = 0; i < 4; i++)
#pragma unroll
                for (int j = 0; j < 4; j++) acc[i][j] += ka[i] * va[j];
        }
    }

    float c2 = 2.f / as_p[0];
    float* Mp = M + (size_t)bh * DPH * DPH;
#pragma unroll
    for (int i = 0; i < 4; i++) {
        float sg = (d1b + i == 0) ? -c2 : c2;
#pragma unroll
        for (int j = 0; j < 4; j++)
            Mp[(d1b + i) * DPH + d2b + j] = acc[i][j] * sg;
    }
}

// ---------------------------------------------------------------------------
__global__ __launch_bounds__(256) void ave_kernel(
    const float* __restrict__ Qb, const float* __restrict__ M,
    const float* __restrict__ CS, float* __restrict__ Out)
{
    int bh = blockIdx.x;
    int b = bh >> 3, h = bh & 7;
    int s0 = blockIdx.y * 32;
    int tid = threadIdx.x;
    int warp = tid >> 5, lane = tid & 31;

    __shared__ float Ms[64][64];
    {
        const float* Mp = M + (size_t)bh * DPH * DPH;
        float* Msf = &Ms[0][0];
        for (int i = tid * 4; i < 4096; i += 1024)
            *(float4*)&Msf[i] = *(const float4*)&Mp[i];
    }
    __syncthreads();

    float cs0 = CS[bh * DPH + lane];
    float cs1 = CS[bh * DPH + lane + 32];
    const float* qp = Qb + (size_t)b * SEQ * DIM + h * DPH;

    for (int r = warp; r < 32; r += 8) {
        int srow = s0 + r;
        const float* q = qp + (size_t)srow * DIM;
        float a0 = cs0, a1 = cs1;
#pragma unroll
        for (int dp = 0; dp < 64; dp++) {
            float qv = __ldg(&q[dp]);
            a0 += qv * Ms[dp][lane];
            a1 += qv * Ms[dp][lane + 32];
        }
        float contrib = a0 * a0 * ((lane == 0) ? -1.f : 1.f) + a1 * a1;
#pragma unroll
        for (int o = 16; o > 0; o >>= 1) contrib += __shfl_xor_sync(0xffffffffu, contrib, o);
        float inv = 1.f / sqrtf(fmaxf(fabsf(contrib), 1e-8f));
        size_t ob = ((size_t)b * SEQ + srow) * DIM + h * DPH;
        Out[ob + lane]      = a0 * inv;
        Out[ob + lane + 32] = a1 * inv;
    }
}

// ===========================================================================
extern "C" void kernel_launch(void* const* d_in, const int* in_sizes, int n_in,
                              void* d_out, int out_size)
{
    const float* key   = (const float*)d_in[0];
    const float* value = (const float*)d_in[1];
    const float* query = (const float*)d_in[2];
    const float* Wq  = (const float*)d_in[3];
    const float* bq  = (const float*)d_in[4];
    const float* lsq = (const float*)d_in[5];
    const float* Wk  = (const float*)d_in[6];
    const float* bk  = (const float*)d_in[7];
    const float* lsk = (const float*)d_in[8];
    const float* Wv  = (const float*)d_in[9];
    const float* bv  = (const float*)d_in[10];
    const float* lsv = (const float*)d_in[11];
    const float* as_p = (const float*)d_in[12];
    const float* ab_p = (const float*)d_in[13];
    float* out = (float*)d_out;

    float *gqkv, *gM, *gcs;
    __half *gxh, *gwh, *gwl;
    cudaGetSymbolAddress((void**)&gqkv, g_qkv);
    cudaGetSymbolAddress((void**)&gxh,  g_xh);
    cudaGetSymbolAddress((void**)&gwh,  g_wh);
    cudaGetSymbolAddress((void**)&gwl,  g_wl);
    cudaGetSymbolAddress((void**)&gM,   g_M);
    cudaGetSymbolAddress((void**)&gcs,  g_cs);

    float* gq = gqkv;
    float* gk = gqkv + (size_t)NROWS * DIM;
    float* gv = gqkv + (size_t)2 * NROWS * DIM;

    const int XN4 = NROWS * DIM / 4;
    const int WN4 = DIM * DIM / 4;

    // 5 launches before GEMM so ncu (-s 5 -c 1) captures the GEMM
    convert_w_kernel<<<WN4/256, 256>>>(Wq, gwh,             gwl,             WN4);
    convert_w_kernel<<<WN4/256, 256>>>(Wk, gwh + DIM*DIM,   gwl + DIM*DIM,   WN4);
    convert_w_kernel<<<WN4/256, 256>>>(Wv, gwh + 2*DIM*DIM, gwl + 2*DIM*DIM, WN4);
    {
        dim3 g1(XN4/256, 1);
        convert_x_kernel<<<g1, 256>>>(query, gxh, query, gxh, XN4);
        dim3 g2(XN4/256, 2);
        convert_x_kernel<<<g2, 256>>>(key,   gxh +   NROWS*DIM,
                                      value, gxh + 2*NROWS*DIM, XN4);
    }

    cudaFuncSetAttribute(gemm_mma_kernel,
                         cudaFuncAttributeMaxDynamicSharedMemorySize, GEMM_SMEM);
    dim3 ggrid(DIM / 128, NROWS / 128, 3);
    gemm_mma_kernel<<<ggrid, 512, GEMM_SMEM>>>(
        gxh, gwh, gwl, bq, bk, bv, gqkv);

    dim3 lgrid(NROWS / 8, 3);
    lorentz_kernel<<<lgrid, 256>>>(gqkv, lsq, lsk, lsv);

    colsum_kernel<<<BATCH * NHEAD, 64>>>(gv, gcs, as_p, ab_p);
    kkv_kernel<<<BATCH * NHEAD, 256>>>(gk, gv, gM, as_p);

    dim3 agrid(BATCH * NHEAD, SEQ / 32);
    ave_kernel<<<agrid, 256>>>(gq, gM, gcs, out);
}

// round 10
// speedup vs baseline: 1.7141x; 1.2012x over previous
#include <cuda_runtime.h>
#include <cuda_fp16.h>
#include <cstdint>
#include <math.h>

#define BATCH 16
#define SEQ   1024
#define DIM   512
#define NHEAD 8
#define DPH   64
#define NROWS (BATCH*SEQ)   // 16384

// ---------------------------------------------------------------------------
// Scratch (device globals: no allocation allowed anywhere)
// ---------------------------------------------------------------------------
__device__ float g_qkv[3*NROWS*DIM];                 // GEMM outputs (q,k,v)
__device__ __half g_xh[3*NROWS*DIM];                 // fp16(x)
__device__ __half g_wh[3*DIM*DIM];                   // fp16(W)
__device__ float g_M[BATCH*NHEAD*DPH*DPH];
__device__ float g_cs[BATCH*NHEAD*DPH];

// ---------------------------------------------------------------------------
// PTX helpers (base-target sm_80+ features only)
// ---------------------------------------------------------------------------
__device__ __forceinline__ uint32_t smem_u32(const void* p) {
    uint32_t a;
    asm("{ .reg .u64 t; cvta.to.shared.u64 t, %1; cvt.u32.u64 %0, t; }"
        : "=r"(a) : "l"(p));
    return a;
}
__device__ __forceinline__ void cp16(uint32_t s, const void* g) {
    asm volatile("cp.async.cg.shared.global [%0], [%1], 16;" :: "r"(s), "l"(g));
}
__device__ __forceinline__ void cp_commit() {
    asm volatile("cp.async.commit_group;" ::: "memory");
}
template <int N>
__device__ __forceinline__ void cp_wait() {
    asm volatile("cp.async.wait_group %0;" :: "n"(N) : "memory");
}
__device__ __forceinline__ void ldsm4(uint32_t* r, uint32_t addr) {
    asm volatile("ldmatrix.sync.aligned.m8n8.x4.shared.b16 {%0,%1,%2,%3}, [%4];"
                 : "=r"(r[0]), "=r"(r[1]), "=r"(r[2]), "=r"(r[3]) : "r"(addr));
}
__device__ __forceinline__ void mma16816(float* c, const uint32_t* a,
                                         uint32_t b0, uint32_t b1) {
    asm volatile(
        "mma.sync.aligned.m16n8k16.row.col.f32.f16.f16.f32 "
        "{%0,%1,%2,%3}, {%4,%5,%6,%7}, {%8,%9}, {%0,%1,%2,%3};"
        : "+f"(c[0]), "+f"(c[1]), "+f"(c[2]), "+f"(c[3])
        : "r"(a[0]), "r"(a[1]), "r"(a[2]), "r"(a[3]), "r"(b0), "r"(b1));
}

// ---------------------------------------------------------------------------
// Converters: fp32 -> fp16 (rn)
// ---------------------------------------------------------------------------
__global__ __launch_bounds__(256) void convert_x_kernel(
    const float* __restrict__ s0, __half* __restrict__ d0,
    const float* __restrict__ s1, __half* __restrict__ d1, int n4)
{
    int i = blockIdx.x * blockDim.x + threadIdx.x;
    if (i >= n4) return;
    const float* s = (blockIdx.y == 0) ? s0 : s1;
    __half*      d = (blockIdx.y == 0) ? d0 : d1;
    float4 x = reinterpret_cast<const float4*>(s)[i];
    __half2 h0 = __float22half2_rn(make_float2(x.x, x.y));
    __half2 h1 = __float22half2_rn(make_float2(x.z, x.w));
    reinterpret_cast<__half2*>(d)[2*i]   = h0;
    reinterpret_cast<__half2*>(d)[2*i+1] = h1;
}

__global__ __launch_bounds__(256) void convert_w_kernel(
    const float* __restrict__ src, __half* __restrict__ dst, int n4)
{
    int i = blockIdx.x * blockDim.x + threadIdx.x;
    if (i >= n4) return;
    float4 x = reinterpret_cast<const float4*>(src)[i];
    __half2 h0 = __float22half2_rn(make_float2(x.x, x.y));
    __half2 h1 = __float22half2_rn(make_float2(x.z, x.w));
    reinterpret_cast<__half2*>(dst)[2*i]   = h0;
    reinterpret_cast<__half2*>(dst)[2*i+1] = h1;
}

// ---------------------------------------------------------------------------
// HMMA plain-fp16 GEMM: Y[n,j] = sum_d X[n,d]*W[j,d] + bias[j]
// 128x128 tile, BK=32, 3-stage cp.async pipeline, 16 warps (4x4),
// warp tile 32x32.
// ---------------------------------------------------------------------------
#define BK 32
#define LDSS 40                       // fp16 elems per padded smem row
#define MATB (128*LDSS*2)             // 10240 B per matrix tile
#define STGB (2*MATB)                 // A | B per stage = 20480
#define GEMM_SMEM (3*STGB)            // 61440 B
#define NSTAGE 16                     // K=512 / BK

__global__ __launch_bounds__(512, 1) void gemm_mma_kernel(
    const __half* __restrict__ Xh, const __half* __restrict__ Wh,
    const float* __restrict__ bq, const float* __restrict__ bk,
    const float* __restrict__ bv, float* __restrict__ Yall)
{
    extern __shared__ char smem[];
    const int z = blockIdx.z;
    const float* bias = (z == 0) ? bq : (z == 1) ? bk : bv;
    float* Y = Yall + (size_t)z * NROWS * DIM;

    const int bm = blockIdx.y * 128;
    const int bn = blockIdx.x * 128;
    const int tid = threadIdx.x;
    const int wid = tid >> 5, lane = tid & 31;
    const int wm = wid >> 2, wn = wid & 3;      // 4x4 warp grid, 32x32 tiles

    uint32_t sb = smem_u32(smem);

    // Loader: threads [0,256) stream A; [256,512) stream B.
    const int cr = (tid & 255) >> 1;
    const int ck = (tid & 1) * 16;
    const bool isA = tid < 256;
    const __half* g0 = isA
        ? Xh + (size_t)z * NROWS * DIM + (size_t)(bm + cr) * DIM + ck
        : Wh + (size_t)z * DIM * DIM   + (size_t)(bn + cr) * DIM + ck;
    const uint32_t d0 = (isA ? 0u : 1u) * MATB + (uint32_t)(cr * LDSS + ck) * 2;

#define ISSUE(stage, k0)                                             \
    {                                                                \
        uint32_t s0 = sb + (stage) * STGB;                           \
        cp16(s0 + d0,      g0 + (k0));                               \
        cp16(s0 + d0 + 16, g0 + (k0) + 8);                           \
        cp_commit();                                                 \
    }

    ISSUE(0, 0)
    ISSUE(1, BK)

    float acc[2][4][4];
#pragma unroll
    for (int i = 0; i < 2; i++)
#pragma unroll
        for (int j = 0; j < 4; j++)
#pragma unroll
            for (int r = 0; r < 4; r++) acc[i][j][r] = 0.f;

    const uint32_t lrow = lane & 15;
    const uint32_t lhalf = (lane >> 4) * 8;

    for (int s = 0; s < NSTAGE; s++) {
        if (s < NSTAGE - 2) cp_wait<1>(); else cp_wait<0>();
        __syncthreads();
        uint32_t st = sb + (s % 3) * STGB;

#pragma unroll
        for (int ks = 0; ks < 2; ks++) {
            uint32_t af[2][4], bf[2][4];
#pragma unroll
            for (int mt = 0; mt < 2; mt++) {
                uint32_t addr = st +
                    ((wm*32 + mt*16 + lrow) * LDSS + ks*16 + lhalf) * 2;
                ldsm4(af[mt], addr);
            }
#pragma unroll
            for (int bt = 0; bt < 2; bt++) {
                uint32_t addr = st + MATB +
                    ((wn*32 + bt*16 + lrow) * LDSS + ks*16 + lhalf) * 2;
                ldsm4(bf[bt], addr);
            }
#pragma unroll
            for (int mt = 0; mt < 2; mt++)
#pragma unroll
                for (int nt = 0; nt < 4; nt++) {
                    int g = nt >> 1, o = nt & 1;
                    mma16816(acc[mt][nt], af[mt], bf[g][o], bf[g][o+2]);
                }
        }
        if (s + 2 < NSTAGE) ISSUE((s + 2) % 3, (s + 2) * BK)
        __syncthreads();
    }
#undef ISSUE

    // Epilogue: bias add + store
#pragma unroll
    for (int nt = 0; nt < 4; nt++) {
        int col = bn + wn*32 + nt*8 + (lane & 3)*2;
        float2 b2 = make_float2(bias[col], bias[col+1]);
#pragma unroll
        for (int mt = 0; mt < 2; mt++) {
            int row = bm + wm*32 + mt*16 + (lane >> 2);
            float* y0 = Y + (size_t)row * DIM + col;
            *reinterpret_cast<float2*>(y0) =
                make_float2(acc[mt][nt][0] + b2.x, acc[mt][nt][1] + b2.y);
            *reinterpret_cast<float2*>(y0 + 8 * DIM) =
                make_float2(acc[mt][nt][2] + b2.x, acc[mt][nt][3] + b2.y);
        }
    }
}

// ---------------------------------------------------------------------------
// Lorentz transform: warp-per-row, 3 tensors fused via grid.y
// ---------------------------------------------------------------------------
__global__ __launch_bounds__(256) void lorentz_kernel(
    float* __restrict__ Yall,
    const float* __restrict__ lsq, const float* __restrict__ lsk,
    const float* __restrict__ lsv)
{
    const int z = blockIdx.y;
    float* Y = Yall + (size_t)z * NROWS * DIM;
    const float* ls = (z == 0) ? lsq : (z == 1) ? lsk : lsv;

    int row  = blockIdx.x * 8 + (threadIdx.x >> 5);
    int lane = threadIdx.x & 31;
    float* y = Y + (size_t)row * DIM + lane * 4;

    float4 v[4];
#pragma unroll
    for (int c = 0; c < 4; c++) v[c] = *reinterpret_cast<float4*>(y + c * 128);

    float ss = 0.f;
#pragma unroll
    for (int c = 0; c < 4; c++)
        ss += v[c].x*v[c].x + v[c].y*v[c].y + v[c].z*v[c].z + v[c].w*v[c].w;
    if (lane == 0) ss -= v[0].x * v[0].x;
#pragma unroll
    for (int o = 16; o > 0; o >>= 1) ss += __shfl_xor_sync(0xffffffffu, ss, o);

    float x0 = __shfl_sync(0xffffffffu, v[0].x, 0);
    float time = expf(ls[0]) / (1.f + expf(-x0)) + 1.0001f;
    float scale = sqrtf((time * time - 1.f) / fmaxf(ss, 1e-8f));
#pragma unroll
    for (int c = 0; c < 4; c++) {
        v[c].x *= scale; v[c].y *= scale; v[c].z *= scale; v[c].w *= scale;
    }
    if (lane == 0) v[0].x = time;
#pragma unroll
    for (int c = 0; c < 4; c++) *reinterpret_cast<float4*>(y + c * 128) = v[c];
}

// ---------------------------------------------------------------------------
__global__ __launch_bounds__(64) void colsum_kernel(
    const float* __restrict__ Vb, float* __restrict__ CS,
    const float* __restrict__ as_p, const float* __restrict__ ab_p)
{
    int bh = blockIdx.x;
    int b = bh >> 3, h = bh & 7;
    int d = threadIdx.x;
    const float* vp = Vb + (size_t)b * SEQ * DIM + h * DPH + d;
    float a0 = 0.f, a1 = 0.f, a2 = 0.f, a3 = 0.f;
#pragma unroll 4
    for (int s = 0; s < SEQ; s += 4) {
        a0 += vp[(size_t)(s+0) * DIM];
        a1 += vp[(size_t)(s+1) * DIM];
        a2 += vp[(size_t)(s+2) * DIM];
        a3 += vp[(size_t)(s+3) * DIM];
    }
    float c1 = 2.f / as_p[0] + ab_p[0];
    CS[bh * DPH + d] = (a0 + a1 + a2 + a3) * c1;
}

// ---------------------------------------------------------------------------
__global__ __launch_bounds__(256) void kkv_kernel(
    const float* __restrict__ Kb, const float* __restrict__ Vb,
    float* __restrict__ M, const float* __restrict__ as_p)
{
    int bh = blockIdx.x;
    int b = bh >> 3, h = bh & 7;
    __shared__ float Ks[32][64];
    __shared__ float Vs[32][64];
    int tid = threadIdx.x;
    int d1b = (tid >> 4) * 4;
    int d2b = (tid & 15) * 4;
    int lr = tid >> 3;
    int lc = (tid & 7) * 8;
    float acc[4][4];
#pragma unroll
    for (int i = 0; i < 4; i++)
#pragma unroll
        for (int j = 0; j < 4; j++) acc[i][j] = 0.f;

    const float* kp = Kb + (size_t)b * SEQ * DIM + h * DPH;
    const float* vp = Vb + (size_t)b * SEQ * DIM + h * DPH;

    for (int s0 = 0; s0 < SEQ; s0 += 32) {
        float4 k0 = *(const float4*)(kp + (size_t)(s0+lr) * DIM + lc);
        float4 k1 = *(const float4*)(kp + (size_t)(s0+lr) * DIM + lc + 4);
        float4 v0 = *(const float4*)(vp + (size_t)(s0+lr) * DIM + lc);
        float4 v1 = *(const float4*)(vp + (size_t)(s0+lr) * DIM + lc + 4);
        __syncthreads();
        *(float4*)&Ks[lr][lc]   = k0; *(float4*)&Ks[lr][lc+4] = k1;
        *(float4*)&Vs[lr][lc]   = v0; *(float4*)&Vs[lr][lc+4] = v1;
        __syncthreads();
#pragma unroll
        for (int ss = 0; ss < 32; ss++) {
            float4 kv = *(const float4*)&Ks[ss][d1b];
            float4 vv = *(const float4*)&Vs[ss][d2b];
            float ka[4] = {kv.x, kv.y, kv.z, kv.w};
            float va[4] = {vv.x, vv.y, vv.z, vv.w};
#pragma unroll
            for (int i = 0; i < 4; i++)
#pragma unroll
                for (int j = 0; j < 4; j++) acc[i][j] += ka[i] * va[j];
        }
    }

    float c2 = 2.f / as_p[0];
    float* Mp = M + (size_t)bh * DPH * DPH;
#pragma unroll
    for (int i = 0; i < 4; i++) {
        float sg = (d1b + i == 0) ? -c2 : c2;
#pragma unroll
        for (int j = 0; j < 4; j++)
            Mp[(d1b + i) * DPH + d2b + j] = acc[i][j] * sg;
    }
}

// ---------------------------------------------------------------------------
__global__ __launch_bounds__(256) void ave_kernel(
    const float* __restrict__ Qb, const float* __restrict__ M,
    const float* __restrict__ CS, float* __restrict__ Out)
{
    int bh = blockIdx.x;
    int b = bh >> 3, h = bh & 7;
    int s0 = blockIdx.y * 32;
    int tid = threadIdx.x;
    int warp = tid >> 5, lane = tid & 31;

    __shared__ float Ms[64][64];
    {
        const float* Mp = M + (size_t)bh * DPH * DPH;
        float* Msf = &Ms[0][0];
        for (int i = tid * 4; i < 4096; i += 1024)
            *(float4*)&Msf[i] = *(const float4*)&Mp[i];
    }
    __syncthreads();

    float cs0 = CS[bh * DPH + lane];
    float cs1 = CS[bh * DPH + lane + 32];
    const float* qp = Qb + (size_t)b * SEQ * DIM + h * DPH;

    for (int r = warp; r < 32; r += 8) {
        int srow = s0 + r;
        const float* q = qp + (size_t)srow * DIM;
        float a0 = cs0, a1 = cs1;
#pragma unroll
        for (int dp = 0; dp < 64; dp++) {
            float qv = __ldg(&q[dp]);
            a0 += qv * Ms[dp][lane];
            a1 += qv * Ms[dp][lane + 32];
        }
        float contrib = a0 * a0 * ((lane == 0) ? -1.f : 1.f) + a1 * a1;
#pragma unroll
        for (int o = 16; o > 0; o >>= 1) contrib += __shfl_xor_sync(0xffffffffu, contrib, o);
        float inv = 1.f / sqrtf(fmaxf(fabsf(contrib), 1e-8f));
        size_t ob = ((size_t)b * SEQ + srow) * DIM + h * DPH;
        Out[ob + lane]      = a0 * inv;
        Out[ob + lane + 32] = a1 * inv;
    }
}

// ===========================================================================
extern "C" void kernel_launch(void* const* d_in, const int* in_sizes, int n_in,
                              void* d_out, int out_size)
{
    const float* key   = (const float*)d_in[0];
    const float* value = (const float*)d_in[1];
    const float* query = (const float*)d_in[2];
    const float* Wq  = (const float*)d_in[3];
    const float* bq  = (const float*)d_in[4];
    const float* lsq = (const float*)d_in[5];
    const float* Wk  = (const float*)d_in[6];
    const float* bk  = (const float*)d_in[7];
    const float* lsk = (const float*)d_in[8];
    const float* Wv  = (const float*)d_in[9];
    const float* bv  = (const float*)d_in[10];
    const float* lsv = (const float*)d_in[11];
    const float* as_p = (const float*)d_in[12];
    const float* ab_p = (const float*)d_in[13];
    float* out = (float*)d_out;

    float *gqkv, *gM, *gcs;
    __half *gxh, *gwh;
    cudaGetSymbolAddress((void**)&gqkv, g_qkv);
    cudaGetSymbolAddress((void**)&gxh,  g_xh);
    cudaGetSymbolAddress((void**)&gwh,  g_wh);
    cudaGetSymbolAddress((void**)&gM,   g_M);
    cudaGetSymbolAddress((void**)&gcs,  g_cs);

    float* gq = gqkv;
    float* gk = gqkv + (size_t)NROWS * DIM;
    float* gv = gqkv + (size_t)2 * NROWS * DIM;

    const int XN4 = NROWS * DIM / 4;
    const int WN4 = DIM * DIM / 4;

    // 5 launches before GEMM so ncu (-s 5 -c 1) captures the GEMM
    convert_w_kernel<<<WN4/256, 256>>>(Wq, gwh,             WN4);
    convert_w_kernel<<<WN4/256, 256>>>(Wk, gwh + DIM*DIM,   WN4);
    convert_w_kernel<<<WN4/256, 256>>>(Wv, gwh + 2*DIM*DIM, WN4);
    {
        dim3 g1(XN4/256, 1);
        convert_x_kernel<<<g1, 256>>>(query, gxh, query, gxh, XN4);
        dim3 g2(XN4/256, 2);
        convert_x_kernel<<<g2, 256>>>(key,   gxh +   NROWS*DIM,
                                      value, gxh + 2*NROWS*DIM, XN4);
    }

    cudaFuncSetAttribute(gemm_mma_kernel,
                         cudaFuncAttributeMaxDynamicSharedMemorySize, GEMM_SMEM);
    dim3 ggrid(DIM / 128, NROWS / 128, 3);
    gemm_mma_kernel<<<ggrid, 512, GEMM_SMEM>>>(
        gxh, gwh, bq, bk, bv, gqkv);

    dim3 lgrid(NROWS / 8, 3);
    lorentz_kernel<<<lgrid, 256>>>(gqkv, lsq, lsk, lsv);

    colsum_kernel<<<BATCH * NHEAD, 64>>>(gv, gcs, as_p, ab_p);
    kkv_kernel<<<BATCH * NHEAD, 256>>>(gk, gv, gM, as_p);

    dim3 agrid(BATCH * NHEAD, SEQ / 32);
    ave_kernel<<<agrid, 256>>>(gq, gM, gcs, out);
}

// round 12
// speedup vs baseline: 1.7328x; 1.0109x over previous
#include <cuda_runtime.h>
#include <cuda_fp16.h>
#include <cstdint>
#include <math.h>

#define BATCH 16
#define SEQ   1024
#define DIM   512
#define NHEAD 8
#define DPH   64
#define NROWS (BATCH*SEQ)   // 16384

// ---------------------------------------------------------------------------
// Scratch (device globals: no allocation allowed anywhere)
// ---------------------------------------------------------------------------
__device__ float g_qkv[3*NROWS*DIM];                 // GEMM outputs (q,k,v)
__device__ __half g_xh[3*NROWS*DIM];                 // fp16(x)
__device__ __half g_wh[3*DIM*DIM];                   // fp16(W)
__device__ float g_M[BATCH*NHEAD*DPH*DPH];
__device__ float g_cs[BATCH*NHEAD*DPH];

// ---------------------------------------------------------------------------
// PTX helpers (base-target sm_80+ features only)
// ---------------------------------------------------------------------------
__device__ __forceinline__ uint32_t smem_u32(const void* p) {
    uint32_t a;
    asm("{ .reg .u64 t; cvta.to.shared.u64 t, %1; cvt.u32.u64 %0, t; }"
        : "=r"(a) : "l"(p));
    return a;
}
__device__ __forceinline__ void cp16(uint32_t s, const void* g) {
    asm volatile("cp.async.cg.shared.global [%0], [%1], 16;" :: "r"(s), "l"(g));
}
__device__ __forceinline__ void cp_commit() {
    asm volatile("cp.async.commit_group;" ::: "memory");
}
template <int N>
__device__ __forceinline__ void cp_wait() {
    asm volatile("cp.async.wait_group %0;" :: "n"(N) : "memory");
}
__device__ __forceinline__ void ldsm4(uint32_t* r, uint32_t addr) {
    asm volatile("ldmatrix.sync.aligned.m8n8.x4.shared.b16 {%0,%1,%2,%3}, [%4];"
                 : "=r"(r[0]), "=r"(r[1]), "=r"(r[2]), "=r"(r[3]) : "r"(addr));
}
__device__ __forceinline__ void mma16816(float* c, const uint32_t* a,
                                         uint32_t b0, uint32_t b1) {
    asm volatile(
        "mma.sync.aligned.m16n8k16.row.col.f32.f16.f16.f32 "
        "{%0,%1,%2,%3}, {%4,%5,%6,%7}, {%8,%9}, {%0,%1,%2,%3};"
        : "+f"(c[0]), "+f"(c[1]), "+f"(c[2]), "+f"(c[3])
        : "r"(a[0]), "r"(a[1]), "r"(a[2]), "r"(a[3]), "r"(b0), "r"(b1));
}

// ---------------------------------------------------------------------------
// Converters: fp32 -> fp16 (rn)
// ---------------------------------------------------------------------------
__global__ __launch_bounds__(256) void convert_x_kernel(
    const float* __restrict__ s0, __half* __restrict__ d0,
    const float* __restrict__ s1, __half* __restrict__ d1, int n4)
{
    int i = blockIdx.x * blockDim.x + threadIdx.x;
    if (i >= n4) return;
    const float* s = (blockIdx.y == 0) ? s0 : s1;
    __half*      d = (blockIdx.y == 0) ? d0 : d1;
    float4 x = reinterpret_cast<const float4*>(s)[i];
    __half2 h0 = __float22half2_rn(make_float2(x.x, x.y));
    __half2 h1 = __float22half2_rn(make_float2(x.z, x.w));
    reinterpret_cast<__half2*>(d)[2*i]   = h0;
    reinterpret_cast<__half2*>(d)[2*i+1] = h1;
}

__global__ __launch_bounds__(256) void convert_w_kernel(
    const float* __restrict__ src, __half* __restrict__ dst, int n4)
{
    int i = blockIdx.x * blockDim.x + threadIdx.x;
    if (i >= n4) return;
    float4 x = reinterpret_cast<const float4*>(src)[i];
    __half2 h0 = __float22half2_rn(make_float2(x.x, x.y));
    __half2 h1 = __float22half2_rn(make_float2(x.z, x.w));
    reinterpret_cast<__half2*>(dst)[2*i]   = h0;
    reinterpret_cast<__half2*>(dst)[2*i+1] = h1;
}

// ---------------------------------------------------------------------------
// HMMA plain-fp16 GEMM: Y[n,j] = sum_d X[n,d]*W[j,d] + bias[j]
// 256x128 CTA tile, BK=32, 3-stage cp.async pipeline, 16 warps (4x4),
// warp tile 64x32 (4 m-frags x 4 n-tiles).
// ---------------------------------------------------------------------------
#define BK 32
#define LDSS 40                       // fp16 elems per padded smem row
#define AMATB (256*LDSS*2)            // 20480 B: A tile (256 rows)
#define BMATB (128*LDSS*2)            // 10240 B: B tile (128 rows)
#define STGB (AMATB + BMATB)          // 30720 B per stage
#define GEMM_SMEM (3*STGB)            // 92160 B
#define NSTAGE 16                     // K=512 / BK

__global__ __launch_bounds__(512, 1) void gemm_mma_kernel(
    const __half* __restrict__ Xh, const __half* __restrict__ Wh,
    const float* __restrict__ bq, const float* __restrict__ bk,
    const float* __restrict__ bv, float* __restrict__ Yall)
{
    extern __shared__ char smem[];
    const int z = blockIdx.z;
    const float* bias = (z == 0) ? bq : (z == 1) ? bk : bv;
    float* Y = Yall + (size_t)z * NROWS * DIM;

    const int bm = blockIdx.y * 256;
    const int bn = blockIdx.x * 128;
    const int tid = threadIdx.x;
    const int wid = tid >> 5, lane = tid & 31;
    const int wm = wid >> 2, wn = wid & 3;      // 4x4 warp grid, 64x32 tiles

    uint32_t sb = smem_u32(smem);

    // Loaders: all 512 threads load A (2 cp16: full 16-elem chunk);
    // threads [0,256) additionally load B (2 cp16).
    const int ar = tid >> 1;
    const int ac = (tid & 1) * 16;
    const __half* gA = Xh + (size_t)z * NROWS * DIM + (size_t)(bm + ar) * DIM + ac;
    const uint32_t da = (uint32_t)(ar * LDSS + ac) * 2;
    const bool hasB = tid < 256;
    const int br = (tid & 255) >> 1;
    const int bc = (tid & 1) * 16;
    const __half* gB = Wh + (size_t)z * DIM * DIM + (size_t)(bn + br) * DIM + bc;
    const uint32_t db = AMATB + (uint32_t)(br * LDSS + bc) * 2;

#define ISSUE(stage, k0)                                             \
    {                                                                \
        uint32_t s0 = sb + (stage) * STGB;                           \
        cp16(s0 + da,      gA + (k0));                               \
        cp16(s0 + da + 16, gA + (k0) + 8);                           \
        if (hasB) {                                                  \
            cp16(s0 + db,      gB + (k0));                           \
            cp16(s0 + db + 16, gB + (k0) + 8);                       \
        }                                                            \
        cp_commit();                                                 \
    }

    ISSUE(0, 0)
    ISSUE(1, BK)

    float acc[4][4][4];
#pragma unroll
    for (int i = 0; i < 4; i++)
#pragma unroll
        for (int j = 0; j < 4; j++)
#pragma unroll
            for (int r = 0; r < 4; r++) acc[i][j][r] = 0.f;

    const uint32_t lrow = lane & 15;
    const uint32_t lhalf = (lane >> 4) * 8;

    for (int s = 0; s < NSTAGE; s++) {
        if (s < NSTAGE - 2) cp_wait<1>(); else cp_wait<0>();
        __syncthreads();
        uint32_t st = sb + (s % 3) * STGB;

#pragma unroll
        for (int ks = 0; ks < 2; ks++) {
            uint32_t af[4][4], bf[2][4];
#pragma unroll
            for (int mt = 0; mt < 4; mt++) {
                uint32_t addr = st +
                    ((wm*64 + mt*16 + lrow) * LDSS + ks*16 + lhalf) * 2;
                ldsm4(af[mt], addr);
            }
#pragma unroll
            for (int bt = 0; bt < 2; bt++) {
                uint32_t addr = st + AMATB +
                    ((wn*32 + bt*16 + lrow) * LDSS + ks*16 + lhalf) * 2;
                ldsm4(bf[bt], addr);
            }
#pragma unroll
            for (int mt = 0; mt < 4; mt++)
#pragma unroll
                for (int nt = 0; nt < 4; nt++) {
                    int g = nt >> 1, o = nt & 1;
                    mma16816(acc[mt][nt], af[mt], bf[g][o], bf[g][o+2]);
                }
        }
        if (s + 2 < NSTAGE) ISSUE((s + 2) % 3, (s + 2) * BK)
        __syncthreads();
    }
#undef ISSUE

    // Epilogue: bias add + store
#pragma unroll
    for (int nt = 0; nt < 4; nt++) {
        int col = bn + wn*32 + nt*8 + (lane & 3)*2;
        float2 b2 = make_float2(bias[col], bias[col+1]);
#pragma unroll
        for (int mt = 0; mt < 4; mt++) {
            int row = bm + wm*64 + mt*16 + (lane >> 2);
            float* y0 = Y + (size_t)row * DIM + col;
            *reinterpret_cast<float2*>(y0) =
                make_float2(acc[mt][nt][0] + b2.x, acc[mt][nt][1] + b2.y);
            *reinterpret_cast<float2*>(y0 + 8 * DIM) =
                make_float2(acc[mt][nt][2] + b2.x, acc[mt][nt][3] + b2.y);
        }
    }
}

// ---------------------------------------------------------------------------
// Lorentz transform: warp-per-row, 3 tensors fused via grid.y
// ---------------------------------------------------------------------------
__global__ __launch_bounds__(256) void lorentz_kernel(
    float* __restrict__ Yall,
    const float* __restrict__ lsq, const float* __restrict__ lsk,
    const float* __restrict__ lsv)
{
    const int z = blockIdx.y;
    float* Y = Yall + (size_t)z * NROWS * DIM;
    const float* ls = (z == 0) ? lsq : (z == 1) ? lsk : lsv;

    int row  = blockIdx.x * 8 + (threadIdx.x >> 5);
    int lane = threadIdx.x & 31;
    float* y = Y + (size_t)row * DIM + lane * 4;

    float4 v[4];
#pragma unroll
    for (int c = 0; c < 4; c++) v[c] = *reinterpret_cast<float4*>(y + c * 128);

    float ss = 0.f;
#pragma unroll
    for (int c = 0; c < 4; c++)
        ss += v[c].x*v[c].x + v[c].y*v[c].y + v[c].z*v[c].z + v[c].w*v[c].w;
    if (lane == 0) ss -= v[0].x * v[0].x;
#pragma unroll
    for (int o = 16; o > 0; o >>= 1) ss += __shfl_xor_sync(0xffffffffu, ss, o);

    float x0 = __shfl_sync(0xffffffffu, v[0].x, 0);
    float time = expf(ls[0]) / (1.f + expf(-x0)) + 1.0001f;
    float scale = sqrtf((time * time - 1.f) / fmaxf(ss, 1e-8f));
#pragma unroll
    for (int c = 0; c < 4; c++) {
        v[c].x *= scale; v[c].y *= scale; v[c].z *= scale; v[c].w *= scale;
    }
    if (lane == 0) v[0].x = time;
#pragma unroll
    for (int c = 0; c < 4; c++) *reinterpret_cast<float4*>(y + c * 128) = v[c];
}

// ---------------------------------------------------------------------------
__global__ __launch_bounds__(64) void colsum_kernel(
    const float* __restrict__ Vb, float* __restrict__ CS,
    const float* __restrict__ as_p, const float* __restrict__ ab_p)
{
    int bh = blockIdx.x;
    int b = bh >> 3, h = bh & 7;
    int d = threadIdx.x;
    const float* vp = Vb + (size_t)b * SEQ * DIM + h * DPH + d;
    float a0 = 0.f, a1 = 0.f, a2 = 0.f, a3 = 0.f;
#pragma unroll 4
    for (int s = 0; s < SEQ; s += 4) {
        a0 += vp[(size_t)(s+0) * DIM];
        a1 += vp[(size_t)(s+1) * DIM];
        a2 += vp[(size_t)(s+2) * DIM];
        a3 += vp[(size_t)(s+3) * DIM];
    }
    float c1 = 2.f / as_p[0] + ab_p[0];
    CS[bh * DPH + d] = (a0 + a1 + a2 + a3) * c1;
}

// ---------------------------------------------------------------------------
__global__ __launch_bounds__(256) void kkv_kernel(
    const float* __restrict__ Kb, const float* __restrict__ Vb,
    float* __restrict__ M, const float* __restrict__ as_p)
{
    int bh = blockIdx.x;
    int b = bh >> 3, h = bh & 7;
    __shared__ float Ks[32][64];
    __shared__ float Vs[32][64];
    int tid = threadIdx.x;
    int d1b = (tid >> 4) * 4;
    int d2b = (tid & 15) * 4;
    int lr = tid >> 3;
    int lc = (tid & 7) * 8;
    float acc[4][4];
#pragma unroll
    for (int i = 0; i < 4; i++)
#pragma unroll
        for (int j = 0; j < 4; j++) acc[i][j] = 0.f;

    const float* kp = Kb + (size_t)b * SEQ * DIM + h * DPH;
    const float* vp = Vb + (size_t)b * SEQ * DIM + h * DPH;

    for (int s0 = 0; s0 < SEQ; s0 += 32) {
        float4 k0 = *(const float4*)(kp + (size_t)(s0+lr) * DIM + lc);
        float4 k1 = *(const float4*)(kp + (size_t)(s0+lr) * DIM + lc + 4);
        float4 v0 = *(const float4*)(vp + (size_t)(s0+lr) * DIM + lc);
        float4 v1 = *(const float4*)(vp + (size_t)(s0+lr) * DIM + lc + 4);
        __syncthreads();
        *(float4*)&Ks[lr][lc]   = k0; *(float4*)&Ks[lr][lc+4] = k1;
        *(float4*)&Vs[lr][lc]   = v0; *(float4*)&Vs[lr][lc+4] = v1;
        __syncthreads();
#pragma unroll
        for (int ss = 0; ss < 32; ss++) {
            float4 kv = *(const float4*)&Ks[ss][d1b];
            float4 vv = *(const float4*)&Vs[ss][d2b];
            float ka[4] = {kv.x, kv.y, kv.z, kv.w};
            float va[4] = {vv.x, vv.y, vv.z, vv.w};
#pragma unroll
            for (int i = 0; i < 4; i++)
#pragma unroll
                for (int j = 0; j < 4; j++) acc[i][j] += ka[i] * va[j];
        }
    }

    float c2 = 2.f / as_p[0];
    float* Mp = M + (size_t)bh * DPH * DPH;
#pragma unroll
    for (int i = 0; i < 4; i++) {
        float sg = (d1b + i == 0) ? -c2 : c2;
#pragma unroll
        for (int j = 0; j < 4; j++)
            Mp[(d1b + i) * DPH + d2b + j] = acc[i][j] * sg;
    }
}

// ---------------------------------------------------------------------------
__global__ __launch_bounds__(256) void ave_kernel(
    const float* __restrict__ Qb, const float* __restrict__ M,
    const float* __restrict__ CS, float* __restrict__ Out)
{
    int bh = blockIdx.x;
    int b = bh >> 3, h = bh & 7;
    int s0 = blockIdx.y * 32;
    int tid = threadIdx.x;
    int warp = tid >> 5, lane = tid & 31;

    __shared__ float Ms[64][64];
    {
        const float* Mp = M + (size_t)bh * DPH * DPH;
        float* Msf = &Ms[0][0];
        for (int i = tid * 4; i < 4096; i += 1024)
            *(float4*)&Msf[i] = *(const float4*)&Mp[i];
    }
    __syncthreads();

    float cs0 = CS[bh * DPH + lane];
    float cs1 = CS[bh * DPH + lane + 32];
    const float* qp = Qb + (size_t)b * SEQ * DIM + h * DPH;

    for (int r = warp; r < 32; r += 8) {
        int srow = s0 + r;
        const float* q = qp + (size_t)srow * DIM;
        float a0 = cs0, a1 = cs1;
#pragma unroll
        for (int dp = 0; dp < 64; dp++) {
            float qv = __ldg(&q[dp]);
            a0 += qv * Ms[dp][lane];
            a1 += qv * Ms[dp][lane + 32];
        }
        float contrib = a0 * a0 * ((lane == 0) ? -1.f : 1.f) + a1 * a1;
#pragma unroll
        for (int o = 16; o > 0; o >>= 1) contrib += __shfl_xor_sync(0xffffffffu, contrib, o);
        float inv = 1.f / sqrtf(fmaxf(fabsf(contrib), 1e-8f));
        size_t ob = ((size_t)b * SEQ + srow) * DIM + h * DPH;
        Out[ob + lane]      = a0 * inv;
        Out[ob + lane + 32] = a1 * inv;
    }
}

// ===========================================================================
extern "C" void kernel_launch(void* const* d_in, const int* in_sizes, int n_in,
                              void* d_out, int out_size)
{
    const float* key   = (const float*)d_in[0];
    const float* value = (const float*)d_in[1];
    const float* query = (const float*)d_in[2];
    const float* Wq  = (const float*)d_in[3];
    const float* bq  = (const float*)d_in[4];
    const float* lsq = (const float*)d_in[5];
    const float* Wk  = (const float*)d_in[6];
    const float* bk  = (const float*)d_in[7];
    const float* lsk = (const float*)d_in[8];
    const float* Wv  = (const float*)d_in[9];
    const float* bv  = (const float*)d_in[10];
    const float* lsv = (const float*)d_in[11];
    const float* as_p = (const float*)d_in[12];
    const float* ab_p = (const float*)d_in[13];
    float* out = (float*)d_out;

    float *gqkv, *gM, *gcs;
    __half *gxh, *gwh;
    cudaGetSymbolAddress((void**)&gqkv, g_qkv);
    cudaGetSymbolAddress((void**)&gxh,  g_xh);
    cudaGetSymbolAddress((void**)&gwh,  g_wh);
    cudaGetSymbolAddress((void**)&gM,   g_M);
    cudaGetSymbolAddress((void**)&gcs,  g_cs);

    float* gq = gqkv;
    float* gk = gqkv + (size_t)NROWS * DIM;
    float* gv = gqkv + (size_t)2 * NROWS * DIM;

    const int XN4 = NROWS * DIM / 4;
    const int WN4 = DIM * DIM / 4;

    // 5 launches before GEMM so ncu (-s 5 -c 1) captures the GEMM
    convert_w_kernel<<<WN4/256, 256>>>(Wq, gwh,             WN4);
    convert_w_kernel<<<WN4/256, 256>>>(Wk, gwh + DIM*DIM,   WN4);
    convert_w_kernel<<<WN4/256, 256>>>(Wv, gwh + 2*DIM*DIM, WN4);
    {
        dim3 g1(XN4/256, 1);
        convert_x_kernel<<<g1, 256>>>(query, gxh, query, gxh, XN4);
        dim3 g2(XN4/256, 2);
        convert_x_kernel<<<g2, 256>>>(key,   gxh +   NROWS*DIM,
                                      value, gxh + 2*NROWS*DIM, XN4);
    }

    cudaFuncSetAttribute(gemm_mma_kernel,
                         cudaFuncAttributeMaxDynamicSharedMemorySize, GEMM_SMEM);
    dim3 ggrid(DIM / 128, NROWS / 256, 3);
    gemm_mma_kernel<<<ggrid, 512, GEMM_SMEM>>>(
        gxh, gwh, bq, bk, bv, gqkv);

    dim3 lgrid(NROWS / 8, 3);
    lorentz_kernel<<<lgrid, 256>>>(gqkv, lsq, lsk, lsv);

    colsum_kernel<<<BATCH * NHEAD, 64>>>(gv, gcs, as_p, ab_p);
    kkv_kernel<<<BATCH * NHEAD, 256>>>(gk, gv, gM, as_p);

    dim3 agrid(BATCH * NHEAD, SEQ / 32);
    ave_kernel<<<agrid, 256>>>(gq, gM, gcs, out);
}

// round 13
// speedup vs baseline: 1.7748x; 1.0242x over previous
#include <cuda_runtime.h>
#include <cuda_fp16.h>
#include <cstdint>
#include <math.h>

#define BATCH 16
#define SEQ   1024
#define DIM   512
#define NHEAD 8
#define DPH   64
#define NROWS (BATCH*SEQ)   // 16384

// ---------------------------------------------------------------------------
// Scratch (device globals: no allocation allowed anywhere)
// ---------------------------------------------------------------------------
__device__ float g_qkv[3*NROWS*DIM];                 // GEMM outputs (q,k,v)
__device__ __half g_xh[3*NROWS*DIM];                 // fp16(x), K-blocked+swizzled
__device__ __half g_wh[3*DIM*DIM];                   // fp16(W), K-blocked+swizzled
__device__ float g_M[BATCH*NHEAD*DPH*DPH];
__device__ float g_cs[BATCH*NHEAD*DPH];

// ---------------------------------------------------------------------------
// PTX helpers (base sm_80/sm_90 features only — no arch-specific 'a' insts)
// ---------------------------------------------------------------------------
__device__ __forceinline__ uint32_t smem_u32(const void* p) {
    uint32_t a;
    asm("{ .reg .u64 t; cvta.to.shared.u64 t, %1; cvt.u32.u64 %0, t; }"
        : "=r"(a) : "l"(p));
    return a;
}
__device__ __forceinline__ void mbar_init(uint32_t addr, uint32_t cnt) {
    asm volatile("mbarrier.init.shared.b64 [%0], %1;" :: "r"(addr), "r"(cnt) : "memory");
}
__device__ __forceinline__ void mbar_expect_tx(uint32_t addr, uint32_t bytes) {
    asm volatile("mbarrier.arrive.expect_tx.shared.b64 _, [%0], %1;"
                 :: "r"(addr), "r"(bytes) : "memory");
}
__device__ __forceinline__ void mbar_wait(uint32_t addr, uint32_t parity) {
    asm volatile(
        "{\n\t.reg .pred P;\n\t"
        "WL_%=:\n\t"
        "mbarrier.try_wait.parity.acquire.cta.shared::cta.b64 P, [%0], %1, 0x989680;\n\t"
        "@P bra.uni WD_%=;\n\t"
        "bra.uni WL_%=;\n\t"
        "WD_%=:\n\t}"
        :: "r"(addr), "r"(parity) : "memory");
}
__device__ __forceinline__ void bulk_g2s(uint32_t dst, const void* src,
                                         uint32_t bytes, uint32_t mbar) {
    asm volatile(
        "cp.async.bulk.shared::cta.global.mbarrier::complete_tx::bytes "
        "[%0], [%1], %2, [%3];"
        :: "r"(dst), "l"(src), "r"(bytes), "r"(mbar) : "memory");
}
__device__ __forceinline__ void ldsm4(uint32_t* r, uint32_t addr) {
    asm volatile("ldmatrix.sync.aligned.m8n8.x4.shared.b16 {%0,%1,%2,%3}, [%4];"
                 : "=r"(r[0]), "=r"(r[1]), "=r"(r[2]), "=r"(r[3]) : "r"(addr));
}
__device__ __forceinline__ void mma16816(float* c, const uint32_t* a,
                                         uint32_t b0, uint32_t b1) {
    asm volatile(
        "mma.sync.aligned.m16n8k16.row.col.f32.f16.f16.f32 "
        "{%0,%1,%2,%3}, {%4,%5,%6,%7}, {%8,%9}, {%0,%1,%2,%3};"
        : "+f"(c[0]), "+f"(c[1]), "+f"(c[2]), "+f"(c[3])
        : "r"(a[0]), "r"(a[1]), "r"(a[2]), "r"(a[3]), "r"(b0), "r"(b1));
}

// ---------------------------------------------------------------------------
// Converter: fp32 row-major -> fp16 K-blocked + swizzled.
// Logical element (r, k): kc=k>>5, c16=(k&31)>>3, w=k&7.
// Stored half offset = (kc*rows + r)*32 + (c16 ^ ((r>>1)&3))*8 + w.
// One thread handles one 16-B chunk (8 halves).
// ---------------------------------------------------------------------------
__global__ __launch_bounds__(256) void convert_blk_kernel(
    const float* __restrict__ s0, __half* __restrict__ d0,
    const float* __restrict__ s1, __half* __restrict__ d1,
    int nchunks, int rows)
{
    int i = blockIdx.x * 256 + threadIdx.x;
    if (i >= nchunks) return;
    const float* s = (blockIdx.y == 0) ? s0 : s1;
    __half*      d = (blockIdx.y == 0) ? d0 : d1;
    int r = i >> 6, c = i & 63;              // c: 16B chunk within 512-col row
    const float4* p = reinterpret_cast<const float4*>(s + (size_t)r * DIM + c * 8);
    float4 x0 = p[0], x1 = p[1];
    __half2 h0 = __float22half2_rn(make_float2(x0.x, x0.y));
    __half2 h1 = __float22half2_rn(make_float2(x0.z, x0.w));
    __half2 h2 = __float22half2_rn(make_float2(x1.x, x1.y));
    __half2 h3 = __float22half2_rn(make_float2(x1.z, x1.w));
    uint4 o;
    o.x = *reinterpret_cast<uint32_t*>(&h0);
    o.y = *reinterpret_cast<uint32_t*>(&h1);
    o.z = *reinterpret_cast<uint32_t*>(&h2);
    o.w = *reinterpret_cast<uint32_t*>(&h3);
    int kc = c >> 2, c16 = c & 3;
    int sw = c16 ^ ((r >> 1) & 3);
    reinterpret_cast<uint4*>(d)[(size_t)(kc * rows + r) * 4 + sw] = o;
}

// ---------------------------------------------------------------------------
// HMMA fp16 GEMM with cp.async.bulk loads.
// 256x128 CTA tile, BK=32, 3-stage mbarrier pipeline, 16 warps (4x4),
// warp tile 64x32. Per stage: ONE 16KB A bulk + ONE 8KB B bulk.
// ---------------------------------------------------------------------------
#define BK 32
#define ATILE 16384                   // 256 rows * 64 B
#define BTILE 8192                    // 128 rows * 64 B
#define STGB (ATILE + BTILE)          // 24576
#define MBAR_OFF (3*STGB)             // 73728
#define GEMM_SMEM (MBAR_OFF + 64)
#define NSTAGE 16                     // K=512 / BK

__global__ __launch_bounds__(512, 1) void gemm_mma_kernel(
    const __half* __restrict__ Xh, const __half* __restrict__ Wh,
    const float* __restrict__ bq, const float* __restrict__ bk,
    const float* __restrict__ bv, float* __restrict__ Yall)
{
    extern __shared__ char smem[];
    const int z = blockIdx.z;
    const float* bias = (z == 0) ? bq : (z == 1) ? bk : bv;
    float* Y = Yall + (size_t)z * NROWS * DIM;

    const int bm = blockIdx.y * 256;
    const int bn = blockIdx.x * 128;
    const int tid = threadIdx.x;
    const int wid = tid >> 5, lane = tid & 31;
    const int wm = wid >> 2, wn = wid & 3;      // 4x4 warp grid, 64x32 tiles

    uint32_t sb = smem_u32(smem);
    uint32_t mb = sb + MBAR_OFF;

    if (tid == 0) {
        mbar_init(mb + 0, 1);
        mbar_init(mb + 8, 1);
        mbar_init(mb + 16, 1);
    }
    __syncthreads();

    // Blocked sources: A chunk for kc = Abase + kc*NROWS*32 halves (16 KB).
    const __half* Abase = Xh + (size_t)z * NROWS * DIM + (size_t)bm * 32;
    const __half* Bbase = Wh + (size_t)z * DIM * DIM   + (size_t)bn * 32;

#define ISSUE(stage, kc)                                                      \
    if (tid == 0) {                                                           \
        uint32_t m = mb + (stage) * 8;                                        \
        mbar_expect_tx(m, STGB);                                              \
        bulk_g2s(sb + (stage) * STGB, Abase + (size_t)(kc) * NROWS * 32,      \
                 ATILE, m);                                                   \
        bulk_g2s(sb + (stage) * STGB + ATILE, Bbase + (size_t)(kc) * DIM * 32,\
                 BTILE, m);                                                   \
    }

    ISSUE(0, 0)
    ISSUE(1, 1)

    float acc[4][4][4];
#pragma unroll
    for (int i = 0; i < 4; i++)
#pragma unroll
        for (int j = 0; j < 4; j++)
#pragma unroll
            for (int r = 0; r < 4; r++) acc[i][j][r] = 0.f;

    const int lrow = lane & 15;
    const int lh = lane >> 4;                  // which 16B chunk of the k-half

    for (int s = 0; s < NSTAGE; s++) {
        mbar_wait(mb + (s % 3) * 8, (s / 3) & 1);
        uint32_t st = sb + (s % 3) * STGB;

#pragma unroll
        for (int ks = 0; ks < 2; ks++) {
            const int c16 = ks * 2 + lh;
            uint32_t af[4][4], bf[2][4];
#pragma unroll
            for (int mt = 0; mt < 4; mt++) {
                int row = wm*64 + mt*16 + lrow;
                uint32_t addr = st + row * 64 + ((c16 ^ ((row >> 1) & 3)) << 4);
                ldsm4(af[mt], addr);
            }
#pragma unroll
            for (int bt = 0; bt < 2; bt++) {
                int row = wn*32 + bt*16 + lrow;
                uint32_t addr = st + ATILE + row * 64
                              + ((c16 ^ ((row >> 1) & 3)) << 4);
                ldsm4(bf[bt], addr);
            }
#pragma unroll
            for (int mt = 0; mt < 4; mt++)
#pragma unroll
                for (int nt = 0; nt < 4; nt++) {
                    int g = nt >> 1, o = nt & 1;
                    mma16816(acc[mt][nt], af[mt], bf[g][o], bf[g][o+2]);
                }
        }
        __syncthreads();
        if (s + 2 < NSTAGE) ISSUE((s + 2) % 3, s + 2)
    }
#undef ISSUE

    // Epilogue: bias add + store
#pragma unroll
    for (int nt = 0; nt < 4; nt++) {
        int col = bn + wn*32 + nt*8 + (lane & 3)*2;
        float2 b2 = make_float2(bias[col], bias[col+1]);
#pragma unroll
        for (int mt = 0; mt < 4; mt++) {
            int row = bm + wm*64 + mt*16 + (lane >> 2);
            float* y0 = Y + (size_t)row * DIM + col;
            *reinterpret_cast<float2*>(y0) =
                make_float2(acc[mt][nt][0] + b2.x, acc[mt][nt][1] + b2.y);
            *reinterpret_cast<float2*>(y0 + 8 * DIM) =
                make_float2(acc[mt][nt][2] + b2.x, acc[mt][nt][3] + b2.y);
        }
    }
}

// ---------------------------------------------------------------------------
// Lorentz transform: warp-per-row, 3 tensors fused via grid.y
// ---------------------------------------------------------------------------
__global__ __launch_bounds__(256) void lorentz_kernel(
    float* __restrict__ Yall,
    const float* __restrict__ lsq, const float* __restrict__ lsk,
    const float* __restrict__ lsv)
{
    const int z = blockIdx.y;
    float* Y = Yall + (size_t)z * NROWS * DIM;
    const float* ls = (z == 0) ? lsq : (z == 1) ? lsk : lsv;

    int row  = blockIdx.x * 8 + (threadIdx.x >> 5);
    int lane = threadIdx.x & 31;
    float* y = Y + (size_t)row * DIM + lane * 4;

    float4 v[4];
#pragma unroll
    for (int c = 0; c < 4; c++) v[c] = *reinterpret_cast<float4*>(y + c * 128);

    float ss = 0.f;
#pragma unroll
    for (int c = 0; c < 4; c++)
        ss += v[c].x*v[c].x + v[c].y*v[c].y + v[c].z*v[c].z + v[c].w*v[c].w;
    if (lane == 0) ss -= v[0].x * v[0].x;
#pragma unroll
    for (int o = 16; o > 0; o >>= 1) ss += __shfl_xor_sync(0xffffffffu, ss, o);

    float x0 = __shfl_sync(0xffffffffu, v[0].x, 0);
    float time = expf(ls[0]) / (1.f + expf(-x0)) + 1.0001f;
    float scale = sqrtf((time * time - 1.f) / fmaxf(ss, 1e-8f));
#pragma unroll
    for (int c = 0; c < 4; c++) {
        v[c].x *= scale; v[c].y *= scale; v[c].z *= scale; v[c].w *= scale;
    }
    if (lane == 0) v[0].x = time;
#pragma unroll
    for (int c = 0; c < 4; c++) *reinterpret_cast<float4*>(y + c * 128) = v[c];
}

// ---------------------------------------------------------------------------
__global__ __launch_bounds__(64) void colsum_kernel(
    const float* __restrict__ Vb, float* __restrict__ CS,
    const float* __restrict__ as_p, const float* __restrict__ ab_p)
{
    int bh = blockIdx.x;
    int b = bh >> 3, h = bh & 7;
    int d = threadIdx.x;
    const float* vp = Vb + (size_t)b * SEQ * DIM + h * DPH + d;
    float a0 = 0.f, a1 = 0.f, a2 = 0.f, a3 = 0.f;
#pragma unroll 4
    for (int s = 0; s < SEQ; s += 4) {
        a0 += vp[(size_t)(s+0) * DIM];
        a1 += vp[(size_t)(s+1) * DIM];
        a2 += vp[(size_t)(s+2) * DIM];
        a3 += vp[(size_t)(s+3) * DIM];
    }
    float c1 = 2.f / as_p[0] + ab_p[0];
    CS[bh * DPH + d] = (a0 + a1 + a2 + a3) * c1;
}

// ---------------------------------------------------------------------------
__global__ __launch_bounds__(256) void kkv_kernel(
    const float* __restrict__ Kb, const float* __restrict__ Vb,
    float* __restrict__ M, const float* __restrict__ as_p)
{
    int bh = blockIdx.x;
    int b = bh >> 3, h = bh & 7;
    __shared__ float Ks[32][64];
    __shared__ float Vs[32][64];
    int tid = threadIdx.x;
    int d1b = (tid >> 4) * 4;
    int d2b = (tid & 15) * 4;
    int lr = tid >> 3;
    int lc = (tid & 7) * 8;
    float acc[4][4];
#pragma unroll
    for (int i = 0; i < 4; i++)
#pragma unroll
        for (int j = 0; j < 4; j++) acc[i][j] = 0.f;

    const float* kp = Kb + (size_t)b * SEQ * DIM + h * DPH;
    const float* vp = Vb + (size_t)b * SEQ * DIM + h * DPH;

    for (int s0 = 0; s0 < SEQ; s0 += 32) {
        float4 k0 = *(const float4*)(kp + (size_t)(s0+lr) * DIM + lc);
        float4 k1 = *(const float4*)(kp + (size_t)(s0+lr) * DIM + lc + 4);
        float4 v0 = *(const float4*)(vp + (size_t)(s0+lr) * DIM + lc);
        float4 v1 = *(const float4*)(vp + (size_t)(s0+lr) * DIM + lc + 4);
        __syncthreads();
        *(float4*)&Ks[lr][lc]   = k0; *(float4*)&Ks[lr][lc+4] = k1;
        *(float4*)&Vs[lr][lc]   = v0; *(float4*)&Vs[lr][lc+4] = v1;
        __syncthreads();
#pragma unroll
        for (int ss = 0; ss < 32; ss++) {
            float4 kv = *(const float4*)&Ks[ss][d1b];
            float4 vv = *(const float4*)&Vs[ss][d2b];
            float ka[4] = {kv.x, kv.y, kv.z, kv.w};
            float va[4] = {vv.x, vv.y, vv.z, vv.w};
#pragma unroll
            for (int i = 0; i < 4; i++)
#pragma unroll
                for (int j = 0; j < 4; j++) acc[i][j] += ka[i] * va[j];
        }
    }

    float c2 = 2.f / as_p[0];
    float* Mp = M + (size_t)bh * DPH * DPH;
#pragma unroll
    for (int i = 0; i < 4; i++) {
        float sg = (d1b + i == 0) ? -c2 : c2;
#pragma unroll
        for (int j = 0; j < 4; j++)
            Mp[(d1b + i) * DPH + d2b + j] = acc[i][j] * sg;
    }
}

// ---------------------------------------------------------------------------
__global__ __launch_bounds__(256) void ave_kernel(
    const float* __restrict__ Qb, const float* __restrict__ M,
    const float* __restrict__ CS, float* __restrict__ Out)
{
    int bh = blockIdx.x;
    int b = bh >> 3, h = bh & 7;
    int s0 = blockIdx.y * 32;
    int tid = threadIdx.x;
    int warp = tid >> 5, lane = tid & 31;

    __shared__ float Ms[64][64];
    {
        const float* Mp = M + (size_t)bh * DPH * DPH;
        float* Msf = &Ms[0][0];
        for (int i = tid * 4; i < 4096; i += 1024)
            *(float4*)&Msf[i] = *(const float4*)&Mp[i];
    }
    __syncthreads();

    float cs0 = CS[bh * DPH + lane];
    float cs1 = CS[bh * DPH + lane + 32];
    const float* qp = Qb + (size_t)b * SEQ * DIM + h * DPH;

    for (int r = warp; r < 32; r += 8) {
        int srow = s0 + r;
        const float* q = qp + (size_t)srow * DIM;
        float a0 = cs0, a1 = cs1;
#pragma unroll
        for (int dp = 0; dp < 64; dp++) {
            float qv = __ldg(&q[dp]);
            a0 += qv * Ms[dp][lane];
            a1 += qv * Ms[dp][lane + 32];
        }
        float contrib = a0 * a0 * ((lane == 0) ? -1.f : 1.f) + a1 * a1;
#pragma unroll
        for (int o = 16; o > 0; o >>= 1) contrib += __shfl_xor_sync(0xffffffffu, contrib, o);
        float inv = 1.f / sqrtf(fmaxf(fabsf(contrib), 1e-8f));
        size_t ob = ((size_t)b * SEQ + srow) * DIM + h * DPH;
        Out[ob + lane]      = a0 * inv;
        Out[ob + lane + 32] = a1 * inv;
    }
}

// ===========================================================================
extern "C" void kernel_launch(void* const* d_in, const int* in_sizes, int n_in,
                              void* d_out, int out_size)
{
    const float* key   = (const float*)d_in[0];
    const float* value = (const float*)d_in[1];
    const float* query = (const float*)d_in[2];
    const float* Wq  = (const float*)d_in[3];
    const float* bq  = (const float*)d_in[4];
    const float* lsq = (const float*)d_in[5];
    const float* Wk  = (const float*)d_in[6];
    const float* bk  = (const float*)d_in[7];
    const float* lsk = (const float*)d_in[8];
    const float* Wv  = (const float*)d_in[9];
    const float* bv  = (const float*)d_in[10];
    const float* lsv = (const float*)d_in[11];
    const float* as_p = (const float*)d_in[12];
    const float* ab_p = (const float*)d_in[13];
    float* out = (float*)d_out;

    float *gqkv, *gM, *gcs;
    __half *gxh, *gwh;
    cudaGetSymbolAddress((void**)&gqkv, g_qkv);
    cudaGetSymbolAddress((void**)&gxh,  g_xh);
    cudaGetSymbolAddress((void**)&gwh,  g_wh);
    cudaGetSymbolAddress((void**)&gM,   g_M);
    cudaGetSymbolAddress((void**)&gcs,  g_cs);

    float* gq = gqkv;
    float* gk = gqkv + (size_t)NROWS * DIM;
    float* gv = gqkv + (size_t)2 * NROWS * DIM;

    const int XCH = NROWS * 64;   // 16B chunks per X tensor
    const int WCH = DIM * 64;     // 16B chunks per W tensor

    // 5 launches before GEMM so ncu (-s 5 -c 1) captures the GEMM
    convert_blk_kernel<<<WCH/256, 256>>>(Wq, gwh,             Wq, gwh,
                                         WCH, DIM);
    convert_blk_kernel<<<WCH/256, 256>>>(Wk, gwh + DIM*DIM,   Wk, gwh + DIM*DIM,
                                         WCH, DIM);
    convert_blk_kernel<<<WCH/256, 256>>>(Wv, gwh + 2*DIM*DIM, Wv, gwh + 2*DIM*DIM,
                                         WCH, DIM);
    {
        dim3 g1(XCH/256, 1);
        convert_blk_kernel<<<g1, 256>>>(query, gxh, query, gxh, XCH, NROWS);
        dim3 g2(XCH/256, 2);
        convert_blk_kernel<<<g2, 256>>>(key,   gxh +   NROWS*DIM,
                                        value, gxh + 2*NROWS*DIM, XCH, NROWS);
    }

    cudaFuncSetAttribute(gemm_mma_kernel,
                         cudaFuncAttributeMaxDynamicSharedMemorySize, GEMM_SMEM);
    dim3 ggrid(DIM / 128, NROWS / 256, 3);
    gemm_mma_kernel<<<ggrid, 512, GEMM_SMEM>>>(
        gxh, gwh, bq, bk, bv, gqkv);

    dim3 lgrid(NROWS / 8, 3);
    lorentz_kernel<<<lgrid, 256>>>(gqkv, lsq, lsk, lsv);

    colsum_kernel<<<BATCH * NHEAD, 64>>>(gv, gcs, as_p, ab_p);
    kkv_kernel<<<BATCH * NHEAD, 256>>>(gk, gv, gM, as_p);

    dim3 agrid(BATCH * NHEAD, SEQ / 32);
    ave_kernel<<<agrid, 256>>>(gq, gM, gcs, out);
}

// round 14
// speedup vs baseline: 1.9967x; 1.1251x over previous
#include <cuda_runtime.h>
#include <cuda_fp16.h>
#include <cstdint>
#include <math.h>

#define BATCH 16
#define SEQ   1024
#define DIM   512
#define NHEAD 8
#define DPH   64
#define NROWS (BATCH*SEQ)   // 16384

// ---------------------------------------------------------------------------
// Scratch (device globals: no allocation allowed anywhere)
// ---------------------------------------------------------------------------
__device__ float g_qkv[3*NROWS*DIM];                 // GEMM outputs (q,k,v)
__device__ __half g_xh[3*NROWS*DIM];                 // fp16(x), K-blocked+swizzled
__device__ __half g_wh[3*DIM*DIM];                   // fp16(W), K-blocked+swizzled
__device__ float g_M[BATCH*NHEAD*DPH*DPH];
__device__ float g_cs[BATCH*NHEAD*DPH];

// ---------------------------------------------------------------------------
// PTX helpers (base sm_80/sm_90 features only — no arch-specific 'a' insts)
// ---------------------------------------------------------------------------
__device__ __forceinline__ uint32_t smem_u32(const void* p) {
    uint32_t a;
    asm("{ .reg .u64 t; cvta.to.shared.u64 t, %1; cvt.u32.u64 %0, t; }"
        : "=r"(a) : "l"(p));
    return a;
}
__device__ __forceinline__ void mbar_init(uint32_t addr, uint32_t cnt) {
    asm volatile("mbarrier.init.shared.b64 [%0], %1;" :: "r"(addr), "r"(cnt) : "memory");
}
__device__ __forceinline__ void mbar_expect_tx(uint32_t addr, uint32_t bytes) {
    asm volatile("mbarrier.arrive.expect_tx.shared.b64 _, [%0], %1;"
                 :: "r"(addr), "r"(bytes) : "memory");
}
__device__ __forceinline__ void mbar_wait(uint32_t addr, uint32_t parity) {
    asm volatile(
        "{\n\t.reg .pred P;\n\t"
        "WL_%=:\n\t"
        "mbarrier.try_wait.parity.acquire.cta.shared::cta.b64 P, [%0], %1, 0x989680;\n\t"
        "@P bra.uni WD_%=;\n\t"
        "bra.uni WL_%=;\n\t"
        "WD_%=:\n\t}"
        :: "r"(addr), "r"(parity) : "memory");
}
__device__ __forceinline__ void bulk_g2s(uint32_t dst, const void* src,
                                         uint32_t bytes, uint32_t mbar) {
    asm volatile(
        "cp.async.bulk.shared::cta.global.mbarrier::complete_tx::bytes "
        "[%0], [%1], %2, [%3];"
        :: "r"(dst), "l"(src), "r"(bytes), "r"(mbar) : "memory");
}
__device__ __forceinline__ void ldsm4(uint32_t* r, uint32_t addr) {
    asm volatile("ldmatrix.sync.aligned.m8n8.x4.shared.b16 {%0,%1,%2,%3}, [%4];"
                 : "=r"(r[0]), "=r"(r[1]), "=r"(r[2]), "=r"(r[3]) : "r"(addr));
}
__device__ __forceinline__ void mma16816(float* c, const uint32_t* a,
                                         uint32_t b0, uint32_t b1) {
    asm volatile(
        "mma.sync.aligned.m16n8k16.row.col.f32.f16.f16.f32 "
        "{%0,%1,%2,%3}, {%4,%5,%6,%7}, {%8,%9}, {%0,%1,%2,%3};"
        : "+f"(c[0]), "+f"(c[1]), "+f"(c[2]), "+f"(c[3])
        : "r"(a[0]), "r"(a[1]), "r"(a[2]), "r"(a[3]), "r"(b0), "r"(b1));
}

// ---------------------------------------------------------------------------
// Converter: fp32 row-major -> fp16 K-blocked + swizzled (3 sources, grid.y).
// Stored half offset = (kc*rows + r)*32 + (c16 ^ ((r>>1)&3))*8 + w.
// ---------------------------------------------------------------------------
__global__ __launch_bounds__(256) void convert_blk_kernel(
    const float* __restrict__ s0, __half* __restrict__ d0,
    const float* __restrict__ s1, __half* __restrict__ d1,
    const float* __restrict__ s2, __half* __restrict__ d2,
    int nchunks, int rows)
{
    int i = blockIdx.x * 256 + threadIdx.x;
    if (i >= nchunks) return;
    const float* s = (blockIdx.y == 0) ? s0 : (blockIdx.y == 1) ? s1 : s2;
    __half*      d = (blockIdx.y == 0) ? d0 : (blockIdx.y == 1) ? d1 : d2;
    int r = i >> 6, c = i & 63;              // c: 16B chunk within 512-col row
    const float4* p = reinterpret_cast<const float4*>(s + (size_t)r * DIM + c * 8);
    float4 x0 = p[0], x1 = p[1];
    __half2 h0 = __float22half2_rn(make_float2(x0.x, x0.y));
    __half2 h1 = __float22half2_rn(make_float2(x0.z, x0.w));
    __half2 h2 = __float22half2_rn(make_float2(x1.x, x1.y));
    __half2 h3 = __float22half2_rn(make_float2(x1.z, x1.w));
    uint4 o;
    o.x = *reinterpret_cast<uint32_t*>(&h0);
    o.y = *reinterpret_cast<uint32_t*>(&h1);
    o.z = *reinterpret_cast<uint32_t*>(&h2);
    o.w = *reinterpret_cast<uint32_t*>(&h3);
    int kc = c >> 2, c16 = c & 3;
    int sw = c16 ^ ((r >> 1) & 3);
    reinterpret_cast<uint4*>(d)[(size_t)(kc * rows + r) * 4 + sw] = o;
}

// ---------------------------------------------------------------------------
// HMMA fp16 GEMM with cp.async.bulk loads.
// 256x128 CTA tile, BK=32, 4-stage mbarrier pipeline, 16 warps (4x4),
// warp tile 64x32. Per stage: ONE 16KB A bulk + ONE 8KB B bulk.
// ---------------------------------------------------------------------------
#define BK 32
#define ATILE 16384                   // 256 rows * 64 B
#define BTILE 8192                    // 128 rows * 64 B
#define STGB (ATILE + BTILE)          // 24576
#define NPIPE 4
#define MBAR_OFF (NPIPE*STGB)         // 98304
#define GEMM_SMEM (MBAR_OFF + 64)
#define NSTAGE 16                     // K=512 / BK

__global__ __launch_bounds__(512, 1) void gemm_mma_kernel(
    const __half* __restrict__ Xh, const __half* __restrict__ Wh,
    const float* __restrict__ bq, const float* __restrict__ bk,
    const float* __restrict__ bv, float* __restrict__ Yall)
{
    extern __shared__ char smem[];
    const int z = blockIdx.z;
    const float* bias = (z == 0) ? bq : (z == 1) ? bk : bv;
    float* Y = Yall + (size_t)z * NROWS * DIM;

    const int bm = blockIdx.y * 256;
    const int bn = blockIdx.x * 128;
    const int tid = threadIdx.x;
    const int wid = tid >> 5, lane = tid & 31;
    const int wm = wid >> 2, wn = wid & 3;      // 4x4 warp grid, 64x32 tiles

    uint32_t sb = smem_u32(smem);
    uint32_t mb = sb + MBAR_OFF;

    if (tid == 0) {
#pragma unroll
        for (int p = 0; p < NPIPE; p++) mbar_init(mb + p * 8, 1);
    }
    __syncthreads();

    const __half* Abase = Xh + (size_t)z * NROWS * DIM + (size_t)bm * 32;
    const __half* Bbase = Wh + (size_t)z * DIM * DIM   + (size_t)bn * 32;

#define ISSUE(stage, kc)                                                      \
    if (tid == 0) {                                                           \
        uint32_t m = mb + (stage) * 8;                                        \
        mbar_expect_tx(m, STGB);                                              \
        bulk_g2s(sb + (stage) * STGB, Abase + (size_t)(kc) * NROWS * 32,      \
                 ATILE, m);                                                   \
        bulk_g2s(sb + (stage) * STGB + ATILE, Bbase + (size_t)(kc) * DIM * 32,\
                 BTILE, m);                                                   \
    }

    ISSUE(0, 0)
    ISSUE(1, 1)
    ISSUE(2, 2)

    float acc[4][4][4];
#pragma unroll
    for (int i = 0; i < 4; i++)
#pragma unroll
        for (int j = 0; j < 4; j++)
#pragma unroll
            for (int r = 0; r < 4; r++) acc[i][j][r] = 0.f;

    const int lrow = lane & 15;
    const int lh = lane >> 4;                  // which 16B chunk of the k-half

    for (int s = 0; s < NSTAGE; s++) {
        mbar_wait(mb + (s % NPIPE) * 8, (s / NPIPE) & 1);
        uint32_t st = sb + (s % NPIPE) * STGB;

#pragma unroll
        for (int ks = 0; ks < 2; ks++) {
            const int c16 = ks * 2 + lh;
            uint32_t af[4][4], bf[2][4];
#pragma unroll
            for (int mt = 0; mt < 4; mt++) {
                int row = wm*64 + mt*16 + lrow;
                uint32_t addr = st + row * 64 + ((c16 ^ ((row >> 1) & 3)) << 4);
                ldsm4(af[mt], addr);
            }
#pragma unroll
            for (int bt = 0; bt < 2; bt++) {
                int row = wn*32 + bt*16 + lrow;
                uint32_t addr = st + ATILE + row * 64
                              + ((c16 ^ ((row >> 1) & 3)) << 4);
                ldsm4(bf[bt], addr);
            }
#pragma unroll
            for (int mt = 0; mt < 4; mt++)
#pragma unroll
                for (int nt = 0; nt < 4; nt++) {
                    int g = nt >> 1, o = nt & 1;
                    mma16816(acc[mt][nt], af[mt], bf[g][o], bf[g][o+2]);
                }
        }
        __syncthreads();
        if (s + 3 < NSTAGE) ISSUE((s + 3) % NPIPE, s + 3)
    }
#undef ISSUE

    // Epilogue: bias add + store
#pragma unroll
    for (int nt = 0; nt < 4; nt++) {
        int col = bn + wn*32 + nt*8 + (lane & 3)*2;
        float2 b2 = make_float2(bias[col], bias[col+1]);
#pragma unroll
        for (int mt = 0; mt < 4; mt++) {
            int row = bm + wm*64 + mt*16 + (lane >> 2);
            float* y0 = Y + (size_t)row * DIM + col;
            *reinterpret_cast<float2*>(y0) =
                make_float2(acc[mt][nt][0] + b2.x, acc[mt][nt][1] + b2.y);
            *reinterpret_cast<float2*>(y0 + 8 * DIM) =
                make_float2(acc[mt][nt][2] + b2.x, acc[mt][nt][3] + b2.y);
        }
    }
}

// ---------------------------------------------------------------------------
// Lorentz transform: warp-per-row, 3 tensors fused via grid.y
// ---------------------------------------------------------------------------
__global__ __launch_bounds__(256) void lorentz_kernel(
    float* __restrict__ Yall,
    const float* __restrict__ lsq, const float* __restrict__ lsk,
    const float* __restrict__ lsv)
{
    const int z = blockIdx.y;
    float* Y = Yall + (size_t)z * NROWS * DIM;
    const float* ls = (z == 0) ? lsq : (z == 1) ? lsk : lsv;

    int row  = blockIdx.x * 8 + (threadIdx.x >> 5);
    int lane = threadIdx.x & 31;
    float* y = Y + (size_t)row * DIM + lane * 4;

    float4 v[4];
#pragma unroll
    for (int c = 0; c < 4; c++) v[c] = *reinterpret_cast<float4*>(y + c * 128);

    float ss = 0.f;
#pragma unroll
    for (int c = 0; c < 4; c++)
        ss += v[c].x*v[c].x + v[c].y*v[c].y + v[c].z*v[c].z + v[c].w*v[c].w;
    if (lane == 0) ss -= v[0].x * v[0].x;
#pragma unroll
    for (int o = 16; o > 0; o >>= 1) ss += __shfl_xor_sync(0xffffffffu, ss, o);

    float x0 = __shfl_sync(0xffffffffu, v[0].x, 0);
    float time = expf(ls[0]) / (1.f + expf(-x0)) + 1.0001f;
    float scale = sqrtf((time * time - 1.f) / fmaxf(ss, 1e-8f));
#pragma unroll
    for (int c = 0; c < 4; c++) {
        v[c].x *= scale; v[c].y *= scale; v[c].z *= scale; v[c].w *= scale;
    }
    if (lane == 0) v[0].x = time;
#pragma unroll
    for (int c = 0; c < 4; c++) *reinterpret_cast<float4*>(y + c * 128) = v[c];
}

// ---------------------------------------------------------------------------
// kkv with fused colsum:
//   M'[d1,d2] = (2/as)*sgn[d1]*sum_s K[s,d1]*V[s,d2]
//   CS[d]     = (2/as + ab)*sum_s V[s,d]      (threads 0-63 accumulate)
// ---------------------------------------------------------------------------
__global__ __launch_bounds__(256) void kkv_kernel(
    const float* __restrict__ Kb, const float* __restrict__ Vb,
    float* __restrict__ M, float* __restrict__ CS,
    const float* __restrict__ as_p, const float* __restrict__ ab_p)
{
    int bh = blockIdx.x;
    int b = bh >> 3, h = bh & 7;
    __shared__ float Ks[32][64];
    __shared__ float Vs[32][64];
    int tid = threadIdx.x;
    int d1b = (tid >> 4) * 4;
    int d2b = (tid & 15) * 4;
    int lr = tid >> 3;
    int lc = (tid & 7) * 8;
    float acc[4][4];
#pragma unroll
    for (int i = 0; i < 4; i++)
#pragma unroll
        for (int j = 0; j < 4; j++) acc[i][j] = 0.f;
    float csum = 0.f;

    const float* kp = Kb + (size_t)b * SEQ * DIM + h * DPH;
    const float* vp = Vb + (size_t)b * SEQ * DIM + h * DPH;

    for (int s0 = 0; s0 < SEQ; s0 += 32) {
        float4 k0 = *(const float4*)(kp + (size_t)(s0+lr) * DIM + lc);
        float4 k1 = *(const float4*)(kp + (size_t)(s0+lr) * DIM + lc + 4);
        float4 v0 = *(const float4*)(vp + (size_t)(s0+lr) * DIM + lc);
        float4 v1 = *(const float4*)(vp + (size_t)(s0+lr) * DIM + lc + 4);
        __syncthreads();
        *(float4*)&Ks[lr][lc]   = k0; *(float4*)&Ks[lr][lc+4] = k1;
        *(float4*)&Vs[lr][lc]   = v0; *(float4*)&Vs[lr][lc+4] = v1;
        __syncthreads();
#pragma unroll
        for (int ss = 0; ss < 32; ss++) {
            float4 kv = *(const float4*)&Ks[ss][d1b];
            float4 vv = *(const float4*)&Vs[ss][d2b];
            float ka[4] = {kv.x, kv.y, kv.z, kv.w};
            float va[4] = {vv.x, vv.y, vv.z, vv.w};
#pragma unroll
            for (int i = 0; i < 4; i++)
#pragma unroll
                for (int j = 0; j < 4; j++) acc[i][j] += ka[i] * va[j];
        }
        if (tid < 64) {
#pragma unroll
            for (int ss = 0; ss < 32; ss++) csum += Vs[ss][tid];
        }
    }

    float c2 = 2.f / as_p[0];
    float* Mp = M + (size_t)bh * DPH * DPH;
#pragma unroll
    for (int i = 0; i < 4; i++) {
        float sg = (d1b + i == 0) ? -c2 : c2;
#pragma unroll
        for (int j = 0; j < 4; j++)
            Mp[(d1b + i) * DPH + d2b + j] = acc[i][j] * sg;
    }
    if (tid < 64) {
        float c1 = 2.f / as_p[0] + ab_p[0];
        CS[bh * DPH + tid] = csum * c1;
    }
}

// ---------------------------------------------------------------------------
__global__ __launch_bounds__(256) void ave_kernel(
    const float* __restrict__ Qb, const float* __restrict__ M,
    const float* __restrict__ CS, float* __restrict__ Out)
{
    int bh = blockIdx.x;
    int b = bh >> 3, h = bh & 7;
    int s0 = blockIdx.y * 32;
    int tid = threadIdx.x;
    int warp = tid >> 5, lane = tid & 31;

    __shared__ float Ms[64][64];
    {
        const float* Mp = M + (size_t)bh * DPH * DPH;
        float* Msf = &Ms[0][0];
        for (int i = tid * 4; i < 4096; i += 1024)
            *(float4*)&Msf[i] = *(const float4*)&Mp[i];
    }
    __syncthreads();

    float cs0 = CS[bh * DPH + lane];
    float cs1 = CS[bh * DPH + lane + 32];
    const float* qp = Qb + (size_t)b * SEQ * DIM + h * DPH;

    for (int r = warp; r < 32; r += 8) {
        int srow = s0 + r;
        const float* q = qp + (size_t)srow * DIM;
        float a0 = cs0, a1 = cs1;
#pragma unroll
        for (int dp = 0; dp < 64; dp++) {
            float qv = __ldg(&q[dp]);
            a0 += qv * Ms[dp][lane];
            a1 += qv * Ms[dp][lane + 32];
        }
        float contrib = a0 * a0 * ((lane == 0) ? -1.f : 1.f) + a1 * a1;
#pragma unroll
        for (int o = 16; o > 0; o >>= 1) contrib += __shfl_xor_sync(0xffffffffu, contrib, o);
        float inv = 1.f / sqrtf(fmaxf(fabsf(contrib), 1e-8f));
        size_t ob = ((size_t)b * SEQ + srow) * DIM + h * DPH;
        Out[ob + lane]      = a0 * inv;
        Out[ob + lane + 32] = a1 * inv;
    }
}

// ===========================================================================
extern "C" void kernel_launch(void* const* d_in, const int* in_sizes, int n_in,
                              void* d_out, int out_size)
{
    const float* key   = (const float*)d_in[0];
    const float* value = (const float*)d_in[1];
    const float* query = (const float*)d_in[2];
    const float* Wq  = (const float*)d_in[3];
    const float* bq  = (const float*)d_in[4];
    const float* lsq = (const float*)d_in[5];
    const float* Wk  = (const float*)d_in[6];
    const float* bk  = (const float*)d_in[7];
    const float* lsk = (const float*)d_in[8];
    const float* Wv  = (const float*)d_in[9];
    const float* bv  = (const float*)d_in[10];
    const float* lsv = (const float*)d_in[11];
    const float* as_p = (const float*)d_in[12];
    const float* ab_p = (const float*)d_in[13];
    float* out = (float*)d_out;

    float *gqkv, *gM, *gcs;
    __half *gxh, *gwh;
    cudaGetSymbolAddress((void**)&gqkv, g_qkv);
    cudaGetSymbolAddress((void**)&gxh,  g_xh);
    cudaGetSymbolAddress((void**)&gwh,  g_wh);
    cudaGetSymbolAddress((void**)&gM,   g_M);
    cudaGetSymbolAddress((void**)&gcs,  g_cs);

    float* gq = gqkv;
    float* gk = gqkv + (size_t)NROWS * DIM;
    float* gv = gqkv + (size_t)2 * NROWS * DIM;

    const int XCH = NROWS * 64;   // 16B chunks per X tensor
    const int WCH = DIM * 64;     // 16B chunks per W tensor

    // Launch order matters for ncu: GEMM must be the 4th launch.
    {   // #1: all three W converts
        dim3 gw(WCH/256, 3);
        convert_blk_kernel<<<gw, 256>>>(Wq, gwh,
                                        Wk, gwh + DIM*DIM,
                                        Wv, gwh + 2*DIM*DIM, WCH, DIM);
    }
    {   // #2: X query
        dim3 g1(XCH/256, 1);
        convert_blk_kernel<<<g1, 256>>>(query, gxh, query, gxh, query, gxh,
                                        XCH, NROWS);
    }
    {   // #3: X key + value
        dim3 g2(XCH/256, 2);
        convert_blk_kernel<<<g2, 256>>>(key,   gxh +   NROWS*DIM,
                                        value, gxh + 2*NROWS*DIM,
                                        value, gxh + 2*NROWS*DIM, XCH, NROWS);
    }

    // #4: GEMM (profiled)
    cudaFuncSetAttribute(gemm_mma_kernel,
                         cudaFuncAttributeMaxDynamicSharedMemorySize, GEMM_SMEM);
    dim3 ggrid(DIM / 128, NROWS / 256, 3);
    gemm_mma_kernel<<<ggrid, 512, GEMM_SMEM>>>(
        gxh, gwh, bq, bk, bv, gqkv);

    // #5: Lorentz transforms
    dim3 lgrid(NROWS / 8, 3);
    lorentz_kernel<<<lgrid, 256>>>(gqkv, lsq, lsk, lsv);

    // #6: kkv + fused colsum
    kkv_kernel<<<BATCH * NHEAD, 256>>>(gk, gv, gM, gcs, as_p, ab_p);

    // #7: ave
    dim3 agrid(BATCH * NHEAD, SEQ / 32);
    ave_kernel<<<agrid, 256>>>(gq, gM, gcs, out);
}

// round 15
// speedup vs baseline: 2.0734x; 1.0384x over previous
#include <cuda_runtime.h>
#include <cuda_fp16.h>
#include <cstdint>
#include <math.h>

#define BATCH 16
#define SEQ   1024
#define DIM   512
#define NHEAD 8
#define DPH   64
#define NROWS (BATCH*SEQ)   // 16384

// ---------------------------------------------------------------------------
// Scratch (device globals: no allocation allowed anywhere)
// ---------------------------------------------------------------------------
__device__ float g_qkv[3*NROWS*DIM];                 // GEMM outputs (q,k,v)
__device__ __half g_xh[3*NROWS*DIM];                 // fp16(x), K-blocked+swizzled
__device__ __half g_wh[3*DIM*DIM];                   // fp16(W), K-blocked+swizzled
__device__ float g_sspart[16*3*NROWS];               // per-(ntile,warp) row sumsq
__device__ float g_scale[3*NROWS];                   // per-row lorentz scale
__device__ float g_M[BATCH*NHEAD*DPH*DPH];
__device__ float g_cs[BATCH*NHEAD*DPH];

// ---------------------------------------------------------------------------
// PTX helpers (base sm_80/sm_90 features only — no arch-specific 'a' insts)
// ---------------------------------------------------------------------------
__device__ __forceinline__ uint32_t smem_u32(const void* p) {
    uint32_t a;
    asm("{ .reg .u64 t; cvta.to.shared.u64 t, %1; cvt.u32.u64 %0, t; }"
        : "=r"(a) : "l"(p));
    return a;
}
__device__ __forceinline__ void mbar_init(uint32_t addr, uint32_t cnt) {
    asm volatile("mbarrier.init.shared.b64 [%0], %1;" :: "r"(addr), "r"(cnt) : "memory");
}
__device__ __forceinline__ void mbar_expect_tx(uint32_t addr, uint32_t bytes) {
    asm volatile("mbarrier.arrive.expect_tx.shared.b64 _, [%0], %1;"
                 :: "r"(addr), "r"(bytes) : "memory");
}
__device__ __forceinline__ void mbar_wait(uint32_t addr, uint32_t parity) {
    asm volatile(
        "{\n\t.reg .pred P;\n\t"
        "WL_%=:\n\t"
        "mbarrier.try_wait.parity.acquire.cta.shared::cta.b64 P, [%0], %1, 0x989680;\n\t"
        "@P bra.uni WD_%=;\n\t"
        "bra.uni WL_%=;\n\t"
        "WD_%=:\n\t}"
        :: "r"(addr), "r"(parity) : "memory");
}
__device__ __forceinline__ void bulk_g2s(uint32_t dst, const void* src,
                                         uint32_t bytes, uint32_t mbar) {
    asm volatile(
        "cp.async.bulk.shared::cta.global.mbarrier::complete_tx::bytes "
        "[%0], [%1], %2, [%3];"
        :: "r"(dst), "l"(src), "r"(bytes), "r"(mbar) : "memory");
}
__device__ __forceinline__ void ldsm4(uint32_t* r, uint32_t addr) {
    asm volatile("ldmatrix.sync.aligned.m8n8.x4.shared.b16 {%0,%1,%2,%3}, [%4];"
                 : "=r"(r[0]), "=r"(r[1]), "=r"(r[2]), "=r"(r[3]) : "r"(addr));
}
__device__ __forceinline__ void mma16816(float* c, const uint32_t* a,
                                         uint32_t b0, uint32_t b1) {
    asm volatile(
        "mma.sync.aligned.m16n8k16.row.col.f32.f16.f16.f32 "
        "{%0,%1,%2,%3}, {%4,%5,%6,%7}, {%8,%9}, {%0,%1,%2,%3};"
        : "+f"(c[0]), "+f"(c[1]), "+f"(c[2]), "+f"(c[3])
        : "r"(a[0]), "r"(a[1]), "r"(a[2]), "r"(a[3]), "r"(b0), "r"(b1));
}

// ---------------------------------------------------------------------------
// Converter: fp32 row-major -> fp16 K-blocked + swizzled (3 sources, grid.y).
// Stored half offset = (kc*rows + r)*32 + (c16 ^ ((r>>1)&3))*8 + w.
// ---------------------------------------------------------------------------
__global__ __launch_bounds__(256) void convert_blk_kernel(
    const float* __restrict__ s0, __half* __restrict__ d0,
    const float* __restrict__ s1, __half* __restrict__ d1,
    const float* __restrict__ s2, __half* __restrict__ d2,
    int nchunks, int rows)
{
    int i = blockIdx.x * 256 + threadIdx.x;
    if (i >= nchunks) return;
    const float* s = (blockIdx.y == 0) ? s0 : (blockIdx.y == 1) ? s1 : s2;
    __half*      d = (blockIdx.y == 0) ? d0 : (blockIdx.y == 1) ? d1 : d2;
    int r = i >> 6, c = i & 63;
    const float4* p = reinterpret_cast<const float4*>(s + (size_t)r * DIM + c * 8);
    float4 x0 = p[0], x1 = p[1];
    __half2 h0 = __float22half2_rn(make_float2(x0.x, x0.y));
    __half2 h1 = __float22half2_rn(make_float2(x0.z, x0.w));
    __half2 h2 = __float22half2_rn(make_float2(x1.x, x1.y));
    __half2 h3 = __float22half2_rn(make_float2(x1.z, x1.w));
    uint4 o;
    o.x = *reinterpret_cast<uint32_t*>(&h0);
    o.y = *reinterpret_cast<uint32_t*>(&h1);
    o.z = *reinterpret_cast<uint32_t*>(&h2);
    o.w = *reinterpret_cast<uint32_t*>(&h3);
    int kc = c >> 2, c16 = c & 3;
    int sw = c16 ^ ((r >> 1) & 3);
    reinterpret_cast<uint4*>(d)[(size_t)(kc * rows + r) * 4 + sw] = o;
}

// ---------------------------------------------------------------------------
// HMMA fp16 GEMM, cp.async.bulk, 128x128 tile, BK=32, 4-stage pipeline,
// 8 warps (2x4), warp tile 64x32, 2 CTAs/SM. Epilogue also emits per-row
// sum-of-squares partials (for the fused lorentz normalization).
// ---------------------------------------------------------------------------
#define BK 32
#define ATILE 8192                    // 128 rows * 64 B
#define BTILE 8192                    // 128 rows * 64 B
#define STGB (ATILE + BTILE)          // 16384
#define NPIPE 4
#define MBAR_OFF (NPIPE*STGB)         // 65536
#define GEMM_SMEM (MBAR_OFF + 64)
#define NSTAGE 16                     // K=512 / BK

__global__ __launch_bounds__(256, 2) void gemm_mma_kernel(
    const __half* __restrict__ Xh, const __half* __restrict__ Wh,
    const float* __restrict__ bq, const float* __restrict__ bk,
    const float* __restrict__ bv,
    float* __restrict__ Yall, float* __restrict__ sspart)
{
    extern __shared__ char smem[];
    const int z = blockIdx.z;
    const float* bias = (z == 0) ? bq : (z == 1) ? bk : bv;
    float* Y = Yall + (size_t)z * NROWS * DIM;

    const int bm = blockIdx.y * 128;
    const int bn = blockIdx.x * 128;
    const int tid = threadIdx.x;
    const int wid = tid >> 5, lane = tid & 31;
    const int wm = wid >> 2, wn = wid & 3;      // 2x4 warp grid, 64x32 tiles

    uint32_t sb = smem_u32(smem);
    uint32_t mb = sb + MBAR_OFF;

    if (tid == 0) {
#pragma unroll
        for (int p = 0; p < NPIPE; p++) mbar_init(mb + p * 8, 1);
    }
    __syncthreads();

    const __half* Abase = Xh + (size_t)z * NROWS * DIM + (size_t)bm * 32;
    const __half* Bbase = Wh + (size_t)z * DIM * DIM   + (size_t)bn * 32;

#define ISSUE(stage, kc)                                                      \
    if (tid == 0) {                                                           \
        uint32_t m = mb + (stage) * 8;                                        \
        mbar_expect_tx(m, STGB);                                              \
        bulk_g2s(sb + (stage) * STGB, Abase + (size_t)(kc) * NROWS * 32,      \
                 ATILE, m);                                                   \
        bulk_g2s(sb + (stage) * STGB + ATILE, Bbase + (size_t)(kc) * DIM * 32,\
                 BTILE, m);                                                   \
    }

    ISSUE(0, 0)
    ISSUE(1, 1)
    ISSUE(2, 2)

    float acc[4][4][4];
#pragma unroll
    for (int i = 0; i < 4; i++)
#pragma unroll
        for (int j = 0; j < 4; j++)
#pragma unroll
            for (int r = 0; r < 4; r++) acc[i][j][r] = 0.f;

    const int lrow = lane & 15;
    const int lh = lane >> 4;

    for (int s = 0; s < NSTAGE; s++) {
        mbar_wait(mb + (s % NPIPE) * 8, (s / NPIPE) & 1);
        uint32_t st = sb + (s % NPIPE) * STGB;

#pragma unroll
        for (int ks = 0; ks < 2; ks++) {
            const int c16 = ks * 2 + lh;
            uint32_t af[4][4], bf[2][4];
#pragma unroll
            for (int mt = 0; mt < 4; mt++) {
                int row = wm*64 + mt*16 + lrow;
                uint32_t addr = st + row * 64 + ((c16 ^ ((row >> 1) & 3)) << 4);
                ldsm4(af[mt], addr);
            }
#pragma unroll
            for (int bt = 0; bt < 2; bt++) {
                int row = wn*32 + bt*16 + lrow;
                uint32_t addr = st + ATILE + row * 64
                              + ((c16 ^ ((row >> 1) & 3)) << 4);
                ldsm4(bf[bt], addr);
            }
#pragma unroll
            for (int mt = 0; mt < 4; mt++)
#pragma unroll
                for (int nt = 0; nt < 4; nt++) {
                    int g = nt >> 1, o = nt & 1;
                    mma16816(acc[mt][nt], af[mt], bf[g][o], bf[g][o+2]);
                }
        }
        __syncthreads();
        if (s + 3 < NSTAGE) ISSUE((s + 3) % NPIPE, s + 3)
    }
#undef ISSUE

    // Epilogue: bias add + store + per-row sumsq partials.
    float2 bb[4];
#pragma unroll
    for (int nt = 0; nt < 4; nt++) {
        int col = bn + wn*32 + nt*8 + (lane & 3)*2;
        bb[nt] = make_float2(bias[col], bias[col+1]);
    }
    const int slot = blockIdx.x * 4 + wn;   // 0..15
#pragma unroll
    for (int mt = 0; mt < 4; mt++) {
        int row = bm + wm*64 + mt*16 + (lane >> 2);
        float s0 = 0.f, s1 = 0.f;
#pragma unroll
        for (int nt = 0; nt < 4; nt++) {
            int col = bn + wn*32 + nt*8 + (lane & 3)*2;
            float y00 = acc[mt][nt][0] + bb[nt].x;
            float y01 = acc[mt][nt][1] + bb[nt].y;
            float y10 = acc[mt][nt][2] + bb[nt].x;
            float y11 = acc[mt][nt][3] + bb[nt].y;
            *reinterpret_cast<float2*>(Y + (size_t)row * DIM + col) =
                make_float2(y00, y01);
            *reinterpret_cast<float2*>(Y + (size_t)(row + 8) * DIM + col) =
                make_float2(y10, y11);
            s0 += y00*y00 + y01*y01;
            s1 += y10*y10 + y11*y11;
        }
        s0 += __shfl_xor_sync(0xffffffffu, s0, 1);
        s0 += __shfl_xor_sync(0xffffffffu, s0, 2);
        s1 += __shfl_xor_sync(0xffffffffu, s1, 1);
        s1 += __shfl_xor_sync(0xffffffffu, s1, 2);
        if ((lane & 3) == 0) {
            sspart[(size_t)slot * 3 * NROWS + z * NROWS + row]     = s0;
            sspart[(size_t)slot * 3 * NROWS + z * NROWS + row + 8] = s1;
        }
    }
}

// ---------------------------------------------------------------------------
// Scale kernel: fold 16 sumsq partials, compute lorentz time/scale per row.
// Stores Y[row,0] = time/scale (so consumers scale uniformly), g_scale[row].
// ---------------------------------------------------------------------------
__global__ __launch_bounds__(256) void scale_kernel(
    float* __restrict__ Yall, const float* __restrict__ sspart,
    float* __restrict__ scales,
    const float* __restrict__ lsq, const float* __restrict__ lsk,
    const float* __restrict__ lsv)
{
    int g = blockIdx.x * 256 + threadIdx.x;
    if (g >= 3 * NROWS) return;
    int z = g / NROWS;
    float ls = (z == 0) ? lsq[0] : (z == 1) ? lsk[0] : lsv[0];
    float y0 = Yall[(size_t)g * DIM];
    float tot = 0.f;
#pragma unroll
    for (int s = 0; s < 16; s++) tot += sspart[(size_t)s * 3 * NROWS + g];
    float rest = fmaxf(tot - y0 * y0, 1e-8f);
    float time = expf(ls) / (1.f + expf(-y0)) + 1.0001f;
    float sc = sqrtf((time * time - 1.f) / rest);
    scales[g] = sc;
    Yall[(size_t)g * DIM] = time / sc;
}

// ---------------------------------------------------------------------------
// kkv + fused colsum, with on-the-fly row scaling (lorentz folded in):
//   M'[d1,d2] = (2/as)*sgn[d1]*sum_s (K[s,d1]*kscale[s])*(V[s,d2]*vscale[s])
//   CS[d]     = (2/as + ab)*sum_s V[s,d]*vscale[s]
// ---------------------------------------------------------------------------
__global__ __launch_bounds__(256) void kkv_kernel(
    const float* __restrict__ Kb, const float* __restrict__ Vb,
    const float* __restrict__ scales,
    float* __restrict__ M, float* __restrict__ CS,
    const float* __restrict__ as_p, const float* __restrict__ ab_p)
{
    int bh = blockIdx.x;
    int b = bh >> 3, h = bh & 7;
    __shared__ float Ks[32][64];
    __shared__ float Vs[32][64];
    int tid = threadIdx.x;
    int d1b = (tid >> 4) * 4;
    int d2b = (tid & 15) * 4;
    int lr = tid >> 3;
    int lc = (tid & 7) * 8;
    float acc[4][4];
#pragma unroll
    for (int i = 0; i < 4; i++)
#pragma unroll
        for (int j = 0; j < 4; j++) acc[i][j] = 0.f;
    float csum = 0.f;

    const float* kp = Kb + (size_t)b * SEQ * DIM + h * DPH;
    const float* vp = Vb + (size_t)b * SEQ * DIM + h * DPH;
    const float* ksc = scales + NROWS + b * SEQ;      // K scales
    const float* vsc = scales + 2 * NROWS + b * SEQ;  // V scales

    for (int s0 = 0; s0 < SEQ; s0 += 32) {
        float ks = ksc[s0 + lr];
        float vs = vsc[s0 + lr];
        float4 k0 = *(const float4*)(kp + (size_t)(s0+lr) * DIM + lc);
        float4 k1 = *(const float4*)(kp + (size_t)(s0+lr) * DIM + lc + 4);
        float4 v0 = *(const float4*)(vp + (size_t)(s0+lr) * DIM + lc);
        float4 v1 = *(const float4*)(vp + (size_t)(s0+lr) * DIM + lc + 4);
        k0.x*=ks; k0.y*=ks; k0.z*=ks; k0.w*=ks;
        k1.x*=ks; k1.y*=ks; k1.z*=ks; k1.w*=ks;
        v0.x*=vs; v0.y*=vs; v0.z*=vs; v0.w*=vs;
        v1.x*=vs; v1.y*=vs; v1.z*=vs; v1.w*=vs;
        __syncthreads();
        *(float4*)&Ks[lr][lc]   = k0; *(float4*)&Ks[lr][lc+4] = k1;
        *(float4*)&Vs[lr][lc]   = v0; *(float4*)&Vs[lr][lc+4] = v1;
        __syncthreads();
#pragma unroll
        for (int ss = 0; ss < 32; ss++) {
            float4 kv = *(const float4*)&Ks[ss][d1b];
            float4 vv = *(const float4*)&Vs[ss][d2b];
            float ka[4] = {kv.x, kv.y, kv.z, kv.w};
            float va[4] = {vv.x, vv.y, vv.z, vv.w};
#pragma unroll
            for (int i = 0; i < 4; i++)
#pragma unroll
                for (int j = 0; j < 4; j++) acc[i][j] += ka[i] * va[j];
        }
        if (tid < 64) {
#pragma unroll
            for (int ss = 0; ss < 32; ss++) csum += Vs[ss][tid];
        }
    }

    float c2 = 2.f / as_p[0];
    float* Mp = M + (size_t)bh * DPH * DPH;
#pragma unroll
    for (int i = 0; i < 4; i++) {
        float sg = (d1b + i == 0) ? -c2 : c2;
#pragma unroll
        for (int j = 0; j < 4; j++)
            Mp[(d1b + i) * DPH + d2b + j] = acc[i][j] * sg;
    }
    if (tid < 64) {
        float c1 = 2.f / as_p[0] + ab_p[0];
        CS[bh * DPH + tid] = csum * c1;
    }
}

// ---------------------------------------------------------------------------
// ave with on-the-fly Q scaling.
// ---------------------------------------------------------------------------
__global__ __launch_bounds__(256) void ave_kernel(
    const float* __restrict__ Qb, const float* __restrict__ scales,
    const float* __restrict__ M, const float* __restrict__ CS,
    float* __restrict__ Out)
{
    int bh = blockIdx.x;
    int b = bh >> 3, h = bh & 7;
    int s0 = blockIdx.y * 32;
    int tid = threadIdx.x;
    int warp = tid >> 5, lane = tid & 31;

    __shared__ float Ms[64][64];
    {
        const float* Mp = M + (size_t)bh * DPH * DPH;
        float* Msf = &Ms[0][0];
        for (int i = tid * 4; i < 4096; i += 1024)
            *(float4*)&Msf[i] = *(const float4*)&Mp[i];
    }
    __syncthreads();

    float cs0 = CS[bh * DPH + lane];
    float cs1 = CS[bh * DPH + lane + 32];
    const float* qp = Qb + (size_t)b * SEQ * DIM + h * DPH;
    const float* qsc = scales + b * SEQ;

    for (int r = warp; r < 32; r += 8) {
        int srow = s0 + r;
        const float* q = qp + (size_t)srow * DIM;
        float qs = qsc[srow];
        float d0 = 0.f, d1 = 0.f;
#pragma unroll
        for (int dp = 0; dp < 64; dp++) {
            float qv = __ldg(&q[dp]);
            d0 += qv * Ms[dp][lane];
            d1 += qv * Ms[dp][lane + 32];
        }
        float a0 = cs0 + qs * d0;
        float a1 = cs1 + qs * d1;
        float contrib = a0 * a0 * ((lane == 0) ? -1.f : 1.f) + a1 * a1;
#pragma unroll
        for (int o = 16; o > 0; o >>= 1) contrib += __shfl_xor_sync(0xffffffffu, contrib, o);
        float inv = 1.f / sqrtf(fmaxf(fabsf(contrib), 1e-8f));
        size_t ob = ((size_t)b * SEQ + srow) * DIM + h * DPH;
        Out[ob + lane]      = a0 * inv;
        Out[ob + lane + 32] = a1 * inv;
    }
}

// ===========================================================================
extern "C" void kernel_launch(void* const* d_in, const int* in_sizes, int n_in,
                              void* d_out, int out_size)
{
    const float* key   = (const float*)d_in[0];
    const float* value = (const float*)d_in[1];
    const float* query = (const float*)d_in[2];
    const float* Wq  = (const float*)d_in[3];
    const float* bq  = (const float*)d_in[4];
    const float* lsq = (const float*)d_in[5];
    const float* Wk  = (const float*)d_in[6];
    const float* bk  = (const float*)d_in[7];
    const float* lsk = (const float*)d_in[8];
    const float* Wv  = (const float*)d_in[9];
    const float* bv  = (const float*)d_in[10];
    const float* lsv = (const float*)d_in[11];
    const float* as_p = (const float*)d_in[12];
    const float* ab_p = (const float*)d_in[13];
    float* out = (float*)d_out;

    float *gqkv, *gM, *gcs, *gss, *gsc;
    __half *gxh, *gwh;
    cudaGetSymbolAddress((void**)&gqkv, g_qkv);
    cudaGetSymbolAddress((void**)&gxh,  g_xh);
    cudaGetSymbolAddress((void**)&gwh,  g_wh);
    cudaGetSymbolAddress((void**)&gss,  g_sspart);
    cudaGetSymbolAddress((void**)&gsc,  g_scale);
    cudaGetSymbolAddress((void**)&gM,   g_M);
    cudaGetSymbolAddress((void**)&gcs,  g_cs);

    float* gq = gqkv;
    float* gk = gqkv + (size_t)NROWS * DIM;
    float* gv = gqkv + (size_t)2 * NROWS * DIM;

    const int XCH = NROWS * 64;   // 16B chunks per X tensor
    const int WCH = DIM * 64;     // 16B chunks per W tensor

    // Launch order: GEMM must stay the 4th launch for ncu.
    {   // #1: all three W converts
        dim3 gw(WCH/256, 3);
        convert_blk_kernel<<<gw, 256>>>(Wq, gwh,
                                        Wk, gwh + DIM*DIM,
                                        Wv, gwh + 2*DIM*DIM, WCH, DIM);
    }
    {   // #2: X query
        dim3 g1(XCH/256, 1);
        convert_blk_kernel<<<g1, 256>>>(query, gxh, query, gxh, query, gxh,
                                        XCH, NROWS);
    }
    {   // #3: X key + value
        dim3 g2(XCH/256, 2);
        convert_blk_kernel<<<g2, 256>>>(key,   gxh +   NROWS*DIM,
                                        value, gxh + 2*NROWS*DIM,
                                        value, gxh + 2*NROWS*DIM, XCH, NROWS);
    }

    // #4: GEMM (profiled)
    cudaFuncSetAttribute(gemm_mma_kernel,
                         cudaFuncAttributeMaxDynamicSharedMemorySize, GEMM_SMEM);
    dim3 ggrid(DIM / 128, NROWS / 128, 3);
    gemm_mma_kernel<<<ggrid, 256, GEMM_SMEM>>>(
        gxh, gwh, bq, bk, bv, gqkv, gss);

    // #5: row scale/time
    scale_kernel<<<(3*NROWS)/256, 256>>>(gqkv, gss, gsc, lsq, lsk, lsv);

    // #6: kkv + fused colsum (scaled on the fly)
    kkv_kernel<<<BATCH * NHEAD, 256>>>(gk, gv, gsc, gM, gcs, as_p, ab_p);

    // #7: ave (scaled on the fly)
    dim3 agrid(BATCH * NHEAD, SEQ / 32);
    ave_kernel<<<agrid, 256>>>(gq, gsc, gM, gcs, out);
}

// round 16
// speedup vs baseline: 2.7924x; 1.3468x over previous
#include <cuda_runtime.h>
#include <cuda_fp16.h>
#include <cstdint>
#include <math.h>

#define BATCH 16
#define SEQ   1024
#define DIM   512
#define NHEAD 8
#define DPH   64
#define NROWS (BATCH*SEQ)   // 16384

// ---------------------------------------------------------------------------
// Scratch (device globals: no allocation allowed anywhere)
// ---------------------------------------------------------------------------
__device__ float g_qkv[3*NROWS*DIM];                 // GEMM outputs (q,k,v)
__device__ __half g_xh[3*NROWS*DIM];                 // fp16(x), K-blocked+swizzled
__device__ __half g_wh[3*DIM*DIM];                   // fp16(W), K-blocked+swizzled
__device__ float g_sspart[16*3*NROWS];               // per-(ntile,warp) row sumsq
__device__ float g_scale[3*NROWS];                   // per-row lorentz scale
__device__ float g_M[2*BATCH*NHEAD*DPH*DPH];         // 2 s-half partials
__device__ float g_cs[2*BATCH*NHEAD*DPH];            // 2 s-half partials

// ---------------------------------------------------------------------------
// PTX helpers (base sm_80/sm_90 features only — no arch-specific 'a' insts)
// ---------------------------------------------------------------------------
__device__ __forceinline__ uint32_t smem_u32(const void* p) {
    uint32_t a;
    asm("{ .reg .u64 t; cvta.to.shared.u64 t, %1; cvt.u32.u64 %0, t; }"
        : "=r"(a) : "l"(p));
    return a;
}
__device__ __forceinline__ void mbar_init(uint32_t addr, uint32_t cnt) {
    asm volatile("mbarrier.init.shared.b64 [%0], %1;" :: "r"(addr), "r"(cnt) : "memory");
}
__device__ __forceinline__ void mbar_expect_tx(uint32_t addr, uint32_t bytes) {
    asm volatile("mbarrier.arrive.expect_tx.shared.b64 _, [%0], %1;"
                 :: "r"(addr), "r"(bytes) : "memory");
}
__device__ __forceinline__ void mbar_wait(uint32_t addr, uint32_t parity) {
    asm volatile(
        "{\n\t.reg .pred P;\n\t"
        "WL_%=:\n\t"
        "mbarrier.try_wait.parity.acquire.cta.shared::cta.b64 P, [%0], %1, 0x989680;\n\t"
        "@P bra.uni WD_%=;\n\t"
        "bra.uni WL_%=;\n\t"
        "WD_%=:\n\t}"
        :: "r"(addr), "r"(parity) : "memory");
}
__device__ __forceinline__ void bulk_g2s(uint32_t dst, const void* src,
                                         uint32_t bytes, uint32_t mbar) {
    asm volatile(
        "cp.async.bulk.shared::cta.global.mbarrier::complete_tx::bytes "
        "[%0], [%1], %2, [%3];"
        :: "r"(dst), "l"(src), "r"(bytes), "r"(mbar) : "memory");
}
__device__ __forceinline__ void ldsm4(uint32_t* r, uint32_t addr) {
    asm volatile("ldmatrix.sync.aligned.m8n8.x4.shared.b16 {%0,%1,%2,%3}, [%4];"
                 : "=r"(r[0]), "=r"(r[1]), "=r"(r[2]), "=r"(r[3]) : "r"(addr));
}
__device__ __forceinline__ void mma16816(float* c, const uint32_t* a,
                                         uint32_t b0, uint32_t b1) {
    asm volatile(
        "mma.sync.aligned.m16n8k16.row.col.f32.f16.f16.f32 "
        "{%0,%1,%2,%3}, {%4,%5,%6,%7}, {%8,%9}, {%0,%1,%2,%3};"
        : "+f"(c[0]), "+f"(c[1]), "+f"(c[2]), "+f"(c[3])
        : "r"(a[0]), "r"(a[1]), "r"(a[2]), "r"(a[3]), "r"(b0), "r"(b1));
}

// ---------------------------------------------------------------------------
// Converter: fp32 row-major -> fp16 K-blocked + swizzled (3 sources, grid.y).
// ---------------------------------------------------------------------------
__global__ __launch_bounds__(256) void convert_blk_kernel(
    const float* __restrict__ s0, __half* __restrict__ d0,
    const float* __restrict__ s1, __half* __restrict__ d1,
    const float* __restrict__ s2, __half* __restrict__ d2,
    int nchunks, int rows)
{
    int i = blockIdx.x * 256 + threadIdx.x;
    if (i >= nchunks) return;
    const float* s = (blockIdx.y == 0) ? s0 : (blockIdx.y == 1) ? s1 : s2;
    __half*      d = (blockIdx.y == 0) ? d0 : (blockIdx.y == 1) ? d1 : d2;
    int r = i >> 6, c = i & 63;
    const float4* p = reinterpret_cast<const float4*>(s + (size_t)r * DIM + c * 8);
    float4 x0 = p[0], x1 = p[1];
    __half2 h0 = __float22half2_rn(make_float2(x0.x, x0.y));
    __half2 h1 = __float22half2_rn(make_float2(x0.z, x0.w));
    __half2 h2 = __float22half2_rn(make_float2(x1.x, x1.y));
    __half2 h3 = __float22half2_rn(make_float2(x1.z, x1.w));
    uint4 o;
    o.x = *reinterpret_cast<uint32_t*>(&h0);
    o.y = *reinterpret_cast<uint32_t*>(&h1);
    o.z = *reinterpret_cast<uint32_t*>(&h2);
    o.w = *reinterpret_cast<uint32_t*>(&h3);
    int kc = c >> 2, c16 = c & 3;
    int sw = c16 ^ ((r >> 1) & 3);
    reinterpret_cast<uint4*>(d)[(size_t)(kc * rows + r) * 4 + sw] = o;
}

// ---------------------------------------------------------------------------
// HMMA fp16 GEMM, cp.async.bulk, 128x128 tile, BK=32, 4-stage pipeline,
// 8 warps (2x4), warp tile 64x32, 2 CTAs/SM. Epilogue emits per-row
// sum-of-squares partials.
// ---------------------------------------------------------------------------
#define BK 32
#define ATILE 8192
#define BTILE 8192
#define STGB (ATILE + BTILE)
#define NPIPE 4
#define MBAR_OFF (NPIPE*STGB)
#define GEMM_SMEM (MBAR_OFF + 64)
#define NSTAGE 16

__global__ __launch_bounds__(256, 2) void gemm_mma_kernel(
    const __half* __restrict__ Xh, const __half* __restrict__ Wh,
    const float* __restrict__ bq, const float* __restrict__ bk,
    const float* __restrict__ bv,
    float* __restrict__ Yall, float* __restrict__ sspart)
{
    extern __shared__ char smem[];
    const int z = blockIdx.z;
    const float* bias = (z == 0) ? bq : (z == 1) ? bk : bv;
    float* Y = Yall + (size_t)z * NROWS * DIM;

    const int bm = blockIdx.y * 128;
    const int bn = blockIdx.x * 128;
    const int tid = threadIdx.x;
    const int wid = tid >> 5, lane = tid & 31;
    const int wm = wid >> 2, wn = wid & 3;

    uint32_t sb = smem_u32(smem);
    uint32_t mb = sb + MBAR_OFF;

    if (tid == 0) {
#pragma unroll
        for (int p = 0; p < NPIPE; p++) mbar_init(mb + p * 8, 1);
    }
    __syncthreads();

    const __half* Abase = Xh + (size_t)z * NROWS * DIM + (size_t)bm * 32;
    const __half* Bbase = Wh + (size_t)z * DIM * DIM   + (size_t)bn * 32;

#define ISSUE(stage, kc)                                                      \
    if (tid == 0) {                                                           \
        uint32_t m = mb + (stage) * 8;                                        \
        mbar_expect_tx(m, STGB);                                              \
        bulk_g2s(sb + (stage) * STGB, Abase + (size_t)(kc) * NROWS * 32,      \
                 ATILE, m);                                                   \
        bulk_g2s(sb + (stage) * STGB + ATILE, Bbase + (size_t)(kc) * DIM * 32,\
                 BTILE, m);                                                   \
    }

    ISSUE(0, 0)
    ISSUE(1, 1)
    ISSUE(2, 2)

    float acc[4][4][4];
#pragma unroll
    for (int i = 0; i < 4; i++)
#pragma unroll
        for (int j = 0; j < 4; j++)
#pragma unroll
            for (int r = 0; r < 4; r++) acc[i][j][r] = 0.f;

    const int lrow = lane & 15;
    const int lh = lane >> 4;

    for (int s = 0; s < NSTAGE; s++) {
        mbar_wait(mb + (s % NPIPE) * 8, (s / NPIPE) & 1);
        uint32_t st = sb + (s % NPIPE) * STGB;

#pragma unroll
        for (int ks = 0; ks < 2; ks++) {
            const int c16 = ks * 2 + lh;
            uint32_t af[4][4], bf[2][4];
#pragma unroll
            for (int mt = 0; mt < 4; mt++) {
                int row = wm*64 + mt*16 + lrow;
                uint32_t addr = st + row * 64 + ((c16 ^ ((row >> 1) & 3)) << 4);
                ldsm4(af[mt], addr);
            }
#pragma unroll
            for (int bt = 0; bt < 2; bt++) {
                int row = wn*32 + bt*16 + lrow;
                uint32_t addr = st + ATILE + row * 64
                              + ((c16 ^ ((row >> 1) & 3)) << 4);
                ldsm4(bf[bt], addr);
            }
#pragma unroll
            for (int mt = 0; mt < 4; mt++)
#pragma unroll
                for (int nt = 0; nt < 4; nt++) {
                    int g = nt >> 1, o = nt & 1;
                    mma16816(acc[mt][nt], af[mt], bf[g][o], bf[g][o+2]);
                }
        }
        __syncthreads();
        if (s + 3 < NSTAGE) ISSUE((s + 3) % NPIPE, s + 3)
    }
#undef ISSUE

    float2 bb[4];
#pragma unroll
    for (int nt = 0; nt < 4; nt++) {
        int col = bn + wn*32 + nt*8 + (lane & 3)*2;
        bb[nt] = make_float2(bias[col], bias[col+1]);
    }
    const int slot = blockIdx.x * 4 + wn;
#pragma unroll
    for (int mt = 0; mt < 4; mt++) {
        int row = bm + wm*64 + mt*16 + (lane >> 2);
        float s0 = 0.f, s1 = 0.f;
#pragma unroll
        for (int nt = 0; nt < 4; nt++) {
            int col = bn + wn*32 + nt*8 + (lane & 3)*2;
            float y00 = acc[mt][nt][0] + bb[nt].x;
            float y01 = acc[mt][nt][1] + bb[nt].y;
            float y10 = acc[mt][nt][2] + bb[nt].x;
            float y11 = acc[mt][nt][3] + bb[nt].y;
            *reinterpret_cast<float2*>(Y + (size_t)row * DIM + col) =
                make_float2(y00, y01);
            *reinterpret_cast<float2*>(Y + (size_t)(row + 8) * DIM + col) =
                make_float2(y10, y11);
            s0 += y00*y00 + y01*y01;
            s1 += y10*y10 + y11*y11;
        }
        s0 += __shfl_xor_sync(0xffffffffu, s0, 1);
        s0 += __shfl_xor_sync(0xffffffffu, s0, 2);
        s1 += __shfl_xor_sync(0xffffffffu, s1, 1);
        s1 += __shfl_xor_sync(0xffffffffu, s1, 2);
        if ((lane & 3) == 0) {
            sspart[(size_t)slot * 3 * NROWS + z * NROWS + row]     = s0;
            sspart[(size_t)slot * 3 * NROWS + z * NROWS + row + 8] = s1;
        }
    }
}

// ---------------------------------------------------------------------------
// Scale kernel: fold 16 sumsq partials, compute lorentz time/scale per row.
// ---------------------------------------------------------------------------
__global__ __launch_bounds__(256) void scale_kernel(
    float* __restrict__ Yall, const float* __restrict__ sspart,
    float* __restrict__ scales,
    const float* __restrict__ lsq, const float* __restrict__ lsk,
    const float* __restrict__ lsv)
{
    int g = blockIdx.x * 256 + threadIdx.x;
    if (g >= 3 * NROWS) return;
    int z = g / NROWS;
    float ls = (z == 0) ? lsq[0] : (z == 1) ? lsk[0] : lsv[0];
    float y0 = Yall[(size_t)g * DIM];
    float tot = 0.f;
#pragma unroll
    for (int s = 0; s < 16; s++) tot += sspart[(size_t)s * 3 * NROWS + g];
    float rest = fmaxf(tot - y0 * y0, 1e-8f);
    float time = expf(ls) / (1.f + expf(-y0)) + 1.0001f;
    float sc = sqrtf((time * time - 1.f) / rest);
    scales[g] = sc;
    Yall[(size_t)g * DIM] = time / sc;
}

// ---------------------------------------------------------------------------
// kkv + fused colsum over an s-half (grid.y = 2 halves), scaling on the fly.
// Writes M/CS partials per half.
// ---------------------------------------------------------------------------
#define NBH (BATCH*NHEAD)
__global__ __launch_bounds__(256) void kkv_kernel(
    const float* __restrict__ Kb, const float* __restrict__ Vb,
    const float* __restrict__ scales,
    float* __restrict__ M, float* __restrict__ CS,
    const float* __restrict__ as_p, const float* __restrict__ ab_p)
{
    int bh = blockIdx.x;
    int half = blockIdx.y;
    int b = bh >> 3, h = bh & 7;
    __shared__ float Ks[32][64];
    __shared__ float Vs[32][64];
    int tid = threadIdx.x;
    int d1b = (tid >> 4) * 4;
    int d2b = (tid & 15) * 4;
    int lr = tid >> 3;
    int lc = (tid & 7) * 8;
    float acc[4][4];
#pragma unroll
    for (int i = 0; i < 4; i++)
#pragma unroll
        for (int j = 0; j < 4; j++) acc[i][j] = 0.f;
    float csum = 0.f;

    const int sbeg = half * (SEQ/2);
    const float* kp = Kb + (size_t)b * SEQ * DIM + h * DPH;
    const float* vp = Vb + (size_t)b * SEQ * DIM + h * DPH;
    const float* ksc = scales + NROWS + b * SEQ;
    const float* vsc = scales + 2 * NROWS + b * SEQ;

    for (int s0 = sbeg; s0 < sbeg + SEQ/2; s0 += 32) {
        float ks = ksc[s0 + lr];
        float vs = vsc[s0 + lr];
        float4 k0 = *(const float4*)(kp + (size_t)(s0+lr) * DIM + lc);
        float4 k1 = *(const float4*)(kp + (size_t)(s0+lr) * DIM + lc + 4);
        float4 v0 = *(const float4*)(vp + (size_t)(s0+lr) * DIM + lc);
        float4 v1 = *(const float4*)(vp + (size_t)(s0+lr) * DIM + lc + 4);
        k0.x*=ks; k0.y*=ks; k0.z*=ks; k0.w*=ks;
        k1.x*=ks; k1.y*=ks; k1.z*=ks; k1.w*=ks;
        v0.x*=vs; v0.y*=vs; v0.z*=vs; v0.w*=vs;
        v1.x*=vs; v1.y*=vs; v1.z*=vs; v1.w*=vs;
        __syncthreads();
        *(float4*)&Ks[lr][lc]   = k0; *(float4*)&Ks[lr][lc+4] = k1;
        *(float4*)&Vs[lr][lc]   = v0; *(float4*)&Vs[lr][lc+4] = v1;
        __syncthreads();
#pragma unroll
        for (int ss = 0; ss < 32; ss++) {
            float4 kv = *(const float4*)&Ks[ss][d1b];
            float4 vv = *(const float4*)&Vs[ss][d2b];
            float ka[4] = {kv.x, kv.y, kv.z, kv.w};
            float va[4] = {vv.x, vv.y, vv.z, vv.w};
#pragma unroll
            for (int i = 0; i < 4; i++)
#pragma unroll
                for (int j = 0; j < 4; j++) acc[i][j] += ka[i] * va[j];
        }
        if (tid < 64) {
#pragma unroll
            for (int ss = 0; ss < 32; ss++) csum += Vs[ss][tid];
        }
    }

    float c2 = 2.f / as_p[0];
    float* Mp = M + ((size_t)half * NBH + bh) * DPH * DPH;
#pragma unroll
    for (int i = 0; i < 4; i++) {
        float sg = (d1b + i == 0) ? -c2 : c2;
#pragma unroll
        for (int j = 0; j < 4; j++)
            Mp[(d1b + i) * DPH + d2b + j] = acc[i][j] * sg;
    }
    if (tid < 64) {
        float c1 = 2.f / as_p[0] + ab_p[0];
        CS[((size_t)half * NBH + bh) * DPH + tid] = csum * c1;
    }
}

// ---------------------------------------------------------------------------
// ave: 4 rows per warp-iteration (Ms reads amortized 4x), Q scaled on the fly,
// M/CS halves folded during smem fill.
// ---------------------------------------------------------------------------
__global__ __launch_bounds__(256) void ave_kernel(
    const float* __restrict__ Qb, const float* __restrict__ scales,
    const float* __restrict__ M, const float* __restrict__ CS,
    float* __restrict__ Out)
{
    int bh = blockIdx.x;
    int b = bh >> 3, h = bh & 7;
    int s0 = blockIdx.y * 32;
    int tid = threadIdx.x;
    int warp = tid >> 5, lane = tid & 31;

    __shared__ float Ms[64][64];
    {
        const float* P0 = M + (size_t)bh * DPH * DPH;
        const float* P1 = M + ((size_t)NBH + bh) * DPH * DPH;
        float* Msf = &Ms[0][0];
        for (int i = tid * 4; i < 4096; i += 1024) {
            float4 a = *(const float4*)&P0[i];
            float4 c = *(const float4*)&P1[i];
            a.x += c.x; a.y += c.y; a.z += c.z; a.w += c.w;
            *(float4*)&Msf[i] = a;
        }
    }
    __syncthreads();

    float cs0 = CS[(size_t)bh * DPH + lane]
              + CS[((size_t)NBH + bh) * DPH + lane];
    float cs1 = CS[(size_t)bh * DPH + lane + 32]
              + CS[((size_t)NBH + bh) * DPH + lane + 32];
    const float* qp = Qb + (size_t)b * SEQ * DIM + h * DPH;
    const float* qsc = scales + b * SEQ;

    // 8 warps x 4 rows = 32 rows
    const int r0 = s0 + warp * 4;
    const float* q0 = qp + (size_t)(r0 + 0) * DIM;
    const float* q1 = qp + (size_t)(r0 + 1) * DIM;
    const float* q2 = qp + (size_t)(r0 + 2) * DIM;
    const float* q3 = qp + (size_t)(r0 + 3) * DIM;

    float d0[4] = {0.f, 0.f, 0.f, 0.f};
    float d1[4] = {0.f, 0.f, 0.f, 0.f};
#pragma unroll
    for (int dp = 0; dp < 64; dp++) {
        float m0 = Ms[dp][lane];
        float m1 = Ms[dp][lane + 32];
        float qa = __ldg(&q0[dp]);
        float qb = __ldg(&q1[dp]);
        float qc = __ldg(&q2[dp]);
        float qd = __ldg(&q3[dp]);
        d0[0] += qa * m0; d1[0] += qa * m1;
        d0[1] += qb * m0; d1[1] += qb * m1;
        d0[2] += qc * m0; d1[2] += qc * m1;
        d0[3] += qd * m0; d1[3] += qd * m1;
    }

#pragma unroll
    for (int i = 0; i < 4; i++) {
        int srow = r0 + i;
        float qs = qsc[srow];
        float a0 = cs0 + qs * d0[i];
        float a1 = cs1 + qs * d1[i];
        float contrib = a0 * a0 * ((lane == 0) ? -1.f : 1.f) + a1 * a1;
#pragma unroll
        for (int o = 16; o > 0; o >>= 1)
            contrib += __shfl_xor_sync(0xffffffffu, contrib, o);
        float inv = 1.f / sqrtf(fmaxf(fabsf(contrib), 1e-8f));
        size_t ob = ((size_t)b * SEQ + srow) * DIM + h * DPH;
        Out[ob + lane]      = a0 * inv;
        Out[ob + lane + 32] = a1 * inv;
    }
}

// ===========================================================================
extern "C" void kernel_launch(void* const* d_in, const int* in_sizes, int n_in,
                              void* d_out, int out_size)
{
    const float* key   = (const float*)d_in[0];
    const float* value = (const float*)d_in[1];
    const float* query = (const float*)d_in[2];
    const float* Wq  = (const float*)d_in[3];
    const float* bq  = (const float*)d_in[4];
    const float* lsq = (const float*)d_in[5];
    const float* Wk  = (const float*)d_in[6];
    const float* bk  = (const float*)d_in[7];
    const float* lsk = (const float*)d_in[8];
    const float* Wv  = (const float*)d_in[9];
    const float* bv  = (const float*)d_in[10];
    const float* lsv = (const float*)d_in[11];
    const float* as_p = (const float*)d_in[12];
    const float* ab_p = (const float*)d_in[13];
    float* out = (float*)d_out;

    float *gqkv, *gM, *gcs, *gss, *gsc;
    __half *gxh, *gwh;
    cudaGetSymbolAddress((void**)&gqkv, g_qkv);
    cudaGetSymbolAddress((void**)&gxh,  g_xh);
    cudaGetSymbolAddress((void**)&gwh,  g_wh);
    cudaGetSymbolAddress((void**)&gss,  g_sspart);
    cudaGetSymbolAddress((void**)&gsc,  g_scale);
    cudaGetSymbolAddress((void**)&gM,   g_M);
    cudaGetSymbolAddress((void**)&gcs,  g_cs);

    float* gq = gqkv;
    float* gk = gqkv + (size_t)NROWS * DIM;
    float* gv = gqkv + (size_t)2 * NROWS * DIM;

    const int XCH = NROWS * 64;
    const int WCH = DIM * 64;

    // Launch order: GEMM stays the 4th launch for ncu.
    {   // #1: all three W converts
        dim3 gw(WCH/256, 3);
        convert_blk_kernel<<<gw, 256>>>(Wq, gwh,
                                        Wk, gwh + DIM*DIM,
                                        Wv, gwh + 2*DIM*DIM, WCH, DIM);
    }
    {   // #2: X query
        dim3 g1(XCH/256, 1);
        convert_blk_kernel<<<g1, 256>>>(query, gxh, query, gxh, query, gxh,
                                        XCH, NROWS);
    }
    {   // #3: X key + value
        dim3 g2(XCH/256, 2);
        convert_blk_kernel<<<g2, 256>>>(key,   gxh +   NROWS*DIM,
                                        value, gxh + 2*NROWS*DIM,
                                        value, gxh + 2*NROWS*DIM, XCH, NROWS);
    }

    // #4: GEMM (profiled)
    cudaFuncSetAttribute(gemm_mma_kernel,
                         cudaFuncAttributeMaxDynamicSharedMemorySize, GEMM_SMEM);
    dim3 ggrid(DIM / 128, NROWS / 128, 3);
    gemm_mma_kernel<<<ggrid, 256, GEMM_SMEM>>>(
        gxh, gwh, bq, bk, bv, gqkv, gss);

    // #5: row scale/time
    scale_kernel<<<(3*NROWS)/256, 256>>>(gqkv, gss, gsc, lsq, lsk, lsv);

    // #6: kkv + fused colsum over 2 s-halves
    dim3 kgrid(NBH, 2);
    kkv_kernel<<<kgrid, 256>>>(gk, gv, gsc, gM, gcs, as_p, ab_p);

    // #7: ave (4 rows per warp, folds M/CS halves)
    dim3 agrid(NBH, SEQ / 32);
    ave_kernel<<<agrid, 256>>>(gq, gsc, gM, gcs, out);
}

// round 17
// speedup vs baseline: 2.9866x; 1.0695x over previous
#include <cuda_runtime.h>
#include <cuda_fp16.h>
#include <cstdint>
#include <math.h>

#define BATCH 16
#define SEQ   1024
#define DIM   512
#define NHEAD 8
#define DPH   64
#define NROWS (BATCH*SEQ)   // 16384
#define NBH (BATCH*NHEAD)

// ---------------------------------------------------------------------------
// Scratch (device globals: no allocation allowed anywhere)
// ---------------------------------------------------------------------------
__device__ float g_qkv[3*NROWS*DIM];                 // GEMM outputs (q,k,v)
__device__ __half g_xh[3*NROWS*DIM];                 // fp16(x), K-blocked+swizzled
__device__ __half g_wh[3*DIM*DIM];                   // fp16(W), K-blocked+swizzled
__device__ float g_sspart[16*3*NROWS];               // per-(ntile,warp) row sumsq
__device__ float g_scale[3*NROWS];                   // per-row lorentz scale
__device__ float g_M[2*NBH*DPH*DPH];                 // 2 s-half partials
__device__ float g_cs[2*NBH*DPH];                    // 2 s-half partials

// ---------------------------------------------------------------------------
// PTX helpers (base sm_80/sm_90 features only — no arch-specific 'a' insts)
// ---------------------------------------------------------------------------
__device__ __forceinline__ uint32_t smem_u32(const void* p) {
    uint32_t a;
    asm("{ .reg .u64 t; cvta.to.shared.u64 t, %1; cvt.u32.u64 %0, t; }"
        : "=r"(a) : "l"(p));
    return a;
}
__device__ __forceinline__ void mbar_init(uint32_t addr, uint32_t cnt) {
    asm volatile("mbarrier.init.shared.b64 [%0], %1;" :: "r"(addr), "r"(cnt) : "memory");
}
__device__ __forceinline__ void mbar_expect_tx(uint32_t addr, uint32_t bytes) {
    asm volatile("mbarrier.arrive.expect_tx.shared.b64 _, [%0], %1;"
                 :: "r"(addr), "r"(bytes) : "memory");
}
__device__ __forceinline__ void mbar_wait(uint32_t addr, uint32_t parity) {
    asm volatile(
        "{\n\t.reg .pred P;\n\t"
        "WL_%=:\n\t"
        "mbarrier.try_wait.parity.acquire.cta.shared::cta.b64 P, [%0], %1, 0x989680;\n\t"
        "@P bra.uni WD_%=;\n\t"
        "bra.uni WL_%=;\n\t"
        "WD_%=:\n\t}"
        :: "r"(addr), "r"(parity) : "memory");
}
__device__ __forceinline__ void bulk_g2s(uint32_t dst, const void* src,
                                         uint32_t bytes, uint32_t mbar) {
    asm volatile(
        "cp.async.bulk.shared::cta.global.mbarrier::complete_tx::bytes "
        "[%0], [%1], %2, [%3];"
        :: "r"(dst), "l"(src), "r"(bytes), "r"(mbar) : "memory");
}
__device__ __forceinline__ void ldsm4(uint32_t* r, uint32_t addr) {
    asm volatile("ldmatrix.sync.aligned.m8n8.x4.shared.b16 {%0,%1,%2,%3}, [%4];"
                 : "=r"(r[0]), "=r"(r[1]), "=r"(r[2]), "=r"(r[3]) : "r"(addr));
}
__device__ __forceinline__ void mma16816(float* c, const uint32_t* a,
                                         uint32_t b0, uint32_t b1) {
    asm volatile(
        "mma.sync.aligned.m16n8k16.row.col.f32.f16.f16.f32 "
        "{%0,%1,%2,%3}, {%4,%5,%6,%7}, {%8,%9}, {%0,%1,%2,%3};"
        : "+f"(c[0]), "+f"(c[1]), "+f"(c[2]), "+f"(c[3])
        : "r"(a[0]), "r"(a[1]), "r"(a[2]), "r"(a[3]), "r"(b0), "r"(b1));
}

// ---------------------------------------------------------------------------
// Converter: fp32 row-major -> fp16 K-blocked + swizzled (3 sources, grid.y).
// Stored half offset = (kc*rows + r)*32 + (c16 ^ ((r>>1)&3))*8 + w.
// ---------------------------------------------------------------------------
__global__ __launch_bounds__(256) void convert_blk_kernel(
    const float* __restrict__ s0, __half* __restrict__ d0,
    const float* __restrict__ s1, __half* __restrict__ d1,
    const float* __restrict__ s2, __half* __restrict__ d2,
    int nchunks, int rows)
{
    int i = blockIdx.x * 256 + threadIdx.x;
    if (i >= nchunks) return;
    const float* s = (blockIdx.y == 0) ? s0 : (blockIdx.y == 1) ? s1 : s2;
    __half*      d = (blockIdx.y == 0) ? d0 : (blockIdx.y == 1) ? d1 : d2;
    int r = i >> 6, c = i & 63;
    const float4* p = reinterpret_cast<const float4*>(s + (size_t)r * DIM + c * 8);
    float4 x0 = p[0], x1 = p[1];
    __half2 h0 = __float22half2_rn(make_float2(x0.x, x0.y));
    __half2 h1 = __float22half2_rn(make_float2(x0.z, x0.w));
    __half2 h2 = __float22half2_rn(make_float2(x1.x, x1.y));
    __half2 h3 = __float22half2_rn(make_float2(x1.z, x1.w));
    uint4 o;
    o.x = *reinterpret_cast<uint32_t*>(&h0);
    o.y = *reinterpret_cast<uint32_t*>(&h1);
    o.z = *reinterpret_cast<uint32_t*>(&h2);
    o.w = *reinterpret_cast<uint32_t*>(&h3);
    int kc = c >> 2, c16 = c & 3;
    int sw = c16 ^ ((r >> 1) & 3);
    reinterpret_cast<uint4*>(d)[(size_t)(kc * rows + r) * 4 + sw] = o;
}

// ---------------------------------------------------------------------------
// HMMA fp16 GEMM, cp.async.bulk, 128x128 tile, BK=64, 3-stage pipeline,
// 8 warps (2x4), warp tile 64x32, 2 CTAs/SM. Epilogue emits per-row
// sum-of-squares partials.
// ---------------------------------------------------------------------------
#define CHB 8192                      // one kc-chunk slab: 128 rows * 64 B
#define STGB (4*CHB)                  // A(kc0|kc1) + B(kc0|kc1) = 32768
#define NPIPE 3
#define MBAR_OFF (NPIPE*STGB)         // 98304
#define GEMM_SMEM (MBAR_OFF + 64)
#define NSTAGE 8                      // K=512 / 64

__global__ __launch_bounds__(256, 2) void gemm_mma_kernel(
    const __half* __restrict__ Xh, const __half* __restrict__ Wh,
    const float* __restrict__ bq, const float* __restrict__ bk,
    const float* __restrict__ bv,
    float* __restrict__ Yall, float* __restrict__ sspart)
{
    extern __shared__ char smem[];
    const int z = blockIdx.z;
    const float* bias = (z == 0) ? bq : (z == 1) ? bk : bv;
    float* Y = Yall + (size_t)z * NROWS * DIM;

    const int bm = blockIdx.y * 128;
    const int bn = blockIdx.x * 128;
    const int tid = threadIdx.x;
    const int wid = tid >> 5, lane = tid & 31;
    const int wm = wid >> 2, wn = wid & 3;

    uint32_t sb = smem_u32(smem);
    uint32_t mb = sb + MBAR_OFF;

    if (tid == 0) {
#pragma unroll
        for (int p = 0; p < NPIPE; p++) mbar_init(mb + p * 8, 1);
    }
    __syncthreads();

    const __half* Abase = Xh + (size_t)z * NROWS * DIM + (size_t)bm * 32;
    const __half* Bbase = Wh + (size_t)z * DIM * DIM   + (size_t)bn * 32;

#define ISSUE(stage, s64)                                                     \
    if (tid == 0) {                                                           \
        uint32_t m = mb + (stage) * 8;                                        \
        uint32_t d = sb + (stage) * STGB;                                     \
        int kc = (s64) * 2;                                                   \
        mbar_expect_tx(m, STGB);                                              \
        bulk_g2s(d,         Abase + (size_t)(kc)   * NROWS * 32, CHB, m);     \
        bulk_g2s(d + CHB,   Abase + (size_t)(kc+1) * NROWS * 32, CHB, m);     \
        bulk_g2s(d + 2*CHB, Bbase + (size_t)(kc)   * DIM * 32,   CHB, m);     \
        bulk_g2s(d + 3*CHB, Bbase + (size_t)(kc+1) * DIM * 32,   CHB, m);     \
    }

    ISSUE(0, 0)
    ISSUE(1, 1)
    ISSUE(2, 2)

    float acc[4][4][4];
#pragma unroll
    for (int i = 0; i < 4; i++)
#pragma unroll
        for (int j = 0; j < 4; j++)
#pragma unroll
            for (int r = 0; r < 4; r++) acc[i][j][r] = 0.f;

    const int lrow = lane & 15;
    const int lh = lane >> 4;

    // Hoisted per-thread ldsm address components
    uint32_t aoff[4], boff[2];
    int axr[4], bxr[2];
#pragma unroll
    for (int mt = 0; mt < 4; mt++) {
        int row = wm*64 + mt*16 + lrow;
        aoff[mt] = row * 64;
        axr[mt] = (row >> 1) & 3;
    }
#pragma unroll
    for (int bt = 0; bt < 2; bt++) {
        int row = wn*32 + bt*16 + lrow;
        boff[bt] = 2*CHB + row * 64;
        bxr[bt] = (row >> 1) & 3;
    }

    for (int s = 0; s < NSTAGE; s++) {
        mbar_wait(mb + (s % NPIPE) * 8, (s / NPIPE) & 1);
        uint32_t st = sb + (s % NPIPE) * STGB;

#pragma unroll
        for (int kh = 0; kh < 2; kh++) {
            uint32_t sth = st + kh * CHB;
#pragma unroll
            for (int ks = 0; ks < 2; ks++) {
                const int c16 = ks * 2 + lh;
                uint32_t af[4][4], bf[2][4];
#pragma unroll
                for (int mt = 0; mt < 4; mt++)
                    ldsm4(af[mt], sth + aoff[mt] + ((c16 ^ axr[mt]) << 4));
#pragma unroll
                for (int bt = 0; bt < 2; bt++)
                    ldsm4(bf[bt], sth + boff[bt] + ((c16 ^ bxr[bt]) << 4));
#pragma unroll
                for (int mt = 0; mt < 4; mt++)
#pragma unroll
                    for (int nt = 0; nt < 4; nt++) {
                        int g = nt >> 1, o = nt & 1;
                        mma16816(acc[mt][nt], af[mt], bf[g][o], bf[g][o+2]);
                    }
            }
        }
        __syncthreads();
        if (s + 3 < NSTAGE) ISSUE((s + 3) % NPIPE, s + 3)
    }
#undef ISSUE

    float2 bb[4];
#pragma unroll
    for (int nt = 0; nt < 4; nt++) {
        int col = bn + wn*32 + nt*8 + (lane & 3)*2;
        bb[nt] = make_float2(bias[col], bias[col+1]);
    }
    const int slot = blockIdx.x * 4 + wn;
#pragma unroll
    for (int mt = 0; mt < 4; mt++) {
        int row = bm + wm*64 + mt*16 + (lane >> 2);
        float s0 = 0.f, s1 = 0.f;
#pragma unroll
        for (int nt = 0; nt < 4; nt++) {
            int col = bn + wn*32 + nt*8 + (lane & 3)*2;
            float y00 = acc[mt][nt][0] + bb[nt].x;
            float y01 = acc[mt][nt][1] + bb[nt].y;
            float y10 = acc[mt][nt][2] + bb[nt].x;
            float y11 = acc[mt][nt][3] + bb[nt].y;
            *reinterpret_cast<float2*>(Y + (size_t)row * DIM + col) =
                make_float2(y00, y01);
            *reinterpret_cast<float2*>(Y + (size_t)(row + 8) * DIM + col) =
                make_float2(y10, y11);
            s0 += y00*y00 + y01*y01;
            s1 += y10*y10 + y11*y11;
        }
        s0 += __shfl_xor_sync(0xffffffffu, s0, 1);
        s0 += __shfl_xor_sync(0xffffffffu, s0, 2);
        s1 += __shfl_xor_sync(0xffffffffu, s1, 1);
        s1 += __shfl_xor_sync(0xffffffffu, s1, 2);
        if ((lane & 3) == 0) {
            sspart[(size_t)slot * 3 * NROWS + z * NROWS + row]     = s0;
            sspart[(size_t)slot * 3 * NROWS + z * NROWS + row + 8] = s1;
        }
    }
}

// ---------------------------------------------------------------------------
// Scale kernel: fold 16 sumsq partials, compute lorentz time/scale per row.
// ---------------------------------------------------------------------------
__global__ __launch_bounds__(256) void scale_kernel(
    float* __restrict__ Yall, const float* __restrict__ sspart,
    float* __restrict__ scales,
    const float* __restrict__ lsq, const float* __restrict__ lsk,
    const float* __restrict__ lsv)
{
    int g = blockIdx.x * 256 + threadIdx.x;
    if (g >= 3 * NROWS) return;
    int z = g / NROWS;
    float ls = (z == 0) ? lsq[0] : (z == 1) ? lsk[0] : lsv[0];
    float y0 = Yall[(size_t)g * DIM];
    float tot = 0.f;
#pragma unroll
    for (int s = 0; s < 16; s++) tot += sspart[(size_t)s * 3 * NROWS + g];
    float rest = fmaxf(tot - y0 * y0, 1e-8f);
    float time = expf(ls) / (1.f + expf(-y0)) + 1.0001f;
    float sc = sqrtf((time * time - 1.f) / rest);
    scales[g] = sc;
    Yall[(size_t)g * DIM] = time / sc;
}

// ---------------------------------------------------------------------------
// kkv + fused colsum over an s-half (grid.y = 2 halves), scaling on the fly.
// ---------------------------------------------------------------------------
__global__ __launch_bounds__(256) void kkv_kernel(
    const float* __restrict__ Kb, const float* __restrict__ Vb,
    const float* __restrict__ scales,
    float* __restrict__ M, float* __restrict__ CS,
    const float* __restrict__ as_p, const float* __restrict__ ab_p)
{
    int bh = blockIdx.x;
    int half = blockIdx.y;
    int b = bh >> 3, h = bh & 7;
    __shared__ float Ks[32][64];
    __shared__ float Vs[32][64];
    int tid = threadIdx.x;
    int d1b = (tid >> 4) * 4;
    int d2b = (tid & 15) * 4;
    int lr = tid >> 3;
    int lc = (tid & 7) * 8;
    float acc[4][4];
#pragma unroll
    for (int i = 0; i < 4; i++)
#pragma unroll
        for (int j = 0; j < 4; j++) acc[i][j] = 0.f;
    float csum = 0.f;

    const int sbeg = half * (SEQ/2);
    const float* kp = Kb + (size_t)b * SEQ * DIM + h * DPH;
    const float* vp = Vb + (size_t)b * SEQ * DIM + h * DPH;
    const float* ksc = scales + NROWS + b * SEQ;
    const float* vsc = scales + 2 * NROWS + b * SEQ;

    for (int s0 = sbeg; s0 < sbeg + SEQ/2; s0 += 32) {
        float ks = ksc[s0 + lr];
        float vs = vsc[s0 + lr];
        float4 k0 = *(const float4*)(kp + (size_t)(s0+lr) * DIM + lc);
        float4 k1 = *(const float4*)(kp + (size_t)(s0+lr) * DIM + lc + 4);
        float4 v0 = *(const float4*)(vp + (size_t)(s0+lr) * DIM + lc);
        float4 v1 = *(const float4*)(vp + (size_t)(s0+lr) * DIM + lc + 4);
        k0.x*=ks; k0.y*=ks; k0.z*=ks; k0.w*=ks;
        k1.x*=ks; k1.y*=ks; k1.z*=ks; k1.w*=ks;
        v0.x*=vs; v0.y*=vs; v0.z*=vs; v0.w*=vs;
        v1.x*=vs; v1.y*=vs; v1.z*=vs; v1.w*=vs;
        __syncthreads();
        *(float4*)&Ks[lr][lc]   = k0; *(float4*)&Ks[lr][lc+4] = k1;
        *(float4*)&Vs[lr][lc]   = v0; *(float4*)&Vs[lr][lc+4] = v1;
        __syncthreads();
#pragma unroll
        for (int ss = 0; ss < 32; ss++) {
            float4 kv = *(const float4*)&Ks[ss][d1b];
            float4 vv = *(const float4*)&Vs[ss][d2b];
            float ka[4] = {kv.x, kv.y, kv.z, kv.w};
            float va[4] = {vv.x, vv.y, vv.z, vv.w};
#pragma unroll
            for (int i = 0; i < 4; i++)
#pragma unroll
                for (int j = 0; j < 4; j++) acc[i][j] += ka[i] * va[j];
        }
        if (tid < 64) {
#pragma unroll
            for (int ss = 0; ss < 32; ss++) csum += Vs[ss][tid];
        }
    }

    float c2 = 2.f / as_p[0];
    float* Mp = M + ((size_t)half * NBH + bh) * DPH * DPH;
#pragma unroll
    for (int i = 0; i < 4; i++) {
        float sg = (d1b + i == 0) ? -c2 : c2;
#pragma unroll
        for (int j = 0; j < 4; j++)
            Mp[(d1b + i) * DPH + d2b + j] = acc[i][j] * sg;
    }
    if (tid < 64) {
        float c1 = 2.f / as_p[0] + ab_p[0];
        CS[((size_t)half * NBH + bh) * DPH + tid] = csum * c1;
    }
}

// ---------------------------------------------------------------------------
// ave: 8 rows per warp; coalesced q loads + register shuffles (no scalar LDG).
// ---------------------------------------------------------------------------
__global__ __launch_bounds__(256) void ave_kernel(
    const float* __restrict__ Qb, const float* __restrict__ scales,
    const float* __restrict__ M, const float* __restrict__ CS,
    float* __restrict__ Out)
{
    int bh = blockIdx.x;
    int b = bh >> 3, h = bh & 7;
    int s0 = blockIdx.y * 64;
    int tid = threadIdx.x;
    int warp = tid >> 5, lane = tid & 31;

    __shared__ float Ms[64][64];
    {
        const float* P0 = M + (size_t)bh * DPH * DPH;
        const float* P1 = M + ((size_t)NBH + bh) * DPH * DPH;
        float* Msf = &Ms[0][0];
        for (int i = tid * 4; i < 4096; i += 1024) {
            float4 a = *(const float4*)&P0[i];
            float4 c = *(const float4*)&P1[i];
            a.x += c.x; a.y += c.y; a.z += c.z; a.w += c.w;
            *(float4*)&Msf[i] = a;
        }
    }
    __syncthreads();

    float cs0 = CS[(size_t)bh * DPH + lane]
              + CS[((size_t)NBH + bh) * DPH + lane];
    float cs1 = CS[(size_t)bh * DPH + lane + 32]
              + CS[((size_t)NBH + bh) * DPH + lane + 32];
    const float* qp = Qb + (size_t)b * SEQ * DIM + h * DPH;
    const float* qsc = scales + b * SEQ;

    const int r0 = s0 + warp * 8;
    float qlo[8], qhi[8];
#pragma unroll
    for (int i = 0; i < 8; i++) {
        const float* qr = qp + (size_t)(r0 + i) * DIM;
        qlo[i] = qr[lane];
        qhi[i] = qr[lane + 32];
    }

    float d0[8], d1[8];
#pragma unroll
    for (int i = 0; i < 8; i++) { d0[i] = 0.f; d1[i] = 0.f; }

#pragma unroll
    for (int dp = 0; dp < 64; dp++) {
        float m0 = Ms[dp][lane];
        float m1 = Ms[dp][lane + 32];
#pragma unroll
        for (int i = 0; i < 8; i++) {
            float qv = (dp < 32) ? __shfl_sync(0xffffffffu, qlo[i], dp)
                                 : __shfl_sync(0xffffffffu, qhi[i], dp - 32);
            d0[i] += qv * m0;
            d1[i] += qv * m1;
        }
    }

#pragma unroll
    for (int i = 0; i < 8; i++) {
        int srow = r0 + i;
        float qs = qsc[srow];
        float a0 = cs0 + qs * d0[i];
        float a1 = cs1 + qs * d1[i];
        float contrib = a0 * a0 * ((lane == 0) ? -1.f : 1.f) + a1 * a1;
#pragma unroll
        for (int o = 16; o > 0; o >>= 1)
            contrib += __shfl_xor_sync(0xffffffffu, contrib, o);
        float inv = 1.f / sqrtf(fmaxf(fabsf(contrib), 1e-8f));
        size_t ob = ((size_t)b * SEQ + srow) * DIM + h * DPH;
        Out[ob + lane]      = a0 * inv;
        Out[ob + lane + 32] = a1 * inv;
    }
}

// ===========================================================================
extern "C" void kernel_launch(void* const* d_in, const int* in_sizes, int n_in,
                              void* d_out, int out_size)
{
    const float* key   = (const float*)d_in[0];
    const float* value = (const float*)d_in[1];
    const float* query = (const float*)d_in[2];
    const float* Wq  = (const float*)d_in[3];
    const float* bq  = (const float*)d_in[4];
    const float* lsq = (const float*)d_in[5];
    const float* Wk  = (const float*)d_in[6];
    const float* bk  = (const float*)d_in[7];
    const float* lsk = (const float*)d_in[8];
    const float* Wv  = (const float*)d_in[9];
    const float* bv  = (const float*)d_in[10];
    const float* lsv = (const float*)d_in[11];
    const float* as_p = (const float*)d_in[12];
    const float* ab_p = (const float*)d_in[13];
    float* out = (float*)d_out;

    float *gqkv, *gM, *gcs, *gss, *gsc;
    __half *gxh, *gwh;
    cudaGetSymbolAddress((void**)&gqkv, g_qkv);
    cudaGetSymbolAddress((void**)&gxh,  g_xh);
    cudaGetSymbolAddress((void**)&gwh,  g_wh);
    cudaGetSymbolAddress((void**)&gss,  g_sspart);
    cudaGetSymbolAddress((void**)&gsc,  g_scale);
    cudaGetSymbolAddress((void**)&gM,   g_M);
    cudaGetSymbolAddress((void**)&gcs,  g_cs);

    float* gq = gqkv;
    float* gk = gqkv + (size_t)NROWS * DIM;
    float* gv = gqkv + (size_t)2 * NROWS * DIM;

    const int XCH = NROWS * 64;
    const int WCH = DIM * 64;

    // Launch order: GEMM stays the 4th launch for ncu.
    {   // #1: all three W converts
        dim3 gw(WCH/256, 3);
        convert_blk_kernel<<<gw, 256>>>(Wq, gwh,
                                        Wk, gwh + DIM*DIM,
                                        Wv, gwh + 2*DIM*DIM, WCH, DIM);
    }
    {   // #2: X query
        dim3 g1(XCH/256, 1);
        convert_blk_kernel<<<g1, 256>>>(query, gxh, query, gxh, query, gxh,
                                        XCH, NROWS);
    }
    {   // #3: X key + value
        dim3 g2(XCH/256, 2);
        convert_blk_kernel<<<g2, 256>>>(key,   gxh +   NROWS*DIM,
                                        value, gxh + 2*NROWS*DIM,
                                        value, gxh + 2*NROWS*DIM, XCH, NROWS);
    }

    // #4: GEMM (profiled)
    cudaFuncSetAttribute(gemm_mma_kernel,
                         cudaFuncAttributeMaxDynamicSharedMemorySize, GEMM_SMEM);
    dim3 ggrid(DIM / 128, NROWS / 128, 3);
    gemm_mma_kernel<<<ggrid, 256, GEMM_SMEM>>>(
        gxh, gwh, bq, bk, bv, gqkv, gss);

    // #5: row scale/time
    scale_kernel<<<(3*NROWS)/256, 256>>>(gqkv, gss, gsc, lsq, lsk, lsv);

    // #6: kkv + fused colsum over 2 s-halves
    dim3 kgrid(NBH, 2);
    kkv_kernel<<<kgrid, 256>>>(gk, gv, gsc, gM, gcs, as_p, ab_p);

    // #7: ave (8 rows per warp, shuffle-broadcast q)
    dim3 agrid(NBH, SEQ / 64);
    ave_kernel<<<agrid, 256>>>(gq, gsc, gM, gcs, out);
}